// round 10
// baseline (speedup 1.0000x reference)
#include <cuda_runtime.h>
#include <cuda_bf16.h>
#include <cstdint>

constexpr int Bdim = 64;
constexpr int Nseq = 512;
constexpr int E    = 128;
constexpr int D    = 128;
constexpr int H    = 4;

// ---------------- scratch (allocation-free) ----------------
__device__ __nv_bfloat16 g_xh [(size_t)Bdim*Nseq*E];
__device__ __nv_bfloat16 g_xl [(size_t)Bdim*Nseq*E];
__device__ __nv_bfloat16 g_WTh[12 * 128 * 128];          // [which*4+h][d][e] (transposed)
__device__ __nv_bfloat16 g_WTl[12 * 128 * 128];
__device__ __nv_bfloat16 g_W1Th[128 * 512];              // [e_out][k]
__device__ __nv_bfloat16 g_W1Tl[128 * 512];
__device__ __nv_bfloat16 g_W2Th[128 * 128];
__device__ __nv_bfloat16 g_W2Tl[128 * 128];
__device__ __nv_bfloat16 g_Qh[(size_t)Bdim*H*Nseq*D];
__device__ __nv_bfloat16 g_Ql[(size_t)Bdim*H*Nseq*D];
__device__ __nv_bfloat16 g_Kh[(size_t)Bdim*H*Nseq*D];
__device__ __nv_bfloat16 g_Kl[(size_t)Bdim*H*Nseq*D];
__device__ __nv_bfloat16 g_Vh[(size_t)Bdim*H*Nseq*E];    // [bh][n][e]
__device__ __nv_bfloat16 g_Vl[(size_t)Bdim*H*Nseq*E];
__device__ __nv_bfloat16 g_Vth[(size_t)Bdim*H*E*Nseq];   // [bh][e][n]
__device__ __nv_bfloat16 g_Vtl[(size_t)Bdim*H*E*Nseq];
// per-h chunked attention buffers (L2-resident working set)
__device__ float         g_S [(size_t)Bdim*Nseq*Nseq];   // [b][n][m] fp32, one h at a time
__device__ __nv_bfloat16 g_Ph[(size_t)Bdim*Nseq*Nseq];   // [b][n][m]
__device__ __nv_bfloat16 g_Pl[(size_t)Bdim*Nseq*Nseq];
__device__ __nv_bfloat16 g_Ah[(size_t)Bdim*Nseq*H*E];    // [B,N,512] concat
__device__ __nv_bfloat16 g_Al[(size_t)Bdim*Nseq*H*E];
__device__ __nv_bfloat16 g_H1h[(size_t)Bdim*Nseq*E];
__device__ __nv_bfloat16 g_H1l[(size_t)Bdim*Nseq*E];

// ======================= mma.sync machinery =======================
__device__ __forceinline__ void ldsm_x4(uint32_t r[4], const void* p) {
    uint32_t addr = (uint32_t)__cvta_generic_to_shared(p);
    asm volatile("ldmatrix.sync.aligned.m8n8.x4.shared.b16 {%0,%1,%2,%3}, [%4];"
                 : "=r"(r[0]), "=r"(r[1]), "=r"(r[2]), "=r"(r[3]) : "r"(addr));
}
__device__ __forceinline__ void mma16816(float c[4], const uint32_t a[4], const uint32_t b[2]) {
    asm volatile("mma.sync.aligned.m16n8k16.row.col.f32.bf16.bf16.f32 "
                 "{%0,%1,%2,%3}, {%4,%5,%6,%7}, {%8,%9}, {%0,%1,%2,%3};"
                 : "+f"(c[0]), "+f"(c[1]), "+f"(c[2]), "+f"(c[3])
                 : "r"(a[0]), "r"(a[1]), "r"(a[2]), "r"(a[3]), "r"(b[0]), "r"(b[1]));
}
// smem plane: 128 rows x 32 bf16 (64B rows), 16B chunks XOR-swizzled
__device__ __forceinline__ int sw_idx(int row, int seg) {
    return row * 32 + ((seg ^ ((row >> 1) & 3)) << 3);
}
__device__ __forceinline__ void cp_plane(__nv_bfloat16* dst, const __nv_bfloat16* src,
                                         int ld, int kc, int tid)
{
    #pragma unroll
    for (int s = 0; s < 2; s++) {
        int idx = tid + s * 256;
        int row = idx >> 2, seg = idx & 3;
        uint32_t d = (uint32_t)__cvta_generic_to_shared(dst + sw_idx(row, seg));
        const __nv_bfloat16* g = src + (size_t)row * ld + kc + seg * 8;
        asm volatile("cp.async.cg.shared.global [%0], [%1], 16;" :: "r"(d), "l"(g));
    }
}
__device__ __forceinline__ void load_a_frag(uint32_t a[4][4], const __nv_bfloat16* plane,
                                            int m0, int seg_base, int lane)
{
    const int r = lane & 15, half = lane >> 4;
    #pragma unroll
    for (int t = 0; t < 4; t++)
        ldsm_x4(a[t], plane + sw_idx(m0 + t * 16 + r, seg_base + half));
}
__device__ __forceinline__ void load_b_frag(uint32_t b[4][2], const __nv_bfloat16* plane,
                                            int n0, int seg_base, int lane)
{
    const int r = lane & 15, half = lane >> 4;
    #pragma unroll
    for (int p = 0; p < 2; p++) {
        uint32_t t[4];
        ldsm_x4(t, plane + sw_idx(n0 + p * 16 + r, seg_base + half));
        b[2*p][0]   = t[0];
        b[2*p+1][0] = t[1];
        b[2*p][1]   = t[2];
        b[2*p+1][1] = t[3];
    }
}
__device__ __forceinline__ void mma_all(float acc[4][4][4], const uint32_t a[4][4],
                                        const uint32_t b[4][2])
{
    #pragma unroll
    for (int mt = 0; mt < 4; mt++)
        #pragma unroll
        for (int nt = 0; nt < 4; nt++)
            mma16816(acc[mt][nt], a[mt], b[nt]);
}

// ---------------------------------------------------------------------------
// Split-bf16 (3-product) 128x128 GEMM core, cp.async 3-stage pipeline.
// sm: 3 stages x 4 planes x 4096 bf16 = 96KB dynamic smem.
// ---------------------------------------------------------------------------
__device__ __forceinline__ void ld_stage(__nv_bfloat16* st,
                                         const __nv_bfloat16* Ah, const __nv_bfloat16* Al, int lda,
                                         const __nv_bfloat16* Bh, const __nv_bfloat16* Bl, int ldb,
                                         int kc, int tid)
{
    cp_plane(st + 0*4096, Ah, lda, kc, tid);
    cp_plane(st + 1*4096, Al, lda, kc, tid);
    cp_plane(st + 2*4096, Bh, ldb, kc, tid);
    cp_plane(st + 3*4096, Bl, ldb, kc, tid);
    asm volatile("cp.async.commit_group;");
}

__device__ __forceinline__ void mma_core(
                         const __nv_bfloat16* __restrict__ Ah,
                         const __nv_bfloat16* __restrict__ Al, int lda,
                         const __nv_bfloat16* __restrict__ Bh,
                         const __nv_bfloat16* __restrict__ Bl, int ldb,
                         int K, __nv_bfloat16* sm, float acc[4][4][4])
{
    const int tid = threadIdx.x, lane = tid & 31, wid = tid >> 5;
    const int m0 = (wid >> 2) * 64, n0 = (wid & 3) * 32;

    #pragma unroll
    for (int mt = 0; mt < 4; mt++)
        #pragma unroll
        for (int nt = 0; nt < 4; nt++)
            #pragma unroll
            for (int q = 0; q < 4; q++) acc[mt][nt][q] = 0.f;

    const int NC = K >> 5;
    ld_stage(sm, Ah, Al, lda, Bh, Bl, ldb, 0, tid);
    if (NC > 1) ld_stage(sm + 16384, Ah, Al, lda, Bh, Bl, ldb, 32, tid);

    int stage = 0;
    for (int c = 0; c < NC; c++) {
        if (c + 1 < NC) asm volatile("cp.async.wait_group 1;");
        else            asm volatile("cp.async.wait_group 0;");
        __syncthreads();
        if (c + 2 < NC) {
            int ps = stage + 2; if (ps >= 3) ps -= 3;
            ld_stage(sm + ps * 16384, Ah, Al, lda, Bh, Bl, ldb, (c + 2) * 32, tid);
        }
        __nv_bfloat16* st = sm + stage * 16384;
        #pragma unroll
        for (int ks = 0; ks < 2; ks++) {
            const int seg = ks * 2;
            uint32_t a[4][4];
            uint32_t bh_[4][2];
            uint32_t bl_[4][2];
            load_a_frag(a, st + 0*4096, m0, seg, lane);   // A hi
            load_b_frag(bh_, st + 2*4096, n0, seg, lane); // B hi
            mma_all(acc, a, bh_);                         // hi*hi
            load_b_frag(bl_, st + 3*4096, n0, seg, lane); // B lo
            mma_all(acc, a, bl_);                         // hi*lo
            load_a_frag(a, st + 1*4096, m0, seg, lane);   // A lo (overwrite)
            mma_all(acc, a, bh_);                         // lo*hi (B hi in regs)
        }
        if (++stage == 3) stage = 0;
    }
    __syncthreads();   // protect smem-reusing epilogues (LN buffers)
}

// LayerNorm over 128 cols in mma fragment layout. lnbuf >= 1280 floats.
__device__ __forceinline__ void ln_mma(float acc[4][4][4], float* lnbuf)
{
    float* lnS = lnbuf;
    float* lnQ = lnbuf + 512;
    float* mrs = lnbuf + 1024;
    const int tid = threadIdx.x, lane = tid & 31, wid = tid >> 5;
    const int wn = wid & 3, m0 = (wid >> 2) * 64;
    const int rr = lane >> 2, cg = lane & 3;

    #pragma unroll
    for (int mt = 0; mt < 4; mt++)
        #pragma unroll
        for (int half = 0; half < 2; half++) {
            float s = 0.f, q = 0.f;
            #pragma unroll
            for (int nt = 0; nt < 4; nt++) {
                float v0 = acc[mt][nt][2*half], v1 = acc[mt][nt][2*half+1];
                s += v0 + v1; q += v0 * v0 + v1 * v1;
            }
            s += __shfl_xor_sync(0xffffffffu, s, 1);
            s += __shfl_xor_sync(0xffffffffu, s, 2);
            q += __shfl_xor_sync(0xffffffffu, q, 1);
            q += __shfl_xor_sync(0xffffffffu, q, 2);
            if (cg == 0) {
                int row = m0 + mt * 16 + half * 8 + rr;
                lnS[row * 4 + wn] = s;
                lnQ[row * 4 + wn] = q;
            }
        }
    __syncthreads();
    if (tid < 128) {
        float s = lnS[tid*4] + lnS[tid*4+1] + lnS[tid*4+2] + lnS[tid*4+3];
        float q = lnQ[tid*4] + lnQ[tid*4+1] + lnQ[tid*4+2] + lnQ[tid*4+3];
        float mean = s * (1.0f / 128.0f);
        float var  = q * (1.0f / 128.0f) - mean * mean;
        mrs[tid]       = mean;
        mrs[128 + tid] = rsqrtf(var + 1e-5f);
    }
    __syncthreads();
    #pragma unroll
    for (int mt = 0; mt < 4; mt++)
        #pragma unroll
        for (int half = 0; half < 2; half++) {
            int row = m0 + mt * 16 + half * 8 + rr;
            float mu = mrs[row], rs = mrs[128 + row];
            #pragma unroll
            for (int nt = 0; nt < 4; nt++) {
                acc[mt][nt][2*half]   = (acc[mt][nt][2*half]   - mu) * rs;
                acc[mt][nt][2*half+1] = (acc[mt][nt][2*half+1] - mu) * rs;
            }
        }
}

__device__ __forceinline__ uint32_t pack_hi2(float v0, float v1, uint32_t& lo)
{
    __nv_bfloat16 h0 = __float2bfloat16(v0), h1 = __float2bfloat16(v1);
    __nv_bfloat16 l0 = __float2bfloat16(v0 - __bfloat162float(h0));
    __nv_bfloat16 l1 = __float2bfloat16(v1 - __bfloat162float(h1));
    lo = (uint32_t)__bfloat16_as_ushort(l0) | ((uint32_t)__bfloat16_as_ushort(l1) << 16);
    return (uint32_t)__bfloat16_as_ushort(h0) | ((uint32_t)__bfloat16_as_ushort(h1) << 16);
}

__device__ __forceinline__ void store_hilo(const float acc[4][4][4],
                                           __nv_bfloat16* oh, __nv_bfloat16* ol,
                                           int ldc)
{
    const int lane = threadIdx.x & 31, wid = threadIdx.x >> 5;
    const int m0 = (wid >> 2) * 64, n0 = (wid & 3) * 32;
    const int rr = lane >> 2, cg = lane & 3;
    #pragma unroll
    for (int mt = 0; mt < 4; mt++)
        #pragma unroll
        for (int half = 0; half < 2; half++) {
            int row = m0 + mt * 16 + half * 8 + rr;
            #pragma unroll
            for (int nt = 0; nt < 4; nt++) {
                int c = n0 + nt * 8 + 2 * cg;
                uint32_t lo;
                uint32_t hi = pack_hi2(acc[mt][nt][2*half], acc[mt][nt][2*half+1], lo);
                *reinterpret_cast<uint32_t*>(oh + (size_t)row * ldc + c) = hi;
                *reinterpret_cast<uint32_t*>(ol + (size_t)row * ldc + c) = lo;
            }
        }
}

// ======================= prep kernels =======================
__global__ __launch_bounds__(256) void split_x_kernel(const float* __restrict__ x)
{
    const size_t i4 = (size_t)blockIdx.x * 256 + threadIdx.x;
    float4 v = *reinterpret_cast<const float4*>(x + i4 * 4);
    uint32_t l0, l1;
    uint32_t h0 = pack_hi2(v.x, v.y, l0);
    uint32_t h1 = pack_hi2(v.z, v.w, l1);
    *reinterpret_cast<uint2*>(g_xh + i4 * 4) = make_uint2(h0, h1);
    *reinterpret_cast<uint2*>(g_xl + i4 * 4) = make_uint2(l0, l1);
}

// transpose+split a [R,C] fp32 matrix -> dst hi/lo [C,R] bf16
__device__ __forceinline__ void transplit_tile(const float* src, __nv_bfloat16* dh,
                                               __nv_bfloat16* dl, int R, int C,
                                               int r0, int c0)
{
    __shared__ float t[32][33];
    const int tid = threadIdx.x;
    #pragma unroll
    for (int s = 0; s < 4; s++) {
        int idx = tid + s * 256;
        int r = idx >> 5, c = idx & 31;
        t[r][c] = src[(size_t)(r0 + r) * C + c0 + c];
    }
    __syncthreads();
    #pragma unroll
    for (int s = 0; s < 4; s++) {
        int idx = tid + s * 256;
        int co = idx >> 5, ro = idx & 31;
        float v = t[ro][co];
        __nv_bfloat16 h = __float2bfloat16(v);
        dh[(size_t)(c0 + co) * R + r0 + ro] = h;
        dl[(size_t)(c0 + co) * R + r0 + ro] = __float2bfloat16(v - __bfloat162float(h));
    }
}

__global__ __launch_bounds__(256) void qkv_prep_kernel(
    const float* __restrict__ Wq, const float* __restrict__ Wk, const float* __restrict__ Wv)
{
    const int midx = blockIdx.x;           // which*4 + h
    const int which = midx >> 2, h = midx & 3;
    const float* src = (which == 0 ? Wq : (which == 1 ? Wk : Wv)) + (size_t)h * 128 * 128;
    transplit_tile(src, g_WTh + (size_t)midx * 16384, g_WTl + (size_t)midx * 16384,
                   128, 128, blockIdx.y * 32, blockIdx.z * 32);
}
__global__ __launch_bounds__(256) void w1_prep_kernel(const float* __restrict__ W1)
{
    transplit_tile(W1, g_W1Th, g_W1Tl, 512, 128, blockIdx.x * 32, blockIdx.y * 32);
}
__global__ __launch_bounds__(256) void w2_prep_kernel(const float* __restrict__ W2)
{
    transplit_tile(W2, g_W2Th, g_W2Tl, 128, 128, blockIdx.x * 32, blockIdx.y * 32);
}

// ======================= main kernels =======================
extern __shared__ __nv_bfloat16 dynsm[];

// QKV: grid (12, 256) — midx fastest so consecutive blocks share the x tile (L2 reuse).
__global__ __launch_bounds__(256) void qkv_mma(
    const float* __restrict__ bq, const float* __restrict__ bk, const float* __restrict__ bv)
{
    const int midx = blockIdx.x;           // which*4 + h
    const int which = midx >> 2, h = midx & 3;
    const int rowBase = blockIdx.y * 128;
    const float* bias = (which == 0 ? bq : (which == 1 ? bk : bv)) + (size_t)h * 128;

    float acc[4][4][4];
    mma_core(g_xh + (size_t)rowBase * E, g_xl + (size_t)rowBase * E, E,
             g_WTh + (size_t)midx * 16384, g_WTl + (size_t)midx * 16384, E,
             E, dynsm, acc);

    const int lane = threadIdx.x & 31, wid = threadIdx.x >> 5;
    const int n0 = (wid & 3) * 32, cg = lane & 3;
    #pragma unroll
    for (int nt = 0; nt < 4; nt++) {
        float2 bv2 = *reinterpret_cast<const float2*>(bias + n0 + nt * 8 + 2 * cg);
        #pragma unroll
        for (int mt = 0; mt < 4; mt++) {
            acc[mt][nt][0] += bv2.x; acc[mt][nt][1] += bv2.y;
            acc[mt][nt][2] += bv2.x; acc[mt][nt][3] += bv2.y;
        }
    }
    ln_mma(acc, (float*)dynsm);

    const int b = rowBase >> 9, nBase = rowBase & 511;
    const int bh = b * H + h;
    const size_t off = ((size_t)bh * Nseq + nBase) * 128;
    __nv_bfloat16* oh = (which == 0 ? g_Qh : (which == 1 ? g_Kh : g_Vh)) + off;
    __nv_bfloat16* ol = (which == 0 ? g_Ql : (which == 1 ? g_Kl : g_Vl)) + off;
    store_hilo(acc, oh, ol, 128);
}

// V transpose: grid (256, 4, 16)
__global__ __launch_bounds__(256) void vtrans_kernel()
{
    __shared__ __nv_bfloat16 th[32][33], tl[32][33];
    const int bh = blockIdx.x, e0 = blockIdx.y * 32, n0 = blockIdx.z * 32;
    const int tid = threadIdx.x;
    const size_t inBase = ((size_t)bh * Nseq + n0) * E + e0;
    #pragma unroll
    for (int s = 0; s < 4; s++) {
        int idx = tid + s * 256;
        int r = idx >> 5, c = idx & 31;
        th[r][c] = g_Vh[inBase + (size_t)r * E + c];
        tl[r][c] = g_Vl[inBase + (size_t)r * E + c];
    }
    __syncthreads();
    const size_t outBase = ((size_t)bh * E + e0) * Nseq + n0;
    #pragma unroll
    for (int s = 0; s < 4; s++) {
        int idx = tid + s * 256;
        int r = idx >> 5, c = idx & 31;
        g_Vth[outBase + (size_t)r * Nseq + c] = th[c][r];
        g_Vtl[outBase + (size_t)r * Nseq + c] = tl[c][r];
    }
}

// scores for ONE head h: S[b][n][m] = Q[b,h] K[b,h]^T. grid (4, 4, 64)
__global__ __launch_bounds__(256) void scores_mma(int h)
{
    const int b = blockIdx.z, bh = b * H + h;
    const size_t rowBase = blockIdx.x * 128, colBase = blockIdx.y * 128;
    float acc[4][4][4];
    mma_core(g_Qh + ((size_t)bh * Nseq + rowBase) * D,
             g_Ql + ((size_t)bh * Nseq + rowBase) * D, D,
             g_Kh + ((size_t)bh * Nseq + colBase) * D,
             g_Kl + ((size_t)bh * Nseq + colBase) * D, D, D, dynsm, acc);

    float* Cout = g_S + (size_t)b * Nseq * Nseq + rowBase * Nseq + colBase;
    const int lane = threadIdx.x & 31, wid = threadIdx.x >> 5;
    const int m0 = (wid >> 2) * 64, n0 = (wid & 3) * 32;
    const int rr = lane >> 2, cg = lane & 3;
    #pragma unroll
    for (int mt = 0; mt < 4; mt++)
        #pragma unroll
        for (int half = 0; half < 2; half++) {
            int r = m0 + mt * 16 + half * 8 + rr;
            #pragma unroll
            for (int nt = 0; nt < 4; nt++) {
                int c = n0 + nt * 8 + 2 * cg;
                *reinterpret_cast<float2*>(Cout + (size_t)r * Nseq + c) =
                    make_float2(acc[mt][nt][2*half], acc[mt][nt][2*half+1]);
            }
        }
}

// batch-axis softmax for one head. grid (1024) over (n,m) = 262144 elems.
__global__ __launch_bounds__(256) void softmax_kernel()
{
    const size_t idx = (size_t)blockIdx.x * 256 + threadIdx.x;   // over N*N
    const size_t stride = (size_t)Nseq * Nseq;
    float v[64];
    float mx = -1e30f;
    #pragma unroll
    for (int b = 0; b < 64; b++) {
        float t = g_S[(size_t)b * stride + idx] * (1.0f / 11.0f);
        v[b] = t;
        mx = fmaxf(mx, t);
    }
    float s = 0.f;
    #pragma unroll
    for (int b = 0; b < 64; b++) { float e = __expf(v[b] - mx); v[b] = e; s += e; }
    const float inv = 1.0f / s;
    #pragma unroll
    for (int b = 0; b < 64; b++) {
        float p = v[b] * inv;
        __nv_bfloat16 hp = __float2bfloat16(p);
        __nv_bfloat16 lp = __float2bfloat16(p - __bfloat162float(hp));
        g_Ph[(size_t)b * stride + idx] = hp;
        g_Pl[(size_t)b * stride + idx] = lp;
    }
}

// A = P V for one head -> hi/lo concat layout. grid (4, 1, 64)
__global__ __launch_bounds__(256) void av_mma(int h)
{
    const int b = blockIdx.z, bh = b * H + h;
    const size_t rowBase = blockIdx.x * 128;
    float acc[4][4][4];
    mma_core(g_Ph + ((size_t)b * Nseq + rowBase) * Nseq,
             g_Pl + ((size_t)b * Nseq + rowBase) * Nseq, Nseq,
             g_Vth + (size_t)bh * E * Nseq,
             g_Vtl + (size_t)bh * E * Nseq, Nseq, Nseq, dynsm, acc);
    const size_t off = ((size_t)b * Nseq + rowBase) * (H * E) + (size_t)h * E;
    store_hilo(acc, g_Ah + off, g_Al + off, H * E);
}

// h1 = relu(A @ W1 + b1) -> hi/lo. grid (256)
__global__ __launch_bounds__(256) void mlp1_mma(const float* __restrict__ b1)
{
    const int rowBase = blockIdx.x * 128;
    float acc[4][4][4];
    mma_core(g_Ah + (size_t)rowBase * (H * E), g_Al + (size_t)rowBase * (H * E), H * E,
             g_W1Th, g_W1Tl, H * E, H * E, dynsm, acc);

    const int lane = threadIdx.x & 31, wid = threadIdx.x >> 5;
    const int n0 = (wid & 3) * 32, cg = lane & 3;
    #pragma unroll
    for (int nt = 0; nt < 4; nt++) {
        float2 bv2 = *reinterpret_cast<const float2*>(b1 + n0 + nt * 8 + 2 * cg);
        #pragma unroll
        for (int mt = 0; mt < 4; mt++) {
            acc[mt][nt][0] = fmaxf(acc[mt][nt][0] + bv2.x, 0.f);
            acc[mt][nt][1] = fmaxf(acc[mt][nt][1] + bv2.y, 0.f);
            acc[mt][nt][2] = fmaxf(acc[mt][nt][2] + bv2.x, 0.f);
            acc[mt][nt][3] = fmaxf(acc[mt][nt][3] + bv2.y, 0.f);
        }
    }
    store_hilo(acc, g_H1h + (size_t)rowBase * E, g_H1l + (size_t)rowBase * E, E);
}

// out = LN(x + relu(h1 @ W2 + b2)) * gamma + beta. grid (256)
__global__ __launch_bounds__(256) void mlp2_mma(
    const float* __restrict__ x, const float* __restrict__ b2,
    const float* __restrict__ gamma, const float* __restrict__ beta,
    float* __restrict__ out)
{
    const int rowBase = blockIdx.x * 128;
    float acc[4][4][4];
    mma_core(g_H1h + (size_t)rowBase * E, g_H1l + (size_t)rowBase * E, E,
             g_W2Th, g_W2Tl, E, E, dynsm, acc);

    const int lane = threadIdx.x & 31, wid = threadIdx.x >> 5;
    const int m0 = (wid >> 2) * 64, n0 = (wid & 3) * 32;
    const int rr = lane >> 2, cg = lane & 3;
    #pragma unroll
    for (int nt = 0; nt < 4; nt++) {
        const int c = n0 + nt * 8 + 2 * cg;
        float2 bv2 = *reinterpret_cast<const float2*>(b2 + c);
        #pragma unroll
        for (int mt = 0; mt < 4; mt++)
            #pragma unroll
            for (int half = 0; half < 2; half++) {
                int row = rowBase + m0 + mt * 16 + half * 8 + rr;
                float2 xv = *reinterpret_cast<const float2*>(x + (size_t)row * E + c);
                acc[mt][nt][2*half]   = fmaxf(acc[mt][nt][2*half]   + bv2.x, 0.f) + xv.x;
                acc[mt][nt][2*half+1] = fmaxf(acc[mt][nt][2*half+1] + bv2.y, 0.f) + xv.y;
            }
    }

    ln_mma(acc, (float*)dynsm);

    #pragma unroll
    for (int nt = 0; nt < 4; nt++) {
        const int c = n0 + nt * 8 + 2 * cg;
        float2 gv = *reinterpret_cast<const float2*>(gamma + c);
        float2 ev = *reinterpret_cast<const float2*>(beta + c);
        #pragma unroll
        for (int mt = 0; mt < 4; mt++)
            #pragma unroll
            for (int half = 0; half < 2; half++) {
                int row = rowBase + m0 + mt * 16 + half * 8 + rr;
                float o0 = acc[mt][nt][2*half]   * gv.x + ev.x;
                float o1 = acc[mt][nt][2*half+1] * gv.y + ev.y;
                *reinterpret_cast<float2*>(out + (size_t)row * E + c) = make_float2(o0, o1);
            }
    }
}

// ---------------------------------------------------------------------------
extern "C" void kernel_launch(void* const* d_in, const int* in_sizes, int n_in,
                              void* d_out, int out_size)
{
    const float* x     = (const float*)d_in[0];
    const float* Wq    = (const float*)d_in[1];
    const float* bq    = (const float*)d_in[2];
    const float* Wk    = (const float*)d_in[3];
    const float* bk    = (const float*)d_in[4];
    const float* Wv    = (const float*)d_in[5];
    const float* bv    = (const float*)d_in[6];
    const float* W1    = (const float*)d_in[7];
    const float* b1    = (const float*)d_in[8];
    const float* W2    = (const float*)d_in[9];
    const float* b2    = (const float*)d_in[10];
    const float* gamma = (const float*)d_in[11];
    const float* beta  = (const float*)d_in[12];
    float* out = (float*)d_out;

    const int SMEM = 3 * 4 * 4096 * (int)sizeof(__nv_bfloat16);   // 96KB
    cudaFuncSetAttribute(qkv_mma,    cudaFuncAttributeMaxDynamicSharedMemorySize, SMEM);
    cudaFuncSetAttribute(scores_mma, cudaFuncAttributeMaxDynamicSharedMemorySize, SMEM);
    cudaFuncSetAttribute(av_mma,     cudaFuncAttributeMaxDynamicSharedMemorySize, SMEM);
    cudaFuncSetAttribute(mlp1_mma,   cudaFuncAttributeMaxDynamicSharedMemorySize, SMEM);
    cudaFuncSetAttribute(mlp2_mma,   cudaFuncAttributeMaxDynamicSharedMemorySize, SMEM);

    dim3 blk(256);
    split_x_kernel <<<dim3(4096), blk>>>(x);
    qkv_prep_kernel<<<dim3(12, 4, 4), blk>>>(Wq, Wk, Wv);
    w1_prep_kernel <<<dim3(16, 4), blk>>>(W1);
    w2_prep_kernel <<<dim3(4, 4), blk>>>(W2);
    qkv_mma        <<<dim3(12, 256), blk, SMEM>>>(bq, bk, bv);
    vtrans_kernel  <<<dim3(256, 4, 16), blk>>>();
    // Per-head attention chunk: S/P working set (~128MB) stays L2-resident.
    for (int h = 0; h < H; h++) {
        scores_mma    <<<dim3(4, 4, 64), blk, SMEM>>>(h);
        softmax_kernel<<<dim3(1024), blk>>>();
        av_mma        <<<dim3(4, 1, 64), blk, SMEM>>>(h);
    }
    mlp1_mma       <<<dim3(256), blk, SMEM>>>(b1);
    mlp2_mma       <<<dim3(256), blk, SMEM>>>(x, b2, gamma, beta, out);
}

// round 11
// speedup vs baseline: 1.1003x; 1.1003x over previous
#include <cuda_runtime.h>
#include <cuda_bf16.h>
#include <cstdint>

constexpr int Bdim = 64;
constexpr int Nseq = 512;
constexpr int E    = 128;
constexpr int D    = 128;
constexpr int H    = 4;

// ---------------- scratch (allocation-free) ----------------
__device__ __nv_bfloat16 g_xh [(size_t)Bdim*Nseq*E];
__device__ __nv_bfloat16 g_xl [(size_t)Bdim*Nseq*E];
__device__ __nv_bfloat16 g_WTh[12 * 128 * 128];          // [which*4+h][d][e] (transposed)
__device__ __nv_bfloat16 g_WTl[12 * 128 * 128];
__device__ __nv_bfloat16 g_W1Th[128 * 512];              // [e_out][k]
__device__ __nv_bfloat16 g_W1Tl[128 * 512];
__device__ __nv_bfloat16 g_W2Th[128 * 128];
__device__ __nv_bfloat16 g_W2Tl[128 * 128];
__device__ __nv_bfloat16 g_Qh[(size_t)Bdim*H*Nseq*D];
__device__ __nv_bfloat16 g_Ql[(size_t)Bdim*H*Nseq*D];
__device__ __nv_bfloat16 g_Kh[(size_t)Bdim*H*Nseq*D];
__device__ __nv_bfloat16 g_Kl[(size_t)Bdim*H*Nseq*D];
__device__ __nv_bfloat16 g_Vh[(size_t)Bdim*H*Nseq*E];    // [bh][n][e]
__device__ __nv_bfloat16 g_Vl[(size_t)Bdim*H*Nseq*E];
__device__ __nv_bfloat16 g_Vth[(size_t)Bdim*H*E*Nseq];   // [bh][e][n]
__device__ __nv_bfloat16 g_Vtl[(size_t)Bdim*H*E*Nseq];
__device__ float         g_S [(size_t)Bdim*H*Nseq*Nseq]; // fp32 scores
__device__ __nv_bfloat16 g_Ph[(size_t)Bdim*H*Nseq*Nseq];
__device__ __nv_bfloat16 g_Pl[(size_t)Bdim*H*Nseq*Nseq];
__device__ __nv_bfloat16 g_Ah[(size_t)Bdim*Nseq*H*E];    // [B,N,512] concat
__device__ __nv_bfloat16 g_Al[(size_t)Bdim*Nseq*H*E];
__device__ __nv_bfloat16 g_H1h[(size_t)Bdim*Nseq*E];
__device__ __nv_bfloat16 g_H1l[(size_t)Bdim*Nseq*E];

// ======================= mma.sync machinery =======================
__device__ __forceinline__ void ldsm_x4(uint32_t r[4], const void* p) {
    uint32_t addr = (uint32_t)__cvta_generic_to_shared(p);
    asm volatile("ldmatrix.sync.aligned.m8n8.x4.shared.b16 {%0,%1,%2,%3}, [%4];"
                 : "=r"(r[0]), "=r"(r[1]), "=r"(r[2]), "=r"(r[3]) : "r"(addr));
}
__device__ __forceinline__ void mma16816(float c[4], const uint32_t a[4], const uint32_t b[2]) {
    asm volatile("mma.sync.aligned.m16n8k16.row.col.f32.bf16.bf16.f32 "
                 "{%0,%1,%2,%3}, {%4,%5,%6,%7}, {%8,%9}, {%0,%1,%2,%3};"
                 : "+f"(c[0]), "+f"(c[1]), "+f"(c[2]), "+f"(c[3])
                 : "r"(a[0]), "r"(a[1]), "r"(a[2]), "r"(a[3]), "r"(b[0]), "r"(b[1]));
}
// smem plane: 128 rows x 32 bf16 (64B rows), 16B chunks XOR-swizzled
__device__ __forceinline__ int sw_idx(int row, int seg) {
    return row * 32 + ((seg ^ ((row >> 1) & 3)) << 3);
}
__device__ __forceinline__ void cp_plane(__nv_bfloat16* dst, const __nv_bfloat16* src,
                                         int ld, int kc, int tid)
{
    #pragma unroll
    for (int s = 0; s < 2; s++) {
        int idx = tid + s * 256;
        int row = idx >> 2, seg = idx & 3;
        uint32_t d = (uint32_t)__cvta_generic_to_shared(dst + sw_idx(row, seg));
        const __nv_bfloat16* g = src + (size_t)row * ld + kc + seg * 8;
        asm volatile("cp.async.cg.shared.global [%0], [%1], 16;" :: "r"(d), "l"(g));
    }
}
__device__ __forceinline__ void load_a_frag(uint32_t a[4][4], const __nv_bfloat16* plane,
                                            int m0, int seg_base, int lane)
{
    const int r = lane & 15, half = lane >> 4;
    #pragma unroll
    for (int t = 0; t < 4; t++)
        ldsm_x4(a[t], plane + sw_idx(m0 + t * 16 + r, seg_base + half));
}
__device__ __forceinline__ void load_b_frag(uint32_t b[4][2], const __nv_bfloat16* plane,
                                            int n0, int seg_base, int lane)
{
    const int r = lane & 15, half = lane >> 4;
    #pragma unroll
    for (int p = 0; p < 2; p++) {
        uint32_t t[4];
        ldsm_x4(t, plane + sw_idx(n0 + p * 16 + r, seg_base + half));
        b[2*p][0]   = t[0];
        b[2*p+1][0] = t[1];
        b[2*p][1]   = t[2];
        b[2*p+1][1] = t[3];
    }
}
__device__ __forceinline__ void mma_all(float acc[4][4][4], const uint32_t a[4][4],
                                        const uint32_t b[4][2])
{
    #pragma unroll
    for (int mt = 0; mt < 4; mt++)
        #pragma unroll
        for (int nt = 0; nt < 4; nt++)
            mma16816(acc[mt][nt], a[mt], b[nt]);
}

// ---------------------------------------------------------------------------
// Split-bf16 (3-product) 128x128 GEMM core with cp.async double buffering.
// sm: 2 stages x 4 planes x 4096 bf16 = 64KB dynamic smem.
// Register budget kept <=128 so mma kernels run 2 CTAs/SM (launch_bounds).
// ---------------------------------------------------------------------------
__device__ __forceinline__ void mma_core(
                         const __nv_bfloat16* __restrict__ Ah,
                         const __nv_bfloat16* __restrict__ Al, int lda,
                         const __nv_bfloat16* __restrict__ Bh,
                         const __nv_bfloat16* __restrict__ Bl, int ldb,
                         int K, __nv_bfloat16* sm, float acc[4][4][4])
{
    const int tid = threadIdx.x, lane = tid & 31, wid = tid >> 5;
    const int m0 = (wid >> 2) * 64, n0 = (wid & 3) * 32;

    #pragma unroll
    for (int mt = 0; mt < 4; mt++)
        #pragma unroll
        for (int nt = 0; nt < 4; nt++)
            #pragma unroll
            for (int q = 0; q < 4; q++) acc[mt][nt][q] = 0.f;

    cp_plane(sm + 0*4096, Ah, lda, 0, tid);
    cp_plane(sm + 1*4096, Al, lda, 0, tid);
    cp_plane(sm + 2*4096, Bh, ldb, 0, tid);
    cp_plane(sm + 3*4096, Bl, ldb, 0, tid);
    asm volatile("cp.async.commit_group;");

    const int NC = K >> 5;
    for (int c = 0; c < NC; c++) {
        __nv_bfloat16* st = sm + (c & 1) * 16384;
        if (c + 1 < NC) {
            __nv_bfloat16* st2 = sm + ((c + 1) & 1) * 16384;
            const int kc = (c + 1) * 32;
            cp_plane(st2 + 0*4096, Ah, lda, kc, tid);
            cp_plane(st2 + 1*4096, Al, lda, kc, tid);
            cp_plane(st2 + 2*4096, Bh, ldb, kc, tid);
            cp_plane(st2 + 3*4096, Bl, ldb, kc, tid);
            asm volatile("cp.async.commit_group;");
            asm volatile("cp.async.wait_group 1;");
        } else {
            asm volatile("cp.async.wait_group 0;");
        }
        __syncthreads();
        #pragma unroll
        for (int ks = 0; ks < 2; ks++) {
            const int seg = ks * 2;
            uint32_t a[4][4];
            uint32_t b[4][2];
            load_b_frag(b, st + 2*4096, n0, seg, lane);   // B hi
            load_a_frag(a, st + 0*4096, m0, seg, lane);   // A hi
            mma_all(acc, a, b);                           // hi*hi
            load_a_frag(a, st + 1*4096, m0, seg, lane);   // A lo
            mma_all(acc, a, b);                           // lo*hi
            load_b_frag(b, st + 3*4096, n0, seg, lane);   // B lo
            load_a_frag(a, st + 0*4096, m0, seg, lane);   // A hi
            mma_all(acc, a, b);                           // hi*lo
        }
        __syncthreads();
    }
}

// LayerNorm over 128 cols in mma fragment layout. lnbuf >= 1280 floats.
__device__ __forceinline__ void ln_mma(float acc[4][4][4], float* lnbuf)
{
    float* lnS = lnbuf;
    float* lnQ = lnbuf + 512;
    float* mrs = lnbuf + 1024;
    const int tid = threadIdx.x, lane = tid & 31, wid = tid >> 5;
    const int wn = wid & 3, m0 = (wid >> 2) * 64;
    const int rr = lane >> 2, cg = lane & 3;

    #pragma unroll
    for (int mt = 0; mt < 4; mt++)
        #pragma unroll
        for (int half = 0; half < 2; half++) {
            float s = 0.f, q = 0.f;
            #pragma unroll
            for (int nt = 0; nt < 4; nt++) {
                float v0 = acc[mt][nt][2*half], v1 = acc[mt][nt][2*half+1];
                s += v0 + v1; q += v0 * v0 + v1 * v1;
            }
            s += __shfl_xor_sync(0xffffffffu, s, 1);
            s += __shfl_xor_sync(0xffffffffu, s, 2);
            q += __shfl_xor_sync(0xffffffffu, q, 1);
            q += __shfl_xor_sync(0xffffffffu, q, 2);
            if (cg == 0) {
                int row = m0 + mt * 16 + half * 8 + rr;
                lnS[row * 4 + wn] = s;
                lnQ[row * 4 + wn] = q;
            }
        }
    __syncthreads();
    if (tid < 128) {
        float s = lnS[tid*4] + lnS[tid*4+1] + lnS[tid*4+2] + lnS[tid*4+3];
        float q = lnQ[tid*4] + lnQ[tid*4+1] + lnQ[tid*4+2] + lnQ[tid*4+3];
        float mean = s * (1.0f / 128.0f);
        float var  = q * (1.0f / 128.0f) - mean * mean;
        mrs[tid]       = mean;
        mrs[128 + tid] = rsqrtf(var + 1e-5f);
    }
    __syncthreads();
    #pragma unroll
    for (int mt = 0; mt < 4; mt++)
        #pragma unroll
        for (int half = 0; half < 2; half++) {
            int row = m0 + mt * 16 + half * 8 + rr;
            float mu = mrs[row], rs = mrs[128 + row];
            #pragma unroll
            for (int nt = 0; nt < 4; nt++) {
                acc[mt][nt][2*half]   = (acc[mt][nt][2*half]   - mu) * rs;
                acc[mt][nt][2*half+1] = (acc[mt][nt][2*half+1] - mu) * rs;
            }
        }
}

__device__ __forceinline__ uint32_t pack_hi2(float v0, float v1, uint32_t& lo)
{
    __nv_bfloat16 h0 = __float2bfloat16(v0), h1 = __float2bfloat16(v1);
    __nv_bfloat16 l0 = __float2bfloat16(v0 - __bfloat162float(h0));
    __nv_bfloat16 l1 = __float2bfloat16(v1 - __bfloat162float(h1));
    lo = (uint32_t)__bfloat16_as_ushort(l0) | ((uint32_t)__bfloat16_as_ushort(l1) << 16);
    return (uint32_t)__bfloat16_as_ushort(h0) | ((uint32_t)__bfloat16_as_ushort(h1) << 16);
}

__device__ __forceinline__ void store_hilo(const float acc[4][4][4],
                                           __nv_bfloat16* oh, __nv_bfloat16* ol,
                                           int ldc)
{
    const int lane = threadIdx.x & 31, wid = threadIdx.x >> 5;
    const int m0 = (wid >> 2) * 64, n0 = (wid & 3) * 32;
    const int rr = lane >> 2, cg = lane & 3;
    #pragma unroll
    for (int mt = 0; mt < 4; mt++)
        #pragma unroll
        for (int half = 0; half < 2; half++) {
            int row = m0 + mt * 16 + half * 8 + rr;
            #pragma unroll
            for (int nt = 0; nt < 4; nt++) {
                int c = n0 + nt * 8 + 2 * cg;
                uint32_t lo;
                uint32_t hi = pack_hi2(acc[mt][nt][2*half], acc[mt][nt][2*half+1], lo);
                *reinterpret_cast<uint32_t*>(oh + (size_t)row * ldc + c) = hi;
                *reinterpret_cast<uint32_t*>(ol + (size_t)row * ldc + c) = lo;
            }
        }
}

// ======================= fused prep kernel =======================
// transpose+split a [R,C] fp32 matrix -> dst hi/lo [C,R] bf16 (one 32x32 tile)
__device__ __forceinline__ void transplit_tile(const float* src, __nv_bfloat16* dh,
                                               __nv_bfloat16* dl, int R, int C,
                                               int r0, int c0)
{
    __shared__ float t[32][33];
    const int tid = threadIdx.x;
    #pragma unroll
    for (int s = 0; s < 4; s++) {
        int idx = tid + s * 256;
        int r = idx >> 5, c = idx & 31;
        t[r][c] = src[(size_t)(r0 + r) * C + c0 + c];
    }
    __syncthreads();
    #pragma unroll
    for (int s = 0; s < 4; s++) {
        int idx = tid + s * 256;
        int co = idx >> 5, ro = idx & 31;
        float v = t[ro][co];
        __nv_bfloat16 h = __float2bfloat16(v);
        dh[(size_t)(c0 + co) * R + r0 + ro] = h;
        dl[(size_t)(c0 + co) * R + r0 + ro] = __float2bfloat16(v - __bfloat162float(h));
    }
}

// One launch does: x split (blocks 0..4095), Wq/Wk/Wv transposes (4096..4287),
// W1 transpose (4288..4351), W2 transpose (4352..4367).
__global__ __launch_bounds__(256) void prep_all(
    const float* __restrict__ x,
    const float* __restrict__ Wq, const float* __restrict__ Wk, const float* __restrict__ Wv,
    const float* __restrict__ W1, const float* __restrict__ W2)
{
    const int bid = blockIdx.x;
    if (bid < 4096) {
        const size_t i4 = (size_t)bid * 256 + threadIdx.x;
        float4 v = *reinterpret_cast<const float4*>(x + i4 * 4);
        uint32_t l0, l1;
        uint32_t h0 = pack_hi2(v.x, v.y, l0);
        uint32_t h1 = pack_hi2(v.z, v.w, l1);
        *reinterpret_cast<uint2*>(g_xh + i4 * 4) = make_uint2(h0, h1);
        *reinterpret_cast<uint2*>(g_xl + i4 * 4) = make_uint2(l0, l1);
    } else if (bid < 4288) {
        const int j = bid - 4096;            // 192 blocks: 12 matrices x 16 tiles
        const int midx = j >> 4, rem = j & 15;
        const int which = midx >> 2, h = midx & 3;
        const float* src = (which == 0 ? Wq : (which == 1 ? Wk : Wv)) + (size_t)h * 128 * 128;
        transplit_tile(src, g_WTh + (size_t)midx * 16384, g_WTl + (size_t)midx * 16384,
                       128, 128, (rem >> 2) * 32, (rem & 3) * 32);
    } else if (bid < 4352) {
        const int j = bid - 4288;            // 64 blocks: 16 x 4 tiles of [512,128]
        transplit_tile(W1, g_W1Th, g_W1Tl, 512, 128, (j >> 2) * 32, (j & 3) * 32);
    } else {
        const int j = bid - 4352;            // 16 blocks: 4 x 4 tiles of [128,128]
        transplit_tile(W2, g_W2Th, g_W2Tl, 128, 128, (j >> 2) * 32, (j & 3) * 32);
    }
}

// ======================= main kernels =======================
extern __shared__ __nv_bfloat16 dynsm[];

// QKV: grid (256, 4, 3)
__global__ __launch_bounds__(256, 2) void qkv_mma(
    const float* __restrict__ bq, const float* __restrict__ bk, const float* __restrict__ bv)
{
    const int rowBase = blockIdx.x * 128;
    const int h = blockIdx.y, which = blockIdx.z;
    const int midx = which * 4 + h;
    const float* bias = (which == 0 ? bq : (which == 1 ? bk : bv)) + (size_t)h * 128;

    float acc[4][4][4];
    mma_core(g_xh + (size_t)rowBase * E, g_xl + (size_t)rowBase * E, E,
             g_WTh + (size_t)midx * 16384, g_WTl + (size_t)midx * 16384, E,
             E, dynsm, acc);

    const int lane = threadIdx.x & 31, wid = threadIdx.x >> 5;
    const int n0 = (wid & 3) * 32, cg = lane & 3;
    #pragma unroll
    for (int nt = 0; nt < 4; nt++) {
        float2 bv2 = *reinterpret_cast<const float2*>(bias + n0 + nt * 8 + 2 * cg);
        #pragma unroll
        for (int mt = 0; mt < 4; mt++) {
            acc[mt][nt][0] += bv2.x; acc[mt][nt][1] += bv2.y;
            acc[mt][nt][2] += bv2.x; acc[mt][nt][3] += bv2.y;
        }
    }
    ln_mma(acc, (float*)dynsm);

    const int b = rowBase >> 9, nBase = rowBase & 511;
    const int bh = b * H + h;
    const size_t off = ((size_t)bh * Nseq + nBase) * 128;
    __nv_bfloat16* oh = (which == 0 ? g_Qh : (which == 1 ? g_Kh : g_Vh)) + off;
    __nv_bfloat16* ol = (which == 0 ? g_Ql : (which == 1 ? g_Kl : g_Vl)) + off;
    store_hilo(acc, oh, ol, 128);
}

// V transpose: grid (256, 4, 16)
__global__ __launch_bounds__(256) void vtrans_kernel()
{
    __shared__ __nv_bfloat16 th[32][33], tl[32][33];
    const int bh = blockIdx.x, e0 = blockIdx.y * 32, n0 = blockIdx.z * 32;
    const int tid = threadIdx.x;
    const size_t inBase = ((size_t)bh * Nseq + n0) * E + e0;
    #pragma unroll
    for (int s = 0; s < 4; s++) {
        int idx = tid + s * 256;
        int r = idx >> 5, c = idx & 31;
        th[r][c] = g_Vh[inBase + (size_t)r * E + c];
        tl[r][c] = g_Vl[inBase + (size_t)r * E + c];
    }
    __syncthreads();
    const size_t outBase = ((size_t)bh * E + e0) * Nseq + n0;
    #pragma unroll
    for (int s = 0; s < 4; s++) {
        int idx = tid + s * 256;
        int r = idx >> 5, c = idx & 31;
        g_Vth[outBase + (size_t)r * Nseq + c] = th[c][r];
        g_Vtl[outBase + (size_t)r * Nseq + c] = tl[c][r];
    }
}

// scores = Q K^T -> fp32 S. grid (4, 4, 256)
__global__ __launch_bounds__(256, 2) void scores_mma()
{
    const int bh = blockIdx.z;
    const size_t rowBase = blockIdx.x * 128, colBase = blockIdx.y * 128;
    float acc[4][4][4];
    mma_core(g_Qh + ((size_t)bh * Nseq + rowBase) * D,
             g_Ql + ((size_t)bh * Nseq + rowBase) * D, D,
             g_Kh + ((size_t)bh * Nseq + colBase) * D,
             g_Kl + ((size_t)bh * Nseq + colBase) * D, D, D, dynsm, acc);

    float* Cout = g_S + (size_t)bh * Nseq * Nseq + rowBase * Nseq + colBase;
    const int lane = threadIdx.x & 31, wid = threadIdx.x >> 5;
    const int m0 = (wid >> 2) * 64, n0 = (wid & 3) * 32;
    const int rr = lane >> 2, cg = lane & 3;
    #pragma unroll
    for (int mt = 0; mt < 4; mt++)
        #pragma unroll
        for (int half = 0; half < 2; half++) {
            int r = m0 + mt * 16 + half * 8 + rr;
            #pragma unroll
            for (int nt = 0; nt < 4; nt++) {
                int c = n0 + nt * 8 + 2 * cg;
                *reinterpret_cast<float2*>(Cout + (size_t)r * Nseq + c) =
                    make_float2(acc[mt][nt][2*half], acc[mt][nt][2*half+1]);
            }
        }
}

// batch-axis softmax. grid (4096)
__global__ __launch_bounds__(256) void softmax_kernel()
{
    const size_t idx = (size_t)blockIdx.x * 256 + threadIdx.x;
    const size_t stride = (size_t)H * Nseq * Nseq;
    float v[64];
    float mx = -1e30f;
    #pragma unroll
    for (int b = 0; b < 64; b++) {
        float t = g_S[(size_t)b * stride + idx] * (1.0f / 11.0f);
        v[b] = t;
        mx = fmaxf(mx, t);
    }
    float s = 0.f;
    #pragma unroll
    for (int b = 0; b < 64; b++) { float e = __expf(v[b] - mx); v[b] = e; s += e; }
    const float inv = 1.0f / s;
    #pragma unroll
    for (int b = 0; b < 64; b++) {
        float p = v[b] * inv;
        __nv_bfloat16 hp = __float2bfloat16(p);
        __nv_bfloat16 lp = __float2bfloat16(p - __bfloat162float(hp));
        g_Ph[(size_t)b * stride + idx] = hp;
        g_Pl[(size_t)b * stride + idx] = lp;
    }
}

// A = P V -> hi/lo concat layout. grid (4, 1, 256)
__global__ __launch_bounds__(256, 2) void av_mma()
{
    const int bh = blockIdx.z, b = bh >> 2, h = bh & 3;
    const size_t rowBase = blockIdx.x * 128;
    float acc[4][4][4];
    mma_core(g_Ph + ((size_t)bh * Nseq + rowBase) * Nseq,
             g_Pl + ((size_t)bh * Nseq + rowBase) * Nseq, Nseq,
             g_Vth + (size_t)bh * E * Nseq,
             g_Vtl + (size_t)bh * E * Nseq, Nseq, Nseq, dynsm, acc);
    const size_t off = ((size_t)b * Nseq + rowBase) * (H * E) + (size_t)h * E;
    store_hilo(acc, g_Ah + off, g_Al + off, H * E);
}

// h1 = relu(A @ W1 + b1) -> hi/lo. grid (256)
__global__ __launch_bounds__(256, 2) void mlp1_mma(const float* __restrict__ b1)
{
    const int rowBase = blockIdx.x * 128;
    float acc[4][4][4];
    mma_core(g_Ah + (size_t)rowBase * (H * E), g_Al + (size_t)rowBase * (H * E), H * E,
             g_W1Th, g_W1Tl, H * E, H * E, dynsm, acc);

    const int lane = threadIdx.x & 31, wid = threadIdx.x >> 5;
    const int n0 = (wid & 3) * 32, cg = lane & 3;
    #pragma unroll
    for (int nt = 0; nt < 4; nt++) {
        float2 bv2 = *reinterpret_cast<const float2*>(b1 + n0 + nt * 8 + 2 * cg);
        #pragma unroll
        for (int mt = 0; mt < 4; mt++) {
            acc[mt][nt][0] = fmaxf(acc[mt][nt][0] + bv2.x, 0.f);
            acc[mt][nt][1] = fmaxf(acc[mt][nt][1] + bv2.y, 0.f);
            acc[mt][nt][2] = fmaxf(acc[mt][nt][2] + bv2.x, 0.f);
            acc[mt][nt][3] = fmaxf(acc[mt][nt][3] + bv2.y, 0.f);
        }
    }
    store_hilo(acc, g_H1h + (size_t)rowBase * E, g_H1l + (size_t)rowBase * E, E);
}

// out = LN(x + relu(h1 @ W2 + b2)) * gamma + beta. grid (256)
__global__ __launch_bounds__(256, 2) void mlp2_mma(
    const float* __restrict__ x, const float* __restrict__ b2,
    const float* __restrict__ gamma, const float* __restrict__ beta,
    float* __restrict__ out)
{
    const int rowBase = blockIdx.x * 128;
    float acc[4][4][4];
    mma_core(g_H1h + (size_t)rowBase * E, g_H1l + (size_t)rowBase * E, E,
             g_W2Th, g_W2Tl, E, E, dynsm, acc);

    const int lane = threadIdx.x & 31, wid = threadIdx.x >> 5;
    const int m0 = (wid >> 2) * 64, n0 = (wid & 3) * 32;
    const int rr = lane >> 2, cg = lane & 3;
    #pragma unroll
    for (int nt = 0; nt < 4; nt++) {
        const int c = n0 + nt * 8 + 2 * cg;
        float2 bv2 = *reinterpret_cast<const float2*>(b2 + c);
        #pragma unroll
        for (int mt = 0; mt < 4; mt++)
            #pragma unroll
            for (int half = 0; half < 2; half++) {
                int row = rowBase + m0 + mt * 16 + half * 8 + rr;
                float2 xv = *reinterpret_cast<const float2*>(x + (size_t)row * E + c);
                acc[mt][nt][2*half]   = fmaxf(acc[mt][nt][2*half]   + bv2.x, 0.f) + xv.x;
                acc[mt][nt][2*half+1] = fmaxf(acc[mt][nt][2*half+1] + bv2.y, 0.f) + xv.y;
            }
    }

    ln_mma(acc, (float*)dynsm);

    #pragma unroll
    for (int nt = 0; nt < 4; nt++) {
        const int c = n0 + nt * 8 + 2 * cg;
        float2 gv = *reinterpret_cast<const float2*>(gamma + c);
        float2 ev = *reinterpret_cast<const float2*>(beta + c);
        #pragma unroll
        for (int mt = 0; mt < 4; mt++)
            #pragma unroll
            for (int half = 0; half < 2; half++) {
                int row = rowBase + m0 + mt * 16 + half * 8 + rr;
                float o0 = acc[mt][nt][2*half]   * gv.x + ev.x;
                float o1 = acc[mt][nt][2*half+1] * gv.y + ev.y;
                *reinterpret_cast<float2*>(out + (size_t)row * E + c) = make_float2(o0, o1);
            }
    }
}

// ---------------------------------------------------------------------------
extern "C" void kernel_launch(void* const* d_in, const int* in_sizes, int n_in,
                              void* d_out, int out_size)
{
    const float* x     = (const float*)d_in[0];
    const float* Wq    = (const float*)d_in[1];
    const float* bq    = (const float*)d_in[2];
    const float* Wk    = (const float*)d_in[3];
    const float* bk    = (const float*)d_in[4];
    const float* Wv    = (const float*)d_in[5];
    const float* bv    = (const float*)d_in[6];
    const float* W1    = (const float*)d_in[7];
    const float* b1    = (const float*)d_in[8];
    const float* W2    = (const float*)d_in[9];
    const float* b2    = (const float*)d_in[10];
    const float* gamma = (const float*)d_in[11];
    const float* beta  = (const float*)d_in[12];
    float* out = (float*)d_out;

    const int SMEM = 2 * 4 * 4096 * (int)sizeof(__nv_bfloat16);   // 64KB
    cudaFuncSetAttribute(qkv_mma,    cudaFuncAttributeMaxDynamicSharedMemorySize, SMEM);
    cudaFuncSetAttribute(scores_mma, cudaFuncAttributeMaxDynamicSharedMemorySize, SMEM);
    cudaFuncSetAttribute(av_mma,     cudaFuncAttributeMaxDynamicSharedMemorySize, SMEM);
    cudaFuncSetAttribute(mlp1_mma,   cudaFuncAttributeMaxDynamicSharedMemorySize, SMEM);
    cudaFuncSetAttribute(mlp2_mma,   cudaFuncAttributeMaxDynamicSharedMemorySize, SMEM);

    dim3 blk(256);
    prep_all      <<<dim3(4368), blk>>>(x, Wq, Wk, Wv, W1, W2);
    qkv_mma       <<<dim3(256, 4, 3), blk, SMEM>>>(bq, bk, bv);
    vtrans_kernel <<<dim3(256, 4, 16), blk>>>();
    scores_mma    <<<dim3(4, 4, 256), blk, SMEM>>>();
    softmax_kernel<<<dim3(4096), blk>>>();
    av_mma        <<<dim3(4, 1, 256), blk, SMEM>>>();
    mlp1_mma      <<<dim3(256), blk, SMEM>>>(b1);
    mlp2_mma      <<<dim3(256), blk, SMEM>>>(x, b2, gamma, beta, out);
}

// round 12
// speedup vs baseline: 1.4269x; 1.2969x over previous
#include <cuda_runtime.h>
#include <cuda_fp16.h>
#include <cstdint>

constexpr int Bdim = 64;
constexpr int Nseq = 512;
constexpr int E    = 128;
constexpr int D    = 128;
constexpr int H    = 4;

// ---------------- scratch (allocation-free) ----------------
// A-side operands: fp16 hi/lo split (exact). B-side: single fp16.
__device__ __half g_xh [(size_t)Bdim*Nseq*E];
__device__ __half g_xl [(size_t)Bdim*Nseq*E];
__device__ __half g_WT [12 * 128 * 128];          // [which*4+h][d][e] transposed, single
__device__ __half g_W1T[128 * 512];               // [e_out][k] single
__device__ __half g_W2T[128 * 128];               // single
__device__ __half g_Qh[(size_t)Bdim*H*Nseq*D];
__device__ __half g_Ql[(size_t)Bdim*H*Nseq*D];
__device__ __half g_K [(size_t)Bdim*H*Nseq*D];    // B of scores: single
__device__ __half g_V [(size_t)Bdim*H*Nseq*E];    // [bh][n][e] single
__device__ __half g_Vt[(size_t)Bdim*H*E*Nseq];    // [bh][e][n] single (B of av)
__device__ float  g_S [(size_t)Bdim*H*Nseq*Nseq]; // fp32 scores
__device__ __half g_Ph[(size_t)Bdim*H*Nseq*Nseq];
__device__ __half g_Pl[(size_t)Bdim*H*Nseq*Nseq];
__device__ __half g_Ah[(size_t)Bdim*Nseq*H*E];    // [B,N,512] concat
__device__ __half g_Al[(size_t)Bdim*Nseq*H*E];
__device__ __half g_H1h[(size_t)Bdim*Nseq*E];
__device__ __half g_H1l[(size_t)Bdim*Nseq*E];

// ======================= mma.sync machinery (fp16) =======================
__device__ __forceinline__ void ldsm_x4(uint32_t r[4], const void* p) {
    uint32_t addr = (uint32_t)__cvta_generic_to_shared(p);
    asm volatile("ldmatrix.sync.aligned.m8n8.x4.shared.b16 {%0,%1,%2,%3}, [%4];"
                 : "=r"(r[0]), "=r"(r[1]), "=r"(r[2]), "=r"(r[3]) : "r"(addr));
}
__device__ __forceinline__ void mma16816(float c[4], const uint32_t a[4], const uint32_t b[2]) {
    asm volatile("mma.sync.aligned.m16n8k16.row.col.f32.f16.f16.f32 "
                 "{%0,%1,%2,%3}, {%4,%5,%6,%7}, {%8,%9}, {%0,%1,%2,%3};"
                 : "+f"(c[0]), "+f"(c[1]), "+f"(c[2]), "+f"(c[3])
                 : "r"(a[0]), "r"(a[1]), "r"(a[2]), "r"(a[3]), "r"(b[0]), "r"(b[1]));
}
// smem plane: 128 rows x 32 fp16 (64B rows), 16B chunks XOR-swizzled
__device__ __forceinline__ int sw_idx(int row, int seg) {
    return row * 32 + ((seg ^ ((row >> 1) & 3)) << 3);
}
__device__ __forceinline__ void cp_plane(__half* dst, const __half* src,
                                         int ld, int kc, int tid)
{
    #pragma unroll
    for (int s = 0; s < 2; s++) {
        int idx = tid + s * 256;
        int row = idx >> 2, seg = idx & 3;
        uint32_t d = (uint32_t)__cvta_generic_to_shared(dst + sw_idx(row, seg));
        const __half* g = src + (size_t)row * ld + kc + seg * 8;
        asm volatile("cp.async.cg.shared.global [%0], [%1], 16;" :: "r"(d), "l"(g));
    }
}
__device__ __forceinline__ void load_a_frag(uint32_t a[4][4], const __half* plane,
                                            int m0, int seg_base, int lane)
{
    const int r = lane & 15, half_ = lane >> 4;
    #pragma unroll
    for (int t = 0; t < 4; t++)
        ldsm_x4(a[t], plane + sw_idx(m0 + t * 16 + r, seg_base + half_));
}
__device__ __forceinline__ void load_b_frag(uint32_t b[4][2], const __half* plane,
                                            int n0, int seg_base, int lane)
{
    const int r = lane & 15, half_ = lane >> 4;
    #pragma unroll
    for (int p = 0; p < 2; p++) {
        uint32_t t[4];
        ldsm_x4(t, plane + sw_idx(n0 + p * 16 + r, seg_base + half_));
        b[2*p][0]   = t[0];
        b[2*p+1][0] = t[1];
        b[2*p][1]   = t[2];
        b[2*p+1][1] = t[3];
    }
}
__device__ __forceinline__ void mma_all(float acc[4][4][4], const uint32_t a[4][4],
                                        const uint32_t b[4][2])
{
    #pragma unroll
    for (int mt = 0; mt < 4; mt++)
        #pragma unroll
        for (int nt = 0; nt < 4; nt++)
            mma16816(acc[mt][nt], a[mt], b[nt]);
}

// ---------------------------------------------------------------------------
// Split-fp16 2-pass 128x128 GEMM core, cp.async double-buffered.
// C = (Ah + Al) * B : pass1 Ah*B, pass2 Al*B.  B single fp16 (err ~2^-12).
// sm: 2 stages x 3 planes (Ah, Al, B) x 4096 half = 48KB dynamic smem.
// ---------------------------------------------------------------------------
#define PLANE 4096
#define STAGE (3 * PLANE)

__device__ __forceinline__ void mma_core(
                         const __half* __restrict__ Ah,
                         const __half* __restrict__ Al, int lda,
                         const __half* __restrict__ B, int ldb,
                         int K, __half* sm, float acc[4][4][4])
{
    const int tid = threadIdx.x, lane = tid & 31, wid = tid >> 5;
    const int m0 = (wid >> 2) * 64, n0 = (wid & 3) * 32;

    #pragma unroll
    for (int mt = 0; mt < 4; mt++)
        #pragma unroll
        for (int nt = 0; nt < 4; nt++)
            #pragma unroll
            for (int q = 0; q < 4; q++) acc[mt][nt][q] = 0.f;

    cp_plane(sm + 0*PLANE, Ah, lda, 0, tid);
    cp_plane(sm + 1*PLANE, Al, lda, 0, tid);
    cp_plane(sm + 2*PLANE, B,  ldb, 0, tid);
    asm volatile("cp.async.commit_group;");

    const int NC = K >> 5;
    for (int c = 0; c < NC; c++) {
        __half* st = sm + (c & 1) * STAGE;
        if (c + 1 < NC) {
            __half* st2 = sm + ((c + 1) & 1) * STAGE;
            const int kc = (c + 1) * 32;
            cp_plane(st2 + 0*PLANE, Ah, lda, kc, tid);
            cp_plane(st2 + 1*PLANE, Al, lda, kc, tid);
            cp_plane(st2 + 2*PLANE, B,  ldb, kc, tid);
            asm volatile("cp.async.commit_group;");
            asm volatile("cp.async.wait_group 1;");
        } else {
            asm volatile("cp.async.wait_group 0;");
        }
        __syncthreads();
        #pragma unroll
        for (int ks = 0; ks < 2; ks++) {
            const int seg = ks * 2;
            uint32_t a[4][4];
            uint32_t b[4][2];
            load_b_frag(b, st + 2*PLANE, n0, seg, lane);  // B
            load_a_frag(a, st + 0*PLANE, m0, seg, lane);  // A hi
            mma_all(acc, a, b);                           // hi*B
            load_a_frag(a, st + 1*PLANE, m0, seg, lane);  // A lo
            mma_all(acc, a, b);                           // lo*B
        }
        __syncthreads();
    }
}

// LayerNorm over 128 cols in mma fragment layout. lnbuf >= 1280 floats.
__device__ __forceinline__ void ln_mma(float acc[4][4][4], float* lnbuf)
{
    float* lnS = lnbuf;
    float* lnQ = lnbuf + 512;
    float* mrs = lnbuf + 1024;
    const int tid = threadIdx.x, lane = tid & 31, wid = tid >> 5;
    const int wn = wid & 3, m0 = (wid >> 2) * 64;
    const int rr = lane >> 2, cg = lane & 3;

    #pragma unroll
    for (int mt = 0; mt < 4; mt++)
        #pragma unroll
        for (int half_ = 0; half_ < 2; half_++) {
            float s = 0.f, q = 0.f;
            #pragma unroll
            for (int nt = 0; nt < 4; nt++) {
                float v0 = acc[mt][nt][2*half_], v1 = acc[mt][nt][2*half_+1];
                s += v0 + v1; q += v0 * v0 + v1 * v1;
            }
            s += __shfl_xor_sync(0xffffffffu, s, 1);
            s += __shfl_xor_sync(0xffffffffu, s, 2);
            q += __shfl_xor_sync(0xffffffffu, q, 1);
            q += __shfl_xor_sync(0xffffffffu, q, 2);
            if (cg == 0) {
                int row = m0 + mt * 16 + half_ * 8 + rr;
                lnS[row * 4 + wn] = s;
                lnQ[row * 4 + wn] = q;
            }
        }
    __syncthreads();
    if (tid < 128) {
        float s = lnS[tid*4] + lnS[tid*4+1] + lnS[tid*4+2] + lnS[tid*4+3];
        float q = lnQ[tid*4] + lnQ[tid*4+1] + lnQ[tid*4+2] + lnQ[tid*4+3];
        float mean = s * (1.0f / 128.0f);
        float var  = q * (1.0f / 128.0f) - mean * mean;
        mrs[tid]       = mean;
        mrs[128 + tid] = rsqrtf(var + 1e-5f);
    }
    __syncthreads();
    #pragma unroll
    for (int mt = 0; mt < 4; mt++)
        #pragma unroll
        for (int half_ = 0; half_ < 2; half_++) {
            int row = m0 + mt * 16 + half_ * 8 + rr;
            float mu = mrs[row], rs = mrs[128 + row];
            #pragma unroll
            for (int nt = 0; nt < 4; nt++) {
                acc[mt][nt][2*half_]   = (acc[mt][nt][2*half_]   - mu) * rs;
                acc[mt][nt][2*half_+1] = (acc[mt][nt][2*half_+1] - mu) * rs;
            }
        }
}

__device__ __forceinline__ uint32_t pack_h2(float v0, float v1, uint32_t& lo)
{
    __half h0 = __float2half(v0), h1 = __float2half(v1);
    __half l0 = __float2half(v0 - __half2float(h0));
    __half l1 = __float2half(v1 - __half2float(h1));
    lo = (uint32_t)__half_as_ushort(l0) | ((uint32_t)__half_as_ushort(l1) << 16);
    return (uint32_t)__half_as_ushort(h0) | ((uint32_t)__half_as_ushort(h1) << 16);
}
__device__ __forceinline__ uint32_t pack_s2(float v0, float v1)
{
    __half h0 = __float2half(v0), h1 = __float2half(v1);
    return (uint32_t)__half_as_ushort(h0) | ((uint32_t)__half_as_ushort(h1) << 16);
}

__device__ __forceinline__ void store_hilo(const float acc[4][4][4],
                                           __half* oh, __half* ol, int ldc)
{
    const int lane = threadIdx.x & 31, wid = threadIdx.x >> 5;
    const int m0 = (wid >> 2) * 64, n0 = (wid & 3) * 32;
    const int rr = lane >> 2, cg = lane & 3;
    #pragma unroll
    for (int mt = 0; mt < 4; mt++)
        #pragma unroll
        for (int half_ = 0; half_ < 2; half_++) {
            int row = m0 + mt * 16 + half_ * 8 + rr;
            #pragma unroll
            for (int nt = 0; nt < 4; nt++) {
                int c = n0 + nt * 8 + 2 * cg;
                uint32_t lo;
                uint32_t hi = pack_h2(acc[mt][nt][2*half_], acc[mt][nt][2*half_+1], lo);
                *reinterpret_cast<uint32_t*>(oh + (size_t)row * ldc + c) = hi;
                *reinterpret_cast<uint32_t*>(ol + (size_t)row * ldc + c) = lo;
            }
        }
}
__device__ __forceinline__ void store_single(const float acc[4][4][4],
                                             __half* o, int ldc)
{
    const int lane = threadIdx.x & 31, wid = threadIdx.x >> 5;
    const int m0 = (wid >> 2) * 64, n0 = (wid & 3) * 32;
    const int rr = lane >> 2, cg = lane & 3;
    #pragma unroll
    for (int mt = 0; mt < 4; mt++)
        #pragma unroll
        for (int half_ = 0; half_ < 2; half_++) {
            int row = m0 + mt * 16 + half_ * 8 + rr;
            #pragma unroll
            for (int nt = 0; nt < 4; nt++) {
                int c = n0 + nt * 8 + 2 * cg;
                *reinterpret_cast<uint32_t*>(o + (size_t)row * ldc + c) =
                    pack_s2(acc[mt][nt][2*half_], acc[mt][nt][2*half_+1]);
            }
        }
}

// ======================= fused prep kernel =======================
// transpose a [R,C] fp32 matrix tile -> dst single fp16 [C,R]
__device__ __forceinline__ void transplit_tile(const float* src, __half* dh,
                                               int R, int C, int r0, int c0)
{
    __shared__ float t[32][33];
    const int tid = threadIdx.x;
    #pragma unroll
    for (int s = 0; s < 4; s++) {
        int idx = tid + s * 256;
        int r = idx >> 5, c = idx & 31;
        t[r][c] = src[(size_t)(r0 + r) * C + c0 + c];
    }
    __syncthreads();
    #pragma unroll
    for (int s = 0; s < 4; s++) {
        int idx = tid + s * 256;
        int co = idx >> 5, ro = idx & 31;
        dh[(size_t)(c0 + co) * R + r0 + ro] = __float2half(t[ro][co]);
    }
}

// blocks: 0..4095 x split; 4096..4287 W qkv; 4288..4351 W1; 4352..4367 W2
__global__ __launch_bounds__(256) void prep_all(
    const float* __restrict__ x,
    const float* __restrict__ Wq, const float* __restrict__ Wk, const float* __restrict__ Wv,
    const float* __restrict__ W1, const float* __restrict__ W2)
{
    const int bid = blockIdx.x;
    if (bid < 4096) {
        const size_t i4 = (size_t)bid * 256 + threadIdx.x;
        float4 v = *reinterpret_cast<const float4*>(x + i4 * 4);
        uint32_t l0, l1;
        uint32_t h0 = pack_h2(v.x, v.y, l0);
        uint32_t h1 = pack_h2(v.z, v.w, l1);
        *reinterpret_cast<uint2*>(g_xh + i4 * 4) = make_uint2(h0, h1);
        *reinterpret_cast<uint2*>(g_xl + i4 * 4) = make_uint2(l0, l1);
    } else if (bid < 4288) {
        const int j = bid - 4096;
        const int midx = j >> 4, rem = j & 15;
        const int which = midx >> 2, h = midx & 3;
        const float* src = (which == 0 ? Wq : (which == 1 ? Wk : Wv)) + (size_t)h * 128 * 128;
        transplit_tile(src, g_WT + (size_t)midx * 16384,
                       128, 128, (rem >> 2) * 32, (rem & 3) * 32);
    } else if (bid < 4352) {
        const int j = bid - 4288;
        transplit_tile(W1, g_W1T, 512, 128, (j >> 2) * 32, (j & 3) * 32);
    } else {
        const int j = bid - 4352;
        transplit_tile(W2, g_W2T, 128, 128, (j >> 2) * 32, (j & 3) * 32);
    }
}

// ======================= main kernels =======================
extern __shared__ __half dynsm[];

// QKV: grid (256, 4, 3). Q -> hi/lo, K/V -> single.
__global__ __launch_bounds__(256, 2) void qkv_mma(
    const float* __restrict__ bq, const float* __restrict__ bk, const float* __restrict__ bv)
{
    const int rowBase = blockIdx.x * 128;
    const int h = blockIdx.y, which = blockIdx.z;
    const int midx = which * 4 + h;
    const float* bias = (which == 0 ? bq : (which == 1 ? bk : bv)) + (size_t)h * 128;

    float acc[4][4][4];
    mma_core(g_xh + (size_t)rowBase * E, g_xl + (size_t)rowBase * E, E,
             g_WT + (size_t)midx * 16384, E, E, dynsm, acc);

    const int lane = threadIdx.x & 31, wid = threadIdx.x >> 5;
    const int n0 = (wid & 3) * 32, cg = lane & 3;
    #pragma unroll
    for (int nt = 0; nt < 4; nt++) {
        float2 bv2 = *reinterpret_cast<const float2*>(bias + n0 + nt * 8 + 2 * cg);
        #pragma unroll
        for (int mt = 0; mt < 4; mt++) {
            acc[mt][nt][0] += bv2.x; acc[mt][nt][1] += bv2.y;
            acc[mt][nt][2] += bv2.x; acc[mt][nt][3] += bv2.y;
        }
    }
    ln_mma(acc, (float*)dynsm);

    const int b = rowBase >> 9, nBase = rowBase & 511;
    const int bh = b * H + h;
    const size_t off = ((size_t)bh * Nseq + nBase) * 128;
    if (which == 0)      store_hilo(acc, g_Qh + off, g_Ql + off, 128);
    else if (which == 1) store_single(acc, g_K + off, 128);
    else                 store_single(acc, g_V + off, 128);
}

// V transpose (single plane): grid (256, 4, 16)
__global__ __launch_bounds__(256) void vtrans_kernel()
{
    __shared__ __half t[32][33];
    const int bh = blockIdx.x, e0 = blockIdx.y * 32, n0 = blockIdx.z * 32;
    const int tid = threadIdx.x;
    const size_t inBase = ((size_t)bh * Nseq + n0) * E + e0;
    #pragma unroll
    for (int s = 0; s < 4; s++) {
        int idx = tid + s * 256;
        int r = idx >> 5, c = idx & 31;
        t[r][c] = g_V[inBase + (size_t)r * E + c];
    }
    __syncthreads();
    const size_t outBase = ((size_t)bh * E + e0) * Nseq + n0;
    #pragma unroll
    for (int s = 0; s < 4; s++) {
        int idx = tid + s * 256;
        int r = idx >> 5, c = idx & 31;
        g_Vt[outBase + (size_t)r * Nseq + c] = t[c][r];
    }
}

// scores = Q K^T -> fp32 S. grid (4, 4, 256)
__global__ __launch_bounds__(256, 2) void scores_mma()
{
    const int bh = blockIdx.z;
    const size_t rowBase = blockIdx.x * 128, colBase = blockIdx.y * 128;
    float acc[4][4][4];
    mma_core(g_Qh + ((size_t)bh * Nseq + rowBase) * D,
             g_Ql + ((size_t)bh * Nseq + rowBase) * D, D,
             g_K + ((size_t)bh * Nseq + colBase) * D, D, D, dynsm, acc);

    float* Cout = g_S + (size_t)bh * Nseq * Nseq + rowBase * Nseq + colBase;
    const int lane = threadIdx.x & 31, wid = threadIdx.x >> 5;
    const int m0 = (wid >> 2) * 64, n0 = (wid & 3) * 32;
    const int rr = lane >> 2, cg = lane & 3;
    #pragma unroll
    for (int mt = 0; mt < 4; mt++)
        #pragma unroll
        for (int half_ = 0; half_ < 2; half_++) {
            int r = m0 + mt * 16 + half_ * 8 + rr;
            #pragma unroll
            for (int nt = 0; nt < 4; nt++) {
                int c = n0 + nt * 8 + 2 * cg;
                *reinterpret_cast<float2*>(Cout + (size_t)r * Nseq + c) =
                    make_float2(acc[mt][nt][2*half_], acc[mt][nt][2*half_+1]);
            }
        }
}

// batch-axis softmax -> P hi/lo. grid (4096)
__global__ __launch_bounds__(256) void softmax_kernel()
{
    const size_t idx = (size_t)blockIdx.x * 256 + threadIdx.x;
    const size_t stride = (size_t)H * Nseq * Nseq;
    float v[64];
    float mx = -1e30f;
    #pragma unroll
    for (int b = 0; b < 64; b++) {
        float t = g_S[(size_t)b * stride + idx] * (1.0f / 11.0f);
        v[b] = t;
        mx = fmaxf(mx, t);
    }
    float s = 0.f;
    #pragma unroll
    for (int b = 0; b < 64; b++) { float e = __expf(v[b] - mx); v[b] = e; s += e; }
    const float inv = 1.0f / s;
    #pragma unroll
    for (int b = 0; b < 64; b++) {
        float p = v[b] * inv;
        __half hp = __float2half(p);
        __half lp = __float2half(p - __half2float(hp));
        g_Ph[(size_t)b * stride + idx] = hp;
        g_Pl[(size_t)b * stride + idx] = lp;
    }
}

// A = P V -> hi/lo concat layout. grid (4, 1, 256)
__global__ __launch_bounds__(256, 2) void av_mma()
{
    const int bh = blockIdx.z, b = bh >> 2, h = bh & 3;
    const size_t rowBase = blockIdx.x * 128;
    float acc[4][4][4];
    mma_core(g_Ph + ((size_t)bh * Nseq + rowBase) * Nseq,
             g_Pl + ((size_t)bh * Nseq + rowBase) * Nseq, Nseq,
             g_Vt + (size_t)bh * E * Nseq, Nseq, Nseq, dynsm, acc);
    const size_t off = ((size_t)b * Nseq + rowBase) * (H * E) + (size_t)h * E;
    store_hilo(acc, g_Ah + off, g_Al + off, H * E);
}

// h1 = relu(A @ W1 + b1) -> hi/lo. grid (256)
__global__ __launch_bounds__(256, 2) void mlp1_mma(const float* __restrict__ b1)
{
    const int rowBase = blockIdx.x * 128;
    float acc[4][4][4];
    mma_core(g_Ah + (size_t)rowBase * (H * E), g_Al + (size_t)rowBase * (H * E), H * E,
             g_W1T, H * E, H * E, dynsm, acc);

    const int lane = threadIdx.x & 31, wid = threadIdx.x >> 5;
    const int n0 = (wid & 3) * 32, cg = lane & 3;
    #pragma unroll
    for (int nt = 0; nt < 4; nt++) {
        float2 bv2 = *reinterpret_cast<const float2*>(b1 + n0 + nt * 8 + 2 * cg);
        #pragma unroll
        for (int mt = 0; mt < 4; mt++) {
            acc[mt][nt][0] = fmaxf(acc[mt][nt][0] + bv2.x, 0.f);
            acc[mt][nt][1] = fmaxf(acc[mt][nt][1] + bv2.y, 0.f);
            acc[mt][nt][2] = fmaxf(acc[mt][nt][2] + bv2.x, 0.f);
            acc[mt][nt][3] = fmaxf(acc[mt][nt][3] + bv2.y, 0.f);
        }
    }
    store_hilo(acc, g_H1h + (size_t)rowBase * E, g_H1l + (size_t)rowBase * E, E);
}

// out = LN(x + relu(h1 @ W2 + b2)) * gamma + beta. grid (256)
__global__ __launch_bounds__(256, 2) void mlp2_mma(
    const float* __restrict__ x, const float* __restrict__ b2,
    const float* __restrict__ gamma, const float* __restrict__ beta,
    float* __restrict__ out)
{
    const int rowBase = blockIdx.x * 128;
    float acc[4][4][4];
    mma_core(g_H1h + (size_t)rowBase * E, g_H1l + (size_t)rowBase * E, E,
             g_W2T, E, E, dynsm, acc);

    const int lane = threadIdx.x & 31, wid = threadIdx.x >> 5;
    const int m0 = (wid >> 2) * 64, n0 = (wid & 3) * 32;
    const int rr = lane >> 2, cg = lane & 3;
    #pragma unroll
    for (int nt = 0; nt < 4; nt++) {
        const int c = n0 + nt * 8 + 2 * cg;
        float2 bv2 = *reinterpret_cast<const float2*>(b2 + c);
        #pragma unroll
        for (int mt = 0; mt < 4; mt++)
            #pragma unroll
            for (int half_ = 0; half_ < 2; half_++) {
                int row = rowBase + m0 + mt * 16 + half_ * 8 + rr;
                float2 xv = *reinterpret_cast<const float2*>(x + (size_t)row * E + c);
                acc[mt][nt][2*half_]   = fmaxf(acc[mt][nt][2*half_]   + bv2.x, 0.f) + xv.x;
                acc[mt][nt][2*half_+1] = fmaxf(acc[mt][nt][2*half_+1] + bv2.y, 0.f) + xv.y;
            }
    }

    ln_mma(acc, (float*)dynsm);

    #pragma unroll
    for (int nt = 0; nt < 4; nt++) {
        const int c = n0 + nt * 8 + 2 * cg;
        float2 gv = *reinterpret_cast<const float2*>(gamma + c);
        float2 ev = *reinterpret_cast<const float2*>(beta + c);
        #pragma unroll
        for (int mt = 0; mt < 4; mt++)
            #pragma unroll
            for (int half_ = 0; half_ < 2; half_++) {
                int row = rowBase + m0 + mt * 16 + half_ * 8 + rr;
                float o0 = acc[mt][nt][2*half_]   * gv.x + ev.x;
                float o1 = acc[mt][nt][2*half_+1] * gv.y + ev.y;
                *reinterpret_cast<float2*>(out + (size_t)row * E + c) = make_float2(o0, o1);
            }
    }
}

// ---------------------------------------------------------------------------
extern "C" void kernel_launch(void* const* d_in, const int* in_sizes, int n_in,
                              void* d_out, int out_size)
{
    const float* x     = (const float*)d_in[0];
    const float* Wq    = (const float*)d_in[1];
    const float* bq    = (const float*)d_in[2];
    const float* Wk    = (const float*)d_in[3];
    const float* bk    = (const float*)d_in[4];
    const float* Wv    = (const float*)d_in[5];
    const float* bv    = (const float*)d_in[6];
    const float* W1    = (const float*)d_in[7];
    const float* b1    = (const float*)d_in[8];
    const float* W2    = (const float*)d_in[9];
    const float* b2    = (const float*)d_in[10];
    const float* gamma = (const float*)d_in[11];
    const float* beta  = (const float*)d_in[12];
    float* out = (float*)d_out;

    const int SMEM = 2 * 3 * 4096 * (int)sizeof(__half);   // 48KB
    cudaFuncSetAttribute(qkv_mma,    cudaFuncAttributeMaxDynamicSharedMemorySize, SMEM);
    cudaFuncSetAttribute(scores_mma, cudaFuncAttributeMaxDynamicSharedMemorySize, SMEM);
    cudaFuncSetAttribute(av_mma,     cudaFuncAttributeMaxDynamicSharedMemorySize, SMEM);
    cudaFuncSetAttribute(mlp1_mma,   cudaFuncAttributeMaxDynamicSharedMemorySize, SMEM);
    cudaFuncSetAttribute(mlp2_mma,   cudaFuncAttributeMaxDynamicSharedMemorySize, SMEM);

    dim3 blk(256);
    prep_all      <<<dim3(4368), blk>>>(x, Wq, Wk, Wv, W1, W2);
    qkv_mma       <<<dim3(256, 4, 3), blk, SMEM>>>(bq, bk, bv);
    vtrans_kernel <<<dim3(256, 4, 16), blk>>>();
    scores_mma    <<<dim3(4, 4, 256), blk, SMEM>>>();
    softmax_kernel<<<dim3(4096), blk>>>();
    av_mma        <<<dim3(4, 1, 256), blk, SMEM>>>();
    mlp1_mma      <<<dim3(256), blk, SMEM>>>(b1);
    mlp2_mma      <<<dim3(256), blk, SMEM>>>(x, b2, gamma, beta, out);
}

// round 13
// speedup vs baseline: 1.6319x; 1.1437x over previous
#include <cuda_runtime.h>
#include <cuda_fp16.h>
#include <cstdint>

constexpr int Bdim = 64;
constexpr int Nseq = 512;
constexpr int E    = 128;
constexpr int D    = 128;
constexpr int H    = 4;

// ---------------- scratch (allocation-free) ----------------
__device__ __half g_xh [(size_t)Bdim*Nseq*E];
__device__ __half g_xl [(size_t)Bdim*Nseq*E];
__device__ __half g_WT [12 * 128 * 128];          // [which*4+h][d][e] transposed
__device__ __half g_W1T[128 * 512];               // [e_out][k]
__device__ __half g_W2T[128 * 128];
__device__ __half g_Qh[(size_t)Bdim*H*Nseq*D];
__device__ __half g_Ql[(size_t)Bdim*H*Nseq*D];
__device__ __half g_K [(size_t)Bdim*H*Nseq*D];
__device__ __half g_V [(size_t)Bdim*H*Nseq*E];    // [bh][n][e]
__device__ __half g_Vt[(size_t)Bdim*H*E*Nseq];    // [bh][e][n]
__device__ float  g_S [(size_t)Bdim*H*Nseq*Nseq]; // fp32 scores
__device__ __half g_P [(size_t)Bdim*H*Nseq*Nseq]; // single-plane P (post-softmax)
__device__ __half g_Ah[(size_t)Bdim*Nseq*H*E];    // [B,N,512] concat
__device__ __half g_Al[(size_t)Bdim*Nseq*H*E];
__device__ __half g_H1h[(size_t)Bdim*Nseq*E];
__device__ __half g_H1l[(size_t)Bdim*Nseq*E];

// ======================= mma.sync machinery (fp16) =======================
__device__ __forceinline__ void ldsm_x4(uint32_t r[4], const void* p) {
    uint32_t addr = (uint32_t)__cvta_generic_to_shared(p);
    asm volatile("ldmatrix.sync.aligned.m8n8.x4.shared.b16 {%0,%1,%2,%3}, [%4];"
                 : "=r"(r[0]), "=r"(r[1]), "=r"(r[2]), "=r"(r[3]) : "r"(addr));
}
__device__ __forceinline__ void mma16816(float c[4], const uint32_t a[4], const uint32_t b[2]) {
    asm volatile("mma.sync.aligned.m16n8k16.row.col.f32.f16.f16.f32 "
                 "{%0,%1,%2,%3}, {%4,%5,%6,%7}, {%8,%9}, {%0,%1,%2,%3};"
                 : "+f"(c[0]), "+f"(c[1]), "+f"(c[2]), "+f"(c[3])
                 : "r"(a[0]), "r"(a[1]), "r"(a[2]), "r"(a[3]), "r"(b[0]), "r"(b[1]));
}
__device__ __forceinline__ int sw_idx(int row, int seg) {
    return row * 32 + ((seg ^ ((row >> 1) & 3)) << 3);
}
__device__ __forceinline__ void cp_plane(__half* dst, const __half* src,
                                         int ld, int kc, int tid)
{
    #pragma unroll
    for (int s = 0; s < 2; s++) {
        int idx = tid + s * 256;
        int row = idx >> 2, seg = idx & 3;
        uint32_t d = (uint32_t)__cvta_generic_to_shared(dst + sw_idx(row, seg));
        const __half* g = src + (size_t)row * ld + kc + seg * 8;
        asm volatile("cp.async.cg.shared.global [%0], [%1], 16;" :: "r"(d), "l"(g));
    }
}
__device__ __forceinline__ void load_a_frag(uint32_t a[4][4], const __half* plane,
                                            int m0, int seg_base, int lane)
{
    const int r = lane & 15, half_ = lane >> 4;
    #pragma unroll
    for (int t = 0; t < 4; t++)
        ldsm_x4(a[t], plane + sw_idx(m0 + t * 16 + r, seg_base + half_));
}
__device__ __forceinline__ void load_b_frag(uint32_t b[4][2], const __half* plane,
                                            int n0, int seg_base, int lane)
{
    const int r = lane & 15, half_ = lane >> 4;
    #pragma unroll
    for (int p = 0; p < 2; p++) {
        uint32_t t[4];
        ldsm_x4(t, plane + sw_idx(n0 + p * 16 + r, seg_base + half_));
        b[2*p][0]   = t[0];
        b[2*p+1][0] = t[1];
        b[2*p][1]   = t[2];
        b[2*p+1][1] = t[3];
    }
}
__device__ __forceinline__ void mma_all(float acc[4][4][4], const uint32_t a[4][4],
                                        const uint32_t b[4][2])
{
    #pragma unroll
    for (int mt = 0; mt < 4; mt++)
        #pragma unroll
        for (int nt = 0; nt < 4; nt++)
            mma16816(acc[mt][nt], a[mt], b[nt]);
}

__device__ __forceinline__ void acc_zero(float acc[4][4][4])
{
    #pragma unroll
    for (int mt = 0; mt < 4; mt++)
        #pragma unroll
        for (int nt = 0; nt < 4; nt++)
            #pragma unroll
            for (int q = 0; q < 4; q++) acc[mt][nt][q] = 0.f;
}

#define PLANE 4096

// ---------------------------------------------------------------------------
// 2-pass core: C = (Ah + Al) * B. 2 stages x 3 planes = 48KB smem.
// ---------------------------------------------------------------------------
__device__ __forceinline__ void mma_core(
                         const __half* __restrict__ Ah,
                         const __half* __restrict__ Al, int lda,
                         const __half* __restrict__ B, int ldb,
                         int K, __half* sm, float acc[4][4][4])
{
    const int tid = threadIdx.x, lane = tid & 31, wid = tid >> 5;
    const int m0 = (wid >> 2) * 64, n0 = (wid & 3) * 32;
    acc_zero(acc);

    cp_plane(sm + 0*PLANE, Ah, lda, 0, tid);
    cp_plane(sm + 1*PLANE, Al, lda, 0, tid);
    cp_plane(sm + 2*PLANE, B,  ldb, 0, tid);
    asm volatile("cp.async.commit_group;");

    const int NC = K >> 5;
    for (int c = 0; c < NC; c++) {
        __half* st = sm + (c & 1) * (3 * PLANE);
        if (c + 1 < NC) {
            __half* st2 = sm + ((c + 1) & 1) * (3 * PLANE);
            const int kc = (c + 1) * 32;
            cp_plane(st2 + 0*PLANE, Ah, lda, kc, tid);
            cp_plane(st2 + 1*PLANE, Al, lda, kc, tid);
            cp_plane(st2 + 2*PLANE, B,  ldb, kc, tid);
            asm volatile("cp.async.commit_group;");
            asm volatile("cp.async.wait_group 1;");
        } else {
            asm volatile("cp.async.wait_group 0;");
        }
        __syncthreads();
        #pragma unroll
        for (int ks = 0; ks < 2; ks++) {
            const int seg = ks * 2;
            uint32_t a[4][4];
            uint32_t b[4][2];
            load_b_frag(b, st + 2*PLANE, n0, seg, lane);  // B
            load_a_frag(a, st + 0*PLANE, m0, seg, lane);  // A hi
            mma_all(acc, a, b);
            load_a_frag(a, st + 1*PLANE, m0, seg, lane);  // A lo
            mma_all(acc, a, b);
        }
        __syncthreads();
    }
}

// ---------------------------------------------------------------------------
// 1-pass core: C = A * B (both single fp16). 2 stages x 2 planes = 32KB smem.
// ---------------------------------------------------------------------------
__device__ __forceinline__ void mma_core1(
                         const __half* __restrict__ A, int lda,
                         const __half* __restrict__ B, int ldb,
                         int K, __half* sm, float acc[4][4][4])
{
    const int tid = threadIdx.x, lane = tid & 31, wid = tid >> 5;
    const int m0 = (wid >> 2) * 64, n0 = (wid & 3) * 32;
    acc_zero(acc);

    cp_plane(sm + 0*PLANE, A, lda, 0, tid);
    cp_plane(sm + 1*PLANE, B, ldb, 0, tid);
    asm volatile("cp.async.commit_group;");

    const int NC = K >> 5;
    for (int c = 0; c < NC; c++) {
        __half* st = sm + (c & 1) * (2 * PLANE);
        if (c + 1 < NC) {
            __half* st2 = sm + ((c + 1) & 1) * (2 * PLANE);
            const int kc = (c + 1) * 32;
            cp_plane(st2 + 0*PLANE, A, lda, kc, tid);
            cp_plane(st2 + 1*PLANE, B, ldb, kc, tid);
            asm volatile("cp.async.commit_group;");
            asm volatile("cp.async.wait_group 1;");
        } else {
            asm volatile("cp.async.wait_group 0;");
        }
        __syncthreads();
        #pragma unroll
        for (int ks = 0; ks < 2; ks++) {
            const int seg = ks * 2;
            uint32_t a[4][4];
            uint32_t b[4][2];
            load_b_frag(b, st + 1*PLANE, n0, seg, lane);
            load_a_frag(a, st + 0*PLANE, m0, seg, lane);
            mma_all(acc, a, b);
        }
        __syncthreads();
    }
}

// LayerNorm over 128 cols in mma fragment layout. lnbuf >= 1280 floats.
__device__ __forceinline__ void ln_mma(float acc[4][4][4], float* lnbuf)
{
    float* lnS = lnbuf;
    float* lnQ = lnbuf + 512;
    float* mrs = lnbuf + 1024;
    const int tid = threadIdx.x, lane = tid & 31, wid = tid >> 5;
    const int wn = wid & 3, m0 = (wid >> 2) * 64;
    const int rr = lane >> 2, cg = lane & 3;

    #pragma unroll
    for (int mt = 0; mt < 4; mt++)
        #pragma unroll
        for (int half_ = 0; half_ < 2; half_++) {
            float s = 0.f, q = 0.f;
            #pragma unroll
            for (int nt = 0; nt < 4; nt++) {
                float v0 = acc[mt][nt][2*half_], v1 = acc[mt][nt][2*half_+1];
                s += v0 + v1; q += v0 * v0 + v1 * v1;
            }
            s += __shfl_xor_sync(0xffffffffu, s, 1);
            s += __shfl_xor_sync(0xffffffffu, s, 2);
            q += __shfl_xor_sync(0xffffffffu, q, 1);
            q += __shfl_xor_sync(0xffffffffu, q, 2);
            if (cg == 0) {
                int row = m0 + mt * 16 + half_ * 8 + rr;
                lnS[row * 4 + wn] = s;
                lnQ[row * 4 + wn] = q;
            }
        }
    __syncthreads();
    if (tid < 128) {
        float s = lnS[tid*4] + lnS[tid*4+1] + lnS[tid*4+2] + lnS[tid*4+3];
        float q = lnQ[tid*4] + lnQ[tid*4+1] + lnQ[tid*4+2] + lnQ[tid*4+3];
        float mean = s * (1.0f / 128.0f);
        float var  = q * (1.0f / 128.0f) - mean * mean;
        mrs[tid]       = mean;
        mrs[128 + tid] = rsqrtf(var + 1e-5f);
    }
    __syncthreads();
    #pragma unroll
    for (int mt = 0; mt < 4; mt++)
        #pragma unroll
        for (int half_ = 0; half_ < 2; half_++) {
            int row = m0 + mt * 16 + half_ * 8 + rr;
            float mu = mrs[row], rs = mrs[128 + row];
            #pragma unroll
            for (int nt = 0; nt < 4; nt++) {
                acc[mt][nt][2*half_]   = (acc[mt][nt][2*half_]   - mu) * rs;
                acc[mt][nt][2*half_+1] = (acc[mt][nt][2*half_+1] - mu) * rs;
            }
        }
}

__device__ __forceinline__ uint32_t pack_h2(float v0, float v1, uint32_t& lo)
{
    __half h0 = __float2half(v0), h1 = __float2half(v1);
    __half l0 = __float2half(v0 - __half2float(h0));
    __half l1 = __float2half(v1 - __half2float(h1));
    lo = (uint32_t)__half_as_ushort(l0) | ((uint32_t)__half_as_ushort(l1) << 16);
    return (uint32_t)__half_as_ushort(h0) | ((uint32_t)__half_as_ushort(h1) << 16);
}
__device__ __forceinline__ uint32_t pack_s2(float v0, float v1)
{
    __half h0 = __float2half(v0), h1 = __float2half(v1);
    return (uint32_t)__half_as_ushort(h0) | ((uint32_t)__half_as_ushort(h1) << 16);
}

__device__ __forceinline__ void store_hilo(const float acc[4][4][4],
                                           __half* oh, __half* ol, int ldc)
{
    const int lane = threadIdx.x & 31, wid = threadIdx.x >> 5;
    const int m0 = (wid >> 2) * 64, n0 = (wid & 3) * 32;
    const int rr = lane >> 2, cg = lane & 3;
    #pragma unroll
    for (int mt = 0; mt < 4; mt++)
        #pragma unroll
        for (int half_ = 0; half_ < 2; half_++) {
            int row = m0 + mt * 16 + half_ * 8 + rr;
            #pragma unroll
            for (int nt = 0; nt < 4; nt++) {
                int c = n0 + nt * 8 + 2 * cg;
                uint32_t lo;
                uint32_t hi = pack_h2(acc[mt][nt][2*half_], acc[mt][nt][2*half_+1], lo);
                *reinterpret_cast<uint32_t*>(oh + (size_t)row * ldc + c) = hi;
                *reinterpret_cast<uint32_t*>(ol + (size_t)row * ldc + c) = lo;
            }
        }
}
__device__ __forceinline__ void store_single(const float acc[4][4][4],
                                             __half* o, int ldc)
{
    const int lane = threadIdx.x & 31, wid = threadIdx.x >> 5;
    const int m0 = (wid >> 2) * 64, n0 = (wid & 3) * 32;
    const int rr = lane >> 2, cg = lane & 3;
    #pragma unroll
    for (int mt = 0; mt < 4; mt++)
        #pragma unroll
        for (int half_ = 0; half_ < 2; half_++) {
            int row = m0 + mt * 16 + half_ * 8 + rr;
            #pragma unroll
            for (int nt = 0; nt < 4; nt++) {
                int c = n0 + nt * 8 + 2 * cg;
                *reinterpret_cast<uint32_t*>(o + (size_t)row * ldc + c) =
                    pack_s2(acc[mt][nt][2*half_], acc[mt][nt][2*half_+1]);
            }
        }
}

// ======================= fused prep kernel =======================
__device__ __forceinline__ void transplit_tile(const float* src, __half* dh,
                                               int R, int C, int r0, int c0)
{
    __shared__ float t[32][33];
    const int tid = threadIdx.x;
    #pragma unroll
    for (int s = 0; s < 4; s++) {
        int idx = tid + s * 256;
        int r = idx >> 5, c = idx & 31;
        t[r][c] = src[(size_t)(r0 + r) * C + c0 + c];
    }
    __syncthreads();
    #pragma unroll
    for (int s = 0; s < 4; s++) {
        int idx = tid + s * 256;
        int co = idx >> 5, ro = idx & 31;
        dh[(size_t)(c0 + co) * R + r0 + ro] = __float2half(t[ro][co]);
    }
}

__global__ __launch_bounds__(256) void prep_all(
    const float* __restrict__ x,
    const float* __restrict__ Wq, const float* __restrict__ Wk, const float* __restrict__ Wv,
    const float* __restrict__ W1, const float* __restrict__ W2)
{
    const int bid = blockIdx.x;
    if (bid < 4096) {
        const size_t i4 = (size_t)bid * 256 + threadIdx.x;
        float4 v = *reinterpret_cast<const float4*>(x + i4 * 4);
        uint32_t l0, l1;
        uint32_t h0 = pack_h2(v.x, v.y, l0);
        uint32_t h1 = pack_h2(v.z, v.w, l1);
        *reinterpret_cast<uint2*>(g_xh + i4 * 4) = make_uint2(h0, h1);
        *reinterpret_cast<uint2*>(g_xl + i4 * 4) = make_uint2(l0, l1);
    } else if (bid < 4288) {
        const int j = bid - 4096;
        const int midx = j >> 4, rem = j & 15;
        const int which = midx >> 2, h = midx & 3;
        const float* src = (which == 0 ? Wq : (which == 1 ? Wk : Wv)) + (size_t)h * 128 * 128;
        transplit_tile(src, g_WT + (size_t)midx * 16384,
                       128, 128, (rem >> 2) * 32, (rem & 3) * 32);
    } else if (bid < 4352) {
        const int j = bid - 4288;
        transplit_tile(W1, g_W1T, 512, 128, (j >> 2) * 32, (j & 3) * 32);
    } else {
        const int j = bid - 4352;
        transplit_tile(W2, g_W2T, 128, 128, (j >> 2) * 32, (j & 3) * 32);
    }
}

// ======================= main kernels =======================
extern __shared__ __half dynsm[];

// QKV: grid (256, 4, 3). Q -> hi/lo, K/V -> single.
__global__ __launch_bounds__(256, 2) void qkv_mma(
    const float* __restrict__ bq, const float* __restrict__ bk, const float* __restrict__ bv)
{
    const int rowBase = blockIdx.x * 128;
    const int h = blockIdx.y, which = blockIdx.z;
    const int midx = which * 4 + h;
    const float* bias = (which == 0 ? bq : (which == 1 ? bk : bv)) + (size_t)h * 128;

    float acc[4][4][4];
    mma_core(g_xh + (size_t)rowBase * E, g_xl + (size_t)rowBase * E, E,
             g_WT + (size_t)midx * 16384, E, E, dynsm, acc);

    const int lane = threadIdx.x & 31, wid = threadIdx.x >> 5;
    const int n0 = (wid & 3) * 32, cg = lane & 3;
    #pragma unroll
    for (int nt = 0; nt < 4; nt++) {
        float2 bv2 = *reinterpret_cast<const float2*>(bias + n0 + nt * 8 + 2 * cg);
        #pragma unroll
        for (int mt = 0; mt < 4; mt++) {
            acc[mt][nt][0] += bv2.x; acc[mt][nt][1] += bv2.y;
            acc[mt][nt][2] += bv2.x; acc[mt][nt][3] += bv2.y;
        }
    }
    ln_mma(acc, (float*)dynsm);

    const int b = rowBase >> 9, nBase = rowBase & 511;
    const int bh = b * H + h;
    const size_t off = ((size_t)bh * Nseq + nBase) * 128;
    if (which == 0)      store_hilo(acc, g_Qh + off, g_Ql + off, 128);
    else if (which == 1) store_single(acc, g_K + off, 128);
    else                 store_single(acc, g_V + off, 128);
}

// V transpose (single plane): grid (256, 4, 16)
__global__ __launch_bounds__(256) void vtrans_kernel()
{
    __shared__ __half t[32][33];
    const int bh = blockIdx.x, e0 = blockIdx.y * 32, n0 = blockIdx.z * 32;
    const int tid = threadIdx.x;
    const size_t inBase = ((size_t)bh * Nseq + n0) * E + e0;
    #pragma unroll
    for (int s = 0; s < 4; s++) {
        int idx = tid + s * 256;
        int r = idx >> 5, c = idx & 31;
        t[r][c] = g_V[inBase + (size_t)r * E + c];
    }
    __syncthreads();
    const size_t outBase = ((size_t)bh * E + e0) * Nseq + n0;
    #pragma unroll
    for (int s = 0; s < 4; s++) {
        int idx = tid + s * 256;
        int r = idx >> 5, c = idx & 31;
        g_Vt[outBase + (size_t)r * Nseq + c] = t[c][r];
    }
}

// scores = Q K^T -> fp32 S. grid (4, 4, 256)
__global__ __launch_bounds__(256, 2) void scores_mma()
{
    const int bh = blockIdx.z;
    const size_t rowBase = blockIdx.x * 128, colBase = blockIdx.y * 128;
    float acc[4][4][4];
    mma_core(g_Qh + ((size_t)bh * Nseq + rowBase) * D,
             g_Ql + ((size_t)bh * Nseq + rowBase) * D, D,
             g_K + ((size_t)bh * Nseq + colBase) * D, D, D, dynsm, acc);

    float* Cout = g_S + (size_t)bh * Nseq * Nseq + rowBase * Nseq + colBase;
    const int lane = threadIdx.x & 31, wid = threadIdx.x >> 5;
    const int m0 = (wid >> 2) * 64, n0 = (wid & 3) * 32;
    const int rr = lane >> 2, cg = lane & 3;
    #pragma unroll
    for (int mt = 0; mt < 4; mt++)
        #pragma unroll
        for (int half_ = 0; half_ < 2; half_++) {
            int r = m0 + mt * 16 + half_ * 8 + rr;
            #pragma unroll
            for (int nt = 0; nt < 4; nt++) {
                int c = n0 + nt * 8 + 2 * cg;
                *reinterpret_cast<float2*>(Cout + (size_t)r * Nseq + c) =
                    make_float2(acc[mt][nt][2*half_], acc[mt][nt][2*half_+1]);
            }
        }
}

// batch-axis softmax -> P single plane. grid (4096)
__global__ __launch_bounds__(256) void softmax_kernel()
{
    const size_t idx = (size_t)blockIdx.x * 256 + threadIdx.x;
    const size_t stride = (size_t)H * Nseq * Nseq;
    float v[64];
    float mx = -1e30f;
    #pragma unroll
    for (int b = 0; b < 64; b++) {
        float t = g_S[(size_t)b * stride + idx] * (1.0f / 11.0f);
        v[b] = t;
        mx = fmaxf(mx, t);
    }
    float s = 0.f;
    #pragma unroll
    for (int b = 0; b < 64; b++) { float e = __expf(v[b] - mx); v[b] = e; s += e; }
    const float inv = 1.0f / s;
    #pragma unroll
    for (int b = 0; b < 64; b++)
        g_P[(size_t)b * stride + idx] = __float2half(v[b] * inv);
}

// A = P V (single-pass) -> hi/lo concat layout. grid (4, 1, 256)
__global__ __launch_bounds__(256, 2) void av_mma()
{
    const int bh = blockIdx.z, b = bh >> 2, h = bh & 3;
    const size_t rowBase = blockIdx.x * 128;
    float acc[4][4][4];
    mma_core1(g_P + ((size_t)bh * Nseq + rowBase) * Nseq, Nseq,
              g_Vt + (size_t)bh * E * Nseq, Nseq, Nseq, dynsm, acc);
    const size_t off = ((size_t)b * Nseq + rowBase) * (H * E) + (size_t)h * E;
    store_hilo(acc, g_Ah + off, g_Al + off, H * E);
}

// h1 = relu(A @ W1 + b1) -> hi/lo. grid (256)
__global__ __launch_bounds__(256, 2) void mlp1_mma(const float* __restrict__ b1)
{
    const int rowBase = blockIdx.x * 128;
    float acc[4][4][4];
    mma_core(g_Ah + (size_t)rowBase * (H * E), g_Al + (size_t)rowBase * (H * E), H * E,
             g_W1T, H * E, H * E, dynsm, acc);

    const int lane = threadIdx.x & 31, wid = threadIdx.x >> 5;
    const int n0 = (wid & 3) * 32, cg = lane & 3;
    #pragma unroll
    for (int nt = 0; nt < 4; nt++) {
        float2 bv2 = *reinterpret_cast<const float2*>(b1 + n0 + nt * 8 + 2 * cg);
        #pragma unroll
        for (int mt = 0; mt < 4; mt++) {
            acc[mt][nt][0] = fmaxf(acc[mt][nt][0] + bv2.x, 0.f);
            acc[mt][nt][1] = fmaxf(acc[mt][nt][1] + bv2.y, 0.f);
            acc[mt][nt][2] = fmaxf(acc[mt][nt][2] + bv2.x, 0.f);
            acc[mt][nt][3] = fmaxf(acc[mt][nt][3] + bv2.y, 0.f);
        }
    }
    store_hilo(acc, g_H1h + (size_t)rowBase * E, g_H1l + (size_t)rowBase * E, E);
}

// out = LN(x + relu(h1 @ W2 + b2)) * gamma + beta. grid (256)
__global__ __launch_bounds__(256, 2) void mlp2_mma(
    const float* __restrict__ x, const float* __restrict__ b2,
    const float* __restrict__ gamma, const float* __restrict__ beta,
    float* __restrict__ out)
{
    const int rowBase = blockIdx.x * 128;
    float acc[4][4][4];
    mma_core(g_H1h + (size_t)rowBase * E, g_H1l + (size_t)rowBase * E, E,
             g_W2T, E, E, dynsm, acc);

    const int lane = threadIdx.x & 31, wid = threadIdx.x >> 5;
    const int m0 = (wid >> 2) * 64, n0 = (wid & 3) * 32;
    const int rr = lane >> 2, cg = lane & 3;
    #pragma unroll
    for (int nt = 0; nt < 4; nt++) {
        const int c = n0 + nt * 8 + 2 * cg;
        float2 bv2 = *reinterpret_cast<const float2*>(b2 + c);
        #pragma unroll
        for (int mt = 0; mt < 4; mt++)
            #pragma unroll
            for (int half_ = 0; half_ < 2; half_++) {
                int row = rowBase + m0 + mt * 16 + half_ * 8 + rr;
                float2 xv = *reinterpret_cast<const float2*>(x + (size_t)row * E + c);
                acc[mt][nt][2*half_]   = fmaxf(acc[mt][nt][2*half_]   + bv2.x, 0.f) + xv.x;
                acc[mt][nt][2*half_+1] = fmaxf(acc[mt][nt][2*half_+1] + bv2.y, 0.f) + xv.y;
            }
    }

    ln_mma(acc, (float*)dynsm);

    #pragma unroll
    for (int nt = 0; nt < 4; nt++) {
        const int c = n0 + nt * 8 + 2 * cg;
        float2 gv = *reinterpret_cast<const float2*>(gamma + c);
        float2 ev = *reinterpret_cast<const float2*>(beta + c);
        #pragma unroll
        for (int mt = 0; mt < 4; mt++)
            #pragma unroll
            for (int half_ = 0; half_ < 2; half_++) {
                int row = rowBase + m0 + mt * 16 + half_ * 8 + rr;
                float o0 = acc[mt][nt][2*half_]   * gv.x + ev.x;
                float o1 = acc[mt][nt][2*half_+1] * gv.y + ev.y;
                *reinterpret_cast<float2*>(out + (size_t)row * E + c) = make_float2(o0, o1);
            }
    }
}

// ---------------------------------------------------------------------------
extern "C" void kernel_launch(void* const* d_in, const int* in_sizes, int n_in,
                              void* d_out, int out_size)
{
    const float* x     = (const float*)d_in[0];
    const float* Wq    = (const float*)d_in[1];
    const float* bq    = (const float*)d_in[2];
    const float* Wk    = (const float*)d_in[3];
    const float* bk    = (const float*)d_in[4];
    const float* Wv    = (const float*)d_in[5];
    const float* bv    = (const float*)d_in[6];
    const float* W1    = (const float*)d_in[7];
    const float* b1    = (const float*)d_in[8];
    const float* W2    = (const float*)d_in[9];
    const float* b2    = (const float*)d_in[10];
    const float* gamma = (const float*)d_in[11];
    const float* beta  = (const float*)d_in[12];
    float* out = (float*)d_out;

    const int SMEM  = 2 * 3 * 4096 * (int)sizeof(__half);   // 48KB (2-pass)
    const int SMEM1 = 2 * 2 * 4096 * (int)sizeof(__half);   // 32KB (1-pass)
    cudaFuncSetAttribute(qkv_mma,    cudaFuncAttributeMaxDynamicSharedMemorySize, SMEM);
    cudaFuncSetAttribute(scores_mma, cudaFuncAttributeMaxDynamicSharedMemorySize, SMEM);
    cudaFuncSetAttribute(av_mma,     cudaFuncAttributeMaxDynamicSharedMemorySize, SMEM1);
    cudaFuncSetAttribute(mlp1_mma,   cudaFuncAttributeMaxDynamicSharedMemorySize, SMEM);
    cudaFuncSetAttribute(mlp2_mma,   cudaFuncAttributeMaxDynamicSharedMemorySize, SMEM);

    dim3 blk(256);
    prep_all      <<<dim3(4368), blk>>>(x, Wq, Wk, Wv, W1, W2);
    qkv_mma       <<<dim3(256, 4, 3), blk, SMEM>>>(bq, bk, bv);
    vtrans_kernel <<<dim3(256, 4, 16), blk>>>();
    scores_mma    <<<dim3(4, 4, 256), blk, SMEM>>>();
    softmax_kernel<<<dim3(4096), blk>>>();
    av_mma        <<<dim3(4, 1, 256), blk, SMEM1>>>();
    mlp1_mma      <<<dim3(256), blk, SMEM>>>(b1);
    mlp2_mma      <<<dim3(256), blk, SMEM>>>(x, b2, gamma, beta, out);
}

// round 14
// speedup vs baseline: 1.9164x; 1.1743x over previous
#include <cuda_runtime.h>
#include <cuda_fp16.h>
#include <cstdint>

constexpr int Bdim = 64;
constexpr int Nseq = 512;
constexpr int E    = 128;
constexpr int D    = 128;
constexpr int H    = 4;

// ---------------- scratch (allocation-free) ----------------
__device__ __half g_xh [(size_t)Bdim*Nseq*E];
__device__ __half g_xl [(size_t)Bdim*Nseq*E];
__device__ __half g_WT [12 * 128 * 128];          // [which*4+h][d][e] transposed
__device__ __half g_W1T[128 * 512];               // [e_out][k]
__device__ __half g_W2T[128 * 128];
__device__ __half g_Q [(size_t)Bdim*H*Nseq*D];    // single
__device__ __half g_K [(size_t)Bdim*H*Nseq*D];    // single
__device__ __half g_V [(size_t)Bdim*H*Nseq*E];    // [bh][n][e]
__device__ __half g_Vt[(size_t)Bdim*H*E*Nseq];    // [bh][e][n]
__device__ float  g_S [(size_t)Bdim*H*Nseq*Nseq]; // fp32 scores
__device__ __half g_P [(size_t)Bdim*H*Nseq*Nseq]; // single post-softmax
__device__ __half g_A [(size_t)Bdim*Nseq*H*E];    // [B,N,512] concat, single
__device__ __half g_H1[(size_t)Bdim*Nseq*E];      // single

// ======================= mma.sync machinery (fp16) =======================
__device__ __forceinline__ void ldsm_x4(uint32_t r[4], const void* p) {
    uint32_t addr = (uint32_t)__cvta_generic_to_shared(p);
    asm volatile("ldmatrix.sync.aligned.m8n8.x4.shared.b16 {%0,%1,%2,%3}, [%4];"
                 : "=r"(r[0]), "=r"(r[1]), "=r"(r[2]), "=r"(r[3]) : "r"(addr));
}
__device__ __forceinline__ void mma16816(float c[4], const uint32_t a[4], const uint32_t b[2]) {
    asm volatile("mma.sync.aligned.m16n8k16.row.col.f32.f16.f16.f32 "
                 "{%0,%1,%2,%3}, {%4,%5,%6,%7}, {%8,%9}, {%0,%1,%2,%3};"
                 : "+f"(c[0]), "+f"(c[1]), "+f"(c[2]), "+f"(c[3])
                 : "r"(a[0]), "r"(a[1]), "r"(a[2]), "r"(a[3]), "r"(b[0]), "r"(b[1]));
}
__device__ __forceinline__ int sw_idx(int row, int seg) {
    return row * 32 + ((seg ^ ((row >> 1) & 3)) << 3);
}
__device__ __forceinline__ void cp_plane(__half* dst, const __half* src,
                                         int ld, int kc, int tid)
{
    #pragma unroll
    for (int s = 0; s < 2; s++) {
        int idx = tid + s * 256;
        int row = idx >> 2, seg = idx & 3;
        uint32_t d = (uint32_t)__cvta_generic_to_shared(dst + sw_idx(row, seg));
        const __half* g = src + (size_t)row * ld + kc + seg * 8;
        asm volatile("cp.async.cg.shared.global [%0], [%1], 16;" :: "r"(d), "l"(g));
    }
}
__device__ __forceinline__ void load_a_frag(uint32_t a[4][4], const __half* plane,
                                            int m0, int seg_base, int lane)
{
    const int r = lane & 15, half_ = lane >> 4;
    #pragma unroll
    for (int t = 0; t < 4; t++)
        ldsm_x4(a[t], plane + sw_idx(m0 + t * 16 + r, seg_base + half_));
}
__device__ __forceinline__ void load_b_frag(uint32_t b[4][2], const __half* plane,
                                            int n0, int seg_base, int lane)
{
    const int r = lane & 15, half_ = lane >> 4;
    #pragma unroll
    for (int p = 0; p < 2; p++) {
        uint32_t t[4];
        ldsm_x4(t, plane + sw_idx(n0 + p * 16 + r, seg_base + half_));
        b[2*p][0]   = t[0];
        b[2*p+1][0] = t[1];
        b[2*p][1]   = t[2];
        b[2*p+1][1] = t[3];
    }
}
__device__ __forceinline__ void mma_all(float acc[4][4][4], const uint32_t a[4][4],
                                        const uint32_t b[4][2])
{
    #pragma unroll
    for (int mt = 0; mt < 4; mt++)
        #pragma unroll
        for (int nt = 0; nt < 4; nt++)
            mma16816(acc[mt][nt], a[mt], b[nt]);
}
__device__ __forceinline__ void acc_zero(float acc[4][4][4])
{
    #pragma unroll
    for (int mt = 0; mt < 4; mt++)
        #pragma unroll
        for (int nt = 0; nt < 4; nt++)
            #pragma unroll
            for (int q = 0; q < 4; q++) acc[mt][nt][q] = 0.f;
}

#define PLANE 4096

// ---------------------------------------------------------------------------
// 2-pass core: C = (Ah + Al) * B. 2 stages x 3 planes = 48KB smem.
// ---------------------------------------------------------------------------
__device__ __forceinline__ void mma_core(
                         const __half* __restrict__ Ah,
                         const __half* __restrict__ Al, int lda,
                         const __half* __restrict__ B, int ldb,
                         int K, __half* sm, float acc[4][4][4])
{
    const int tid = threadIdx.x, lane = tid & 31, wid = tid >> 5;
    const int m0 = (wid >> 2) * 64, n0 = (wid & 3) * 32;
    acc_zero(acc);

    cp_plane(sm + 0*PLANE, Ah, lda, 0, tid);
    cp_plane(sm + 1*PLANE, Al, lda, 0, tid);
    cp_plane(sm + 2*PLANE, B,  ldb, 0, tid);
    asm volatile("cp.async.commit_group;");

    const int NC = K >> 5;
    for (int c = 0; c < NC; c++) {
        __half* st = sm + (c & 1) * (3 * PLANE);
        if (c + 1 < NC) {
            __half* st2 = sm + ((c + 1) & 1) * (3 * PLANE);
            const int kc = (c + 1) * 32;
            cp_plane(st2 + 0*PLANE, Ah, lda, kc, tid);
            cp_plane(st2 + 1*PLANE, Al, lda, kc, tid);
            cp_plane(st2 + 2*PLANE, B,  ldb, kc, tid);
            asm volatile("cp.async.commit_group;");
            asm volatile("cp.async.wait_group 1;");
        } else {
            asm volatile("cp.async.wait_group 0;");
        }
        __syncthreads();
        #pragma unroll
        for (int ks = 0; ks < 2; ks++) {
            const int seg = ks * 2;
            uint32_t a[4][4];
            uint32_t b[4][2];
            load_b_frag(b, st + 2*PLANE, n0, seg, lane);
            load_a_frag(a, st + 0*PLANE, m0, seg, lane);
            mma_all(acc, a, b);
            load_a_frag(a, st + 1*PLANE, m0, seg, lane);
            mma_all(acc, a, b);
        }
        __syncthreads();
    }
}

// ---------------------------------------------------------------------------
// 1-pass core: C = A * B (both single fp16). 2 stages x 2 planes = 32KB smem.
// ---------------------------------------------------------------------------
__device__ __forceinline__ void mma_core1(
                         const __half* __restrict__ A, int lda,
                         const __half* __restrict__ B, int ldb,
                         int K, __half* sm, float acc[4][4][4])
{
    const int tid = threadIdx.x, lane = tid & 31, wid = tid >> 5;
    const int m0 = (wid >> 2) * 64, n0 = (wid & 3) * 32;
    acc_zero(acc);

    cp_plane(sm + 0*PLANE, A, lda, 0, tid);
    cp_plane(sm + 1*PLANE, B, ldb, 0, tid);
    asm volatile("cp.async.commit_group;");

    const int NC = K >> 5;
    for (int c = 0; c < NC; c++) {
        __half* st = sm + (c & 1) * (2 * PLANE);
        if (c + 1 < NC) {
            __half* st2 = sm + ((c + 1) & 1) * (2 * PLANE);
            const int kc = (c + 1) * 32;
            cp_plane(st2 + 0*PLANE, A, lda, kc, tid);
            cp_plane(st2 + 1*PLANE, B, ldb, kc, tid);
            asm volatile("cp.async.commit_group;");
            asm volatile("cp.async.wait_group 1;");
        } else {
            asm volatile("cp.async.wait_group 0;");
        }
        __syncthreads();
        #pragma unroll
        for (int ks = 0; ks < 2; ks++) {
            const int seg = ks * 2;
            uint32_t a[4][4];
            uint32_t b[4][2];
            load_b_frag(b, st + 1*PLANE, n0, seg, lane);
            load_a_frag(a, st + 0*PLANE, m0, seg, lane);
            mma_all(acc, a, b);
        }
        __syncthreads();
    }
}

// LayerNorm over 128 cols in mma fragment layout. lnbuf >= 1280 floats.
__device__ __forceinline__ void ln_mma(float acc[4][4][4], float* lnbuf)
{
    float* lnS = lnbuf;
    float* lnQ = lnbuf + 512;
    float* mrs = lnbuf + 1024;
    const int tid = threadIdx.x, lane = tid & 31, wid = tid >> 5;
    const int wn = wid & 3, m0 = (wid >> 2) * 64;
    const int rr = lane >> 2, cg = lane & 3;

    #pragma unroll
    for (int mt = 0; mt < 4; mt++)
        #pragma unroll
        for (int half_ = 0; half_ < 2; half_++) {
            float s = 0.f, q = 0.f;
            #pragma unroll
            for (int nt = 0; nt < 4; nt++) {
                float v0 = acc[mt][nt][2*half_], v1 = acc[mt][nt][2*half_+1];
                s += v0 + v1; q += v0 * v0 + v1 * v1;
            }
            s += __shfl_xor_sync(0xffffffffu, s, 1);
            s += __shfl_xor_sync(0xffffffffu, s, 2);
            q += __shfl_xor_sync(0xffffffffu, q, 1);
            q += __shfl_xor_sync(0xffffffffu, q, 2);
            if (cg == 0) {
                int row = m0 + mt * 16 + half_ * 8 + rr;
                lnS[row * 4 + wn] = s;
                lnQ[row * 4 + wn] = q;
            }
        }
    __syncthreads();
    if (tid < 128) {
        float s = lnS[tid*4] + lnS[tid*4+1] + lnS[tid*4+2] + lnS[tid*4+3];
        float q = lnQ[tid*4] + lnQ[tid*4+1] + lnQ[tid*4+2] + lnQ[tid*4+3];
        float mean = s * (1.0f / 128.0f);
        float var  = q * (1.0f / 128.0f) - mean * mean;
        mrs[tid]       = mean;
        mrs[128 + tid] = rsqrtf(var + 1e-5f);
    }
    __syncthreads();
    #pragma unroll
    for (int mt = 0; mt < 4; mt++)
        #pragma unroll
        for (int half_ = 0; half_ < 2; half_++) {
            int row = m0 + mt * 16 + half_ * 8 + rr;
            float mu = mrs[row], rs = mrs[128 + row];
            #pragma unroll
            for (int nt = 0; nt < 4; nt++) {
                acc[mt][nt][2*half_]   = (acc[mt][nt][2*half_]   - mu) * rs;
                acc[mt][nt][2*half_+1] = (acc[mt][nt][2*half_+1] - mu) * rs;
            }
        }
}

__device__ __forceinline__ uint32_t pack_h2(float v0, float v1, uint32_t& lo)
{
    __half h0 = __float2half(v0), h1 = __float2half(v1);
    __half l0 = __float2half(v0 - __half2float(h0));
    __half l1 = __float2half(v1 - __half2float(h1));
    lo = (uint32_t)__half_as_ushort(l0) | ((uint32_t)__half_as_ushort(l1) << 16);
    return (uint32_t)__half_as_ushort(h0) | ((uint32_t)__half_as_ushort(h1) << 16);
}
__device__ __forceinline__ uint32_t pack_s2(float v0, float v1)
{
    __half h0 = __float2half(v0), h1 = __float2half(v1);
    return (uint32_t)__half_as_ushort(h0) | ((uint32_t)__half_as_ushort(h1) << 16);
}

__device__ __forceinline__ void store_single(const float acc[4][4][4],
                                             __half* o, int ldc)
{
    const int lane = threadIdx.x & 31, wid = threadIdx.x >> 5;
    const int m0 = (wid >> 2) * 64, n0 = (wid & 3) * 32;
    const int rr = lane >> 2, cg = lane & 3;
    #pragma unroll
    for (int mt = 0; mt < 4; mt++)
        #pragma unroll
        for (int half_ = 0; half_ < 2; half_++) {
            int row = m0 + mt * 16 + half_ * 8 + rr;
            #pragma unroll
            for (int nt = 0; nt < 4; nt++) {
                int c = n0 + nt * 8 + 2 * cg;
                *reinterpret_cast<uint32_t*>(o + (size_t)row * ldc + c) =
                    pack_s2(acc[mt][nt][2*half_], acc[mt][nt][2*half_+1]);
            }
        }
}

// ======================= fused prep kernel =======================
__device__ __forceinline__ void transplit_tile(const float* src, __half* dh,
                                               int R, int C, int r0, int c0)
{
    __shared__ float t[32][33];
    const int tid = threadIdx.x;
    #pragma unroll
    for (int s = 0; s < 4; s++) {
        int idx = tid + s * 256;
        int r = idx >> 5, c = idx & 31;
        t[r][c] = src[(size_t)(r0 + r) * C + c0 + c];
    }
    __syncthreads();
    #pragma unroll
    for (int s = 0; s < 4; s++) {
        int idx = tid + s * 256;
        int co = idx >> 5, ro = idx & 31;
        dh[(size_t)(c0 + co) * R + r0 + ro] = __float2half(t[ro][co]);
    }
}

__global__ __launch_bounds__(256) void prep_all(
    const float* __restrict__ x,
    const float* __restrict__ Wq, const float* __restrict__ Wk, const float* __restrict__ Wv,
    const float* __restrict__ W1, const float* __restrict__ W2)
{
    const int bid = blockIdx.x;
    if (bid < 4096) {
        const size_t i4 = (size_t)bid * 256 + threadIdx.x;
        float4 v = *reinterpret_cast<const float4*>(x + i4 * 4);
        uint32_t l0, l1;
        uint32_t h0 = pack_h2(v.x, v.y, l0);
        uint32_t h1 = pack_h2(v.z, v.w, l1);
        *reinterpret_cast<uint2*>(g_xh + i4 * 4) = make_uint2(h0, h1);
        *reinterpret_cast<uint2*>(g_xl + i4 * 4) = make_uint2(l0, l1);
    } else if (bid < 4288) {
        const int j = bid - 4096;
        const int midx = j >> 4, rem = j & 15;
        const int which = midx >> 2, h = midx & 3;
        const float* src = (which == 0 ? Wq : (which == 1 ? Wk : Wv)) + (size_t)h * 128 * 128;
        transplit_tile(src, g_WT + (size_t)midx * 16384,
                       128, 128, (rem >> 2) * 32, (rem & 3) * 32);
    } else if (bid < 4352) {
        const int j = bid - 4288;
        transplit_tile(W1, g_W1T, 512, 128, (j >> 2) * 32, (j & 3) * 32);
    } else {
        const int j = bid - 4352;
        transplit_tile(W2, g_W2T, 128, 128, (j >> 2) * 32, (j & 3) * 32);
    }
}

// ======================= main kernels =======================
extern __shared__ __half dynsm[];

// QKV: grid (256, 4, 3). x hi/lo (2-pass); Q/K/V all stored single.
__global__ __launch_bounds__(256, 2) void qkv_mma(
    const float* __restrict__ bq, const float* __restrict__ bk, const float* __restrict__ bv)
{
    const int rowBase = blockIdx.x * 128;
    const int h = blockIdx.y, which = blockIdx.z;
    const int midx = which * 4 + h;
    const float* bias = (which == 0 ? bq : (which == 1 ? bk : bv)) + (size_t)h * 128;

    float acc[4][4][4];
    mma_core(g_xh + (size_t)rowBase * E, g_xl + (size_t)rowBase * E, E,
             g_WT + (size_t)midx * 16384, E, E, dynsm, acc);

    const int lane = threadIdx.x & 31, wid = threadIdx.x >> 5;
    const int n0 = (wid & 3) * 32, cg = lane & 3;
    #pragma unroll
    for (int nt = 0; nt < 4; nt++) {
        float2 bv2 = *reinterpret_cast<const float2*>(bias + n0 + nt * 8 + 2 * cg);
        #pragma unroll
        for (int mt = 0; mt < 4; mt++) {
            acc[mt][nt][0] += bv2.x; acc[mt][nt][1] += bv2.y;
            acc[mt][nt][2] += bv2.x; acc[mt][nt][3] += bv2.y;
        }
    }
    ln_mma(acc, (float*)dynsm);

    const int b = rowBase >> 9, nBase = rowBase & 511;
    const int bh = b * H + h;
    const size_t off = ((size_t)bh * Nseq + nBase) * 128;
    __half* o = (which == 0 ? g_Q : (which == 1 ? g_K : g_V)) + off;
    store_single(acc, o, 128);
}

// V transpose: grid (256, 4, 16)
__global__ __launch_bounds__(256) void vtrans_kernel()
{
    __shared__ __half t[32][33];
    const int bh = blockIdx.x, e0 = blockIdx.y * 32, n0 = blockIdx.z * 32;
    const int tid = threadIdx.x;
    const size_t inBase = ((size_t)bh * Nseq + n0) * E + e0;
    #pragma unroll
    for (int s = 0; s < 4; s++) {
        int idx = tid + s * 256;
        int r = idx >> 5, c = idx & 31;
        t[r][c] = g_V[inBase + (size_t)r * E + c];
    }
    __syncthreads();
    const size_t outBase = ((size_t)bh * E + e0) * Nseq + n0;
    #pragma unroll
    for (int s = 0; s < 4; s++) {
        int idx = tid + s * 256;
        int r = idx >> 5, c = idx & 31;
        g_Vt[outBase + (size_t)r * Nseq + c] = t[c][r];
    }
}

// scores = Q K^T (1-pass) -> fp32 S. grid (4, 4, 256)
__global__ __launch_bounds__(256, 2) void scores_mma()
{
    const int bh = blockIdx.z;
    const size_t rowBase = blockIdx.x * 128, colBase = blockIdx.y * 128;
    float acc[4][4][4];
    mma_core1(g_Q + ((size_t)bh * Nseq + rowBase) * D, D,
              g_K + ((size_t)bh * Nseq + colBase) * D, D, D, dynsm, acc);

    float* Cout = g_S + (size_t)bh * Nseq * Nseq + rowBase * Nseq + colBase;
    const int lane = threadIdx.x & 31, wid = threadIdx.x >> 5;
    const int m0 = (wid >> 2) * 64, n0 = (wid & 3) * 32;
    const int rr = lane >> 2, cg = lane & 3;
    #pragma unroll
    for (int mt = 0; mt < 4; mt++)
        #pragma unroll
        for (int half_ = 0; half_ < 2; half_++) {
            int r = m0 + mt * 16 + half_ * 8 + rr;
            #pragma unroll
            for (int nt = 0; nt < 4; nt++) {
                int c = n0 + nt * 8 + 2 * cg;
                *reinterpret_cast<float2*>(Cout + (size_t)r * Nseq + c) =
                    make_float2(acc[mt][nt][2*half_], acc[mt][nt][2*half_+1]);
            }
        }
}

// batch-axis softmax -> P single plane. grid (4096)
__global__ __launch_bounds__(256) void softmax_kernel()
{
    const size_t idx = (size_t)blockIdx.x * 256 + threadIdx.x;
    const size_t stride = (size_t)H * Nseq * Nseq;
    float v[64];
    float mx = -1e30f;
    #pragma unroll
    for (int b = 0; b < 64; b++) {
        float t = g_S[(size_t)b * stride + idx] * (1.0f / 11.0f);
        v[b] = t;
        mx = fmaxf(mx, t);
    }
    float s = 0.f;
    #pragma unroll
    for (int b = 0; b < 64; b++) { float e = __expf(v[b] - mx); v[b] = e; s += e; }
    const float inv = 1.0f / s;
    #pragma unroll
    for (int b = 0; b < 64; b++)
        g_P[(size_t)b * stride + idx] = __float2half(v[b] * inv);
}

// A = P V (1-pass) -> single concat layout. grid (4, 1, 256)
__global__ __launch_bounds__(256, 2) void av_mma()
{
    const int bh = blockIdx.z, b = bh >> 2, h = bh & 3;
    const size_t rowBase = blockIdx.x * 128;
    float acc[4][4][4];
    mma_core1(g_P + ((size_t)bh * Nseq + rowBase) * Nseq, Nseq,
              g_Vt + (size_t)bh * E * Nseq, Nseq, Nseq, dynsm, acc);
    const size_t off = ((size_t)b * Nseq + rowBase) * (H * E) + (size_t)h * E;
    store_single(acc, g_A + off, H * E);
}

// h1 = relu(A @ W1 + b1) (1-pass) -> single. grid (256)
__global__ __launch_bounds__(256, 2) void mlp1_mma(const float* __restrict__ b1)
{
    const int rowBase = blockIdx.x * 128;
    float acc[4][4][4];
    mma_core1(g_A + (size_t)rowBase * (H * E), H * E,
              g_W1T, H * E, H * E, dynsm, acc);

    const int lane = threadIdx.x & 31, wid = threadIdx.x >> 5;
    const int n0 = (wid & 3) * 32, cg = lane & 3;
    #pragma unroll
    for (int nt = 0; nt < 4; nt++) {
        float2 bv2 = *reinterpret_cast<const float2*>(b1 + n0 + nt * 8 + 2 * cg);
        #pragma unroll
        for (int mt = 0; mt < 4; mt++) {
            acc[mt][nt][0] = fmaxf(acc[mt][nt][0] + bv2.x, 0.f);
            acc[mt][nt][1] = fmaxf(acc[mt][nt][1] + bv2.y, 0.f);
            acc[mt][nt][2] = fmaxf(acc[mt][nt][2] + bv2.x, 0.f);
            acc[mt][nt][3] = fmaxf(acc[mt][nt][3] + bv2.y, 0.f);
        }
    }
    store_single(acc, g_H1 + (size_t)rowBase * E, E);
}

// out = LN(x + relu(h1 @ W2 + b2)) * gamma + beta (1-pass). grid (256)
__global__ __launch_bounds__(256, 2) void mlp2_mma(
    const float* __restrict__ x, const float* __restrict__ b2,
    const float* __restrict__ gamma, const float* __restrict__ beta,
    float* __restrict__ out)
{
    const int rowBase = blockIdx.x * 128;
    float acc[4][4][4];
    mma_core1(g_H1 + (size_t)rowBase * E, E, g_W2T, E, E, dynsm, acc);

    const int lane = threadIdx.x & 31, wid = threadIdx.x >> 5;
    const int m0 = (wid >> 2) * 64, n0 = (wid & 3) * 32;
    const int rr = lane >> 2, cg = lane & 3;
    #pragma unroll
    for (int nt = 0; nt < 4; nt++) {
        const int c = n0 + nt * 8 + 2 * cg;
        float2 bv2 = *reinterpret_cast<const float2*>(b2 + c);
        #pragma unroll
        for (int mt = 0; mt < 4; mt++)
            #pragma unroll
            for (int half_ = 0; half_ < 2; half_++) {
                int row = rowBase + m0 + mt * 16 + half_ * 8 + rr;
                float2 xv = *reinterpret_cast<const float2*>(x + (size_t)row * E + c);
                acc[mt][nt][2*half_]   = fmaxf(acc[mt][nt][2*half_]   + bv2.x, 0.f) + xv.x;
                acc[mt][nt][2*half_+1] = fmaxf(acc[mt][nt][2*half_+1] + bv2.y, 0.f) + xv.y;
            }
    }

    ln_mma(acc, (float*)dynsm);

    #pragma unroll
    for (int nt = 0; nt < 4; nt++) {
        const int c = n0 + nt * 8 + 2 * cg;
        float2 gv = *reinterpret_cast<const float2*>(gamma + c);
        float2 ev = *reinterpret_cast<const float2*>(beta + c);
        #pragma unroll
        for (int mt = 0; mt < 4; mt++)
            #pragma unroll
            for (int half_ = 0; half_ < 2; half_++) {
                int row = rowBase + m0 + mt * 16 + half_ * 8 + rr;
                float o0 = acc[mt][nt][2*half_]   * gv.x + ev.x;
                float o1 = acc[mt][nt][2*half_+1] * gv.y + ev.y;
                *reinterpret_cast<float2*>(out + (size_t)row * E + c) = make_float2(o0, o1);
            }
    }
}

// ---------------------------------------------------------------------------
extern "C" void kernel_launch(void* const* d_in, const int* in_sizes, int n_in,
                              void* d_out, int out_size)
{
    const float* x     = (const float*)d_in[0];
    const float* Wq    = (const float*)d_in[1];
    const float* bq    = (const float*)d_in[2];
    const float* Wk    = (const float*)d_in[3];
    const float* bk    = (const float*)d_in[4];
    const float* Wv    = (const float*)d_in[5];
    const float* bv    = (const float*)d_in[6];
    const float* W1    = (const float*)d_in[7];
    const float* b1    = (const float*)d_in[8];
    const float* W2    = (const float*)d_in[9];
    const float* b2    = (const float*)d_in[10];
    const float* gamma = (const float*)d_in[11];
    const float* beta  = (const float*)d_in[12];
    float* out = (float*)d_out;

    const int SMEM  = 2 * 3 * 4096 * (int)sizeof(__half);   // 48KB (2-pass)
    const int SMEM1 = 2 * 2 * 4096 * (int)sizeof(__half);   // 32KB (1-pass)
    cudaFuncSetAttribute(qkv_mma,    cudaFuncAttributeMaxDynamicSharedMemorySize, SMEM);
    cudaFuncSetAttribute(scores_mma, cudaFuncAttributeMaxDynamicSharedMemorySize, SMEM1);
    cudaFuncSetAttribute(av_mma,     cudaFuncAttributeMaxDynamicSharedMemorySize, SMEM1);
    cudaFuncSetAttribute(mlp1_mma,   cudaFuncAttributeMaxDynamicSharedMemorySize, SMEM1);
    cudaFuncSetAttribute(mlp2_mma,   cudaFuncAttributeMaxDynamicSharedMemorySize, SMEM1);

    dim3 blk(256);
    prep_all      <<<dim3(4368), blk>>>(x, Wq, Wk, Wv, W1, W2);
    qkv_mma       <<<dim3(256, 4, 3), blk, SMEM>>>(bq, bk, bv);
    vtrans_kernel <<<dim3(256, 4, 16), blk>>>();
    scores_mma    <<<dim3(4, 4, 256), blk, SMEM1>>>();
    softmax_kernel<<<dim3(4096), blk>>>();
    av_mma        <<<dim3(4, 1, 256), blk, SMEM1>>>();
    mlp1_mma      <<<dim3(256), blk, SMEM1>>>(b1);
    mlp2_mma      <<<dim3(256), blk, SMEM1>>>(x, b2, gamma, beta, out);
}

// round 15
// speedup vs baseline: 2.1571x; 1.1256x over previous
#include <cuda_runtime.h>
#include <cuda_fp16.h>
#include <cstdint>

constexpr int Bdim = 64;
constexpr int Nseq = 512;
constexpr int E    = 128;
constexpr int D    = 128;
constexpr int H    = 4;

// ---------------- scratch (allocation-free) ----------------
__device__ __half g_x  [(size_t)Bdim*Nseq*E];     // single fp16
__device__ __half g_WT [12 * 128 * 128];          // [which*4+h][d][e] transposed
__device__ __half g_W1T[128 * 512];               // [e_out][k]
__device__ __half g_W2T[128 * 128];
__device__ __half g_Q [(size_t)Bdim*H*Nseq*D];
__device__ __half g_K [(size_t)Bdim*H*Nseq*D];
__device__ __half g_V [(size_t)Bdim*H*Nseq*E];    // [bh][n][e]
__device__ __half g_Vt[(size_t)Bdim*H*E*Nseq];    // [bh][e][n]
__device__ __half g_S [(size_t)Bdim*H*Nseq*Nseq]; // fp16 scores (unscaled)
__device__ __half g_P [(size_t)Bdim*H*Nseq*Nseq]; // post-softmax
__device__ __half g_A [(size_t)Bdim*Nseq*H*E];    // [B,N,512] concat
__device__ __half g_H1[(size_t)Bdim*Nseq*E];

// ======================= mma.sync machinery (fp16) =======================
__device__ __forceinline__ void ldsm_x4(uint32_t r[4], const void* p) {
    uint32_t addr = (uint32_t)__cvta_generic_to_shared(p);
    asm volatile("ldmatrix.sync.aligned.m8n8.x4.shared.b16 {%0,%1,%2,%3}, [%4];"
                 : "=r"(r[0]), "=r"(r[1]), "=r"(r[2]), "=r"(r[3]) : "r"(addr));
}
__device__ __forceinline__ void mma16816(float c[4], const uint32_t a[4], const uint32_t b[2]) {
    asm volatile("mma.sync.aligned.m16n8k16.row.col.f32.f16.f16.f32 "
                 "{%0,%1,%2,%3}, {%4,%5,%6,%7}, {%8,%9}, {%0,%1,%2,%3};"
                 : "+f"(c[0]), "+f"(c[1]), "+f"(c[2]), "+f"(c[3])
                 : "r"(a[0]), "r"(a[1]), "r"(a[2]), "r"(a[3]), "r"(b[0]), "r"(b[1]));
}
__device__ __forceinline__ int sw_idx(int row, int seg) {
    return row * 32 + ((seg ^ ((row >> 1) & 3)) << 3);
}
__device__ __forceinline__ void cp_plane(__half* dst, const __half* src,
                                         int ld, int kc, int tid)
{
    #pragma unroll
    for (int s = 0; s < 2; s++) {
        int idx = tid + s * 256;
        int row = idx >> 2, seg = idx & 3;
        uint32_t d = (uint32_t)__cvta_generic_to_shared(dst + sw_idx(row, seg));
        const __half* g = src + (size_t)row * ld + kc + seg * 8;
        asm volatile("cp.async.cg.shared.global [%0], [%1], 16;" :: "r"(d), "l"(g));
    }
}
__device__ __forceinline__ void load_a_frag(uint32_t a[4][4], const __half* plane,
                                            int m0, int seg_base, int lane)
{
    const int r = lane & 15, half_ = lane >> 4;
    #pragma unroll
    for (int t = 0; t < 4; t++)
        ldsm_x4(a[t], plane + sw_idx(m0 + t * 16 + r, seg_base + half_));
}
__device__ __forceinline__ void load_b_frag(uint32_t b[4][2], const __half* plane,
                                            int n0, int seg_base, int lane)
{
    const int r = lane & 15, half_ = lane >> 4;
    #pragma unroll
    for (int p = 0; p < 2; p++) {
        uint32_t t[4];
        ldsm_x4(t, plane + sw_idx(n0 + p * 16 + r, seg_base + half_));
        b[2*p][0]   = t[0];
        b[2*p+1][0] = t[1];
        b[2*p][1]   = t[2];
        b[2*p+1][1] = t[3];
    }
}
__device__ __forceinline__ void mma_all(float acc[4][4][4], const uint32_t a[4][4],
                                        const uint32_t b[4][2])
{
    #pragma unroll
    for (int mt = 0; mt < 4; mt++)
        #pragma unroll
        for (int nt = 0; nt < 4; nt++)
            mma16816(acc[mt][nt], a[mt], b[nt]);
}
__device__ __forceinline__ void acc_zero(float acc[4][4][4])
{
    #pragma unroll
    for (int mt = 0; mt < 4; mt++)
        #pragma unroll
        for (int nt = 0; nt < 4; nt++)
            #pragma unroll
            for (int q = 0; q < 4; q++) acc[mt][nt][q] = 0.f;
}

#define PLANE 4096

// ---------------------------------------------------------------------------
// 1-pass core: C = A * B (both single fp16). 2 stages x 2 planes = 32KB smem.
// ---------------------------------------------------------------------------
__device__ __forceinline__ void mma_core1(
                         const __half* __restrict__ A, int lda,
                         const __half* __restrict__ B, int ldb,
                         int K, __half* sm, float acc[4][4][4])
{
    const int tid = threadIdx.x, lane = tid & 31, wid = tid >> 5;
    const int m0 = (wid >> 2) * 64, n0 = (wid & 3) * 32;
    acc_zero(acc);

    cp_plane(sm + 0*PLANE, A, lda, 0, tid);
    cp_plane(sm + 1*PLANE, B, ldb, 0, tid);
    asm volatile("cp.async.commit_group;");

    const int NC = K >> 5;
    for (int c = 0; c < NC; c++) {
        __half* st = sm + (c & 1) * (2 * PLANE);
        if (c + 1 < NC) {
            __half* st2 = sm + ((c + 1) & 1) * (2 * PLANE);
            const int kc = (c + 1) * 32;
            cp_plane(st2 + 0*PLANE, A, lda, kc, tid);
            cp_plane(st2 + 1*PLANE, B, ldb, kc, tid);
            asm volatile("cp.async.commit_group;");
            asm volatile("cp.async.wait_group 1;");
        } else {
            asm volatile("cp.async.wait_group 0;");
        }
        __syncthreads();
        #pragma unroll
        for (int ks = 0; ks < 2; ks++) {
            const int seg = ks * 2;
            uint32_t a[4][4];
            uint32_t b[4][2];
            load_b_frag(b, st + 1*PLANE, n0, seg, lane);
            load_a_frag(a, st + 0*PLANE, m0, seg, lane);
            mma_all(acc, a, b);
        }
        __syncthreads();
    }
}

// LayerNorm over 128 cols in mma fragment layout. lnbuf >= 1280 floats.
__device__ __forceinline__ void ln_mma(float acc[4][4][4], float* lnbuf)
{
    float* lnS = lnbuf;
    float* lnQ = lnbuf + 512;
    float* mrs = lnbuf + 1024;
    const int tid = threadIdx.x, lane = tid & 31, wid = tid >> 5;
    const int wn = wid & 3, m0 = (wid >> 2) * 64;
    const int rr = lane >> 2, cg = lane & 3;

    #pragma unroll
    for (int mt = 0; mt < 4; mt++)
        #pragma unroll
        for (int half_ = 0; half_ < 2; half_++) {
            float s = 0.f, q = 0.f;
            #pragma unroll
            for (int nt = 0; nt < 4; nt++) {
                float v0 = acc[mt][nt][2*half_], v1 = acc[mt][nt][2*half_+1];
                s += v0 + v1; q += v0 * v0 + v1 * v1;
            }
            s += __shfl_xor_sync(0xffffffffu, s, 1);
            s += __shfl_xor_sync(0xffffffffu, s, 2);
            q += __shfl_xor_sync(0xffffffffu, q, 1);
            q += __shfl_xor_sync(0xffffffffu, q, 2);
            if (cg == 0) {
                int row = m0 + mt * 16 + half_ * 8 + rr;
                lnS[row * 4 + wn] = s;
                lnQ[row * 4 + wn] = q;
            }
        }
    __syncthreads();
    if (tid < 128) {
        float s = lnS[tid*4] + lnS[tid*4+1] + lnS[tid*4+2] + lnS[tid*4+3];
        float q = lnQ[tid*4] + lnQ[tid*4+1] + lnQ[tid*4+2] + lnQ[tid*4+3];
        float mean = s * (1.0f / 128.0f);
        float var  = q * (1.0f / 128.0f) - mean * mean;
        mrs[tid]       = mean;
        mrs[128 + tid] = rsqrtf(var + 1e-5f);
    }
    __syncthreads();
    #pragma unroll
    for (int mt = 0; mt < 4; mt++)
        #pragma unroll
        for (int half_ = 0; half_ < 2; half_++) {
            int row = m0 + mt * 16 + half_ * 8 + rr;
            float mu = mrs[row], rs = mrs[128 + row];
            #pragma unroll
            for (int nt = 0; nt < 4; nt++) {
                acc[mt][nt][2*half_]   = (acc[mt][nt][2*half_]   - mu) * rs;
                acc[mt][nt][2*half_+1] = (acc[mt][nt][2*half_+1] - mu) * rs;
            }
        }
}

__device__ __forceinline__ uint32_t pack_s2(float v0, float v1)
{
    __half h0 = __float2half(v0), h1 = __float2half(v1);
    return (uint32_t)__half_as_ushort(h0) | ((uint32_t)__half_as_ushort(h1) << 16);
}

__device__ __forceinline__ void store_single(const float acc[4][4][4],
                                             __half* o, int ldc)
{
    const int lane = threadIdx.x & 31, wid = threadIdx.x >> 5;
    const int m0 = (wid >> 2) * 64, n0 = (wid & 3) * 32;
    const int rr = lane >> 2, cg = lane & 3;
    #pragma unroll
    for (int mt = 0; mt < 4; mt++)
        #pragma unroll
        for (int half_ = 0; half_ < 2; half_++) {
            int row = m0 + mt * 16 + half_ * 8 + rr;
            #pragma unroll
            for (int nt = 0; nt < 4; nt++) {
                int c = n0 + nt * 8 + 2 * cg;
                *reinterpret_cast<uint32_t*>(o + (size_t)row * ldc + c) =
                    pack_s2(acc[mt][nt][2*half_], acc[mt][nt][2*half_+1]);
            }
        }
}

// ======================= fused prep kernel =======================
__device__ __forceinline__ void transplit_tile(const float* src, __half* dh,
                                               int R, int C, int r0, int c0)
{
    __shared__ float t[32][33];
    const int tid = threadIdx.x;
    #pragma unroll
    for (int s = 0; s < 4; s++) {
        int idx = tid + s * 256;
        int r = idx >> 5, c = idx & 31;
        t[r][c] = src[(size_t)(r0 + r) * C + c0 + c];
    }
    __syncthreads();
    #pragma unroll
    for (int s = 0; s < 4; s++) {
        int idx = tid + s * 256;
        int co = idx >> 5, ro = idx & 31;
        dh[(size_t)(c0 + co) * R + r0 + ro] = __float2half(t[ro][co]);
    }
}

// blocks: 0..4095 x convert; 4096..4287 W qkv; 4288..4351 W1; 4352..4367 W2
__global__ __launch_bounds__(256) void prep_all(
    const float* __restrict__ x,
    const float* __restrict__ Wq, const float* __restrict__ Wk, const float* __restrict__ Wv,
    const float* __restrict__ W1, const float* __restrict__ W2)
{
    const int bid = blockIdx.x;
    if (bid < 4096) {
        const size_t i4 = (size_t)bid * 256 + threadIdx.x;
        float4 v = *reinterpret_cast<const float4*>(x + i4 * 4);
        uint32_t h0 = pack_s2(v.x, v.y);
        uint32_t h1 = pack_s2(v.z, v.w);
        *reinterpret_cast<uint2*>(g_x + i4 * 4) = make_uint2(h0, h1);
    } else if (bid < 4288) {
        const int j = bid - 4096;
        const int midx = j >> 4, rem = j & 15;
        const int which = midx >> 2, h = midx & 3;
        const float* src = (which == 0 ? Wq : (which == 1 ? Wk : Wv)) + (size_t)h * 128 * 128;
        transplit_tile(src, g_WT + (size_t)midx * 16384,
                       128, 128, (rem >> 2) * 32, (rem & 3) * 32);
    } else if (bid < 4352) {
        const int j = bid - 4288;
        transplit_tile(W1, g_W1T, 512, 128, (j >> 2) * 32, (j & 3) * 32);
    } else {
        const int j = bid - 4352;
        transplit_tile(W2, g_W2T, 128, 128, (j >> 2) * 32, (j & 3) * 32);
    }
}

// ======================= main kernels =======================
extern __shared__ __half dynsm[];

// QKV (1-pass): grid (256, 4, 3). Q/K/V all stored single.
__global__ __launch_bounds__(256, 2) void qkv_mma(
    const float* __restrict__ bq, const float* __restrict__ bk, const float* __restrict__ bv)
{
    const int rowBase = blockIdx.x * 128;
    const int h = blockIdx.y, which = blockIdx.z;
    const int midx = which * 4 + h;
    const float* bias = (which == 0 ? bq : (which == 1 ? bk : bv)) + (size_t)h * 128;

    float acc[4][4][4];
    mma_core1(g_x + (size_t)rowBase * E, E,
              g_WT + (size_t)midx * 16384, E, E, dynsm, acc);

    const int lane = threadIdx.x & 31, wid = threadIdx.x >> 5;
    const int n0 = (wid & 3) * 32, cg = lane & 3;
    #pragma unroll
    for (int nt = 0; nt < 4; nt++) {
        float2 bv2 = *reinterpret_cast<const float2*>(bias + n0 + nt * 8 + 2 * cg);
        #pragma unroll
        for (int mt = 0; mt < 4; mt++) {
            acc[mt][nt][0] += bv2.x; acc[mt][nt][1] += bv2.y;
            acc[mt][nt][2] += bv2.x; acc[mt][nt][3] += bv2.y;
        }
    }
    ln_mma(acc, (float*)dynsm);

    const int b = rowBase >> 9, nBase = rowBase & 511;
    const int bh = b * H + h;
    const size_t off = ((size_t)bh * Nseq + nBase) * 128;
    __half* o = (which == 0 ? g_Q : (which == 1 ? g_K : g_V)) + off;
    store_single(acc, o, 128);
}

// V transpose: grid (256, 4, 16)
__global__ __launch_bounds__(256) void vtrans_kernel()
{
    __shared__ __half t[32][33];
    const int bh = blockIdx.x, e0 = blockIdx.y * 32, n0 = blockIdx.z * 32;
    const int tid = threadIdx.x;
    const size_t inBase = ((size_t)bh * Nseq + n0) * E + e0;
    #pragma unroll
    for (int s = 0; s < 4; s++) {
        int idx = tid + s * 256;
        int r = idx >> 5, c = idx & 31;
        t[r][c] = g_V[inBase + (size_t)r * E + c];
    }
    __syncthreads();
    const size_t outBase = ((size_t)bh * E + e0) * Nseq + n0;
    #pragma unroll
    for (int s = 0; s < 4; s++) {
        int idx = tid + s * 256;
        int r = idx >> 5, c = idx & 31;
        g_Vt[outBase + (size_t)r * Nseq + c] = t[c][r];
    }
}

// scores = Q K^T (1-pass) -> fp16 S. grid (4, 4, 256)
__global__ __launch_bounds__(256, 2) void scores_mma()
{
    const int bh = blockIdx.z;
    const size_t rowBase = blockIdx.x * 128, colBase = blockIdx.y * 128;
    float acc[4][4][4];
    mma_core1(g_Q + ((size_t)bh * Nseq + rowBase) * D, D,
              g_K + ((size_t)bh * Nseq + colBase) * D, D, D, dynsm, acc);
    store_single(acc, g_S + (size_t)bh * Nseq * Nseq + rowBase * Nseq + colBase, Nseq);
}

// batch-axis softmax -> P single plane. grid (4096)
__global__ __launch_bounds__(256) void softmax_kernel()
{
    const size_t idx = (size_t)blockIdx.x * 256 + threadIdx.x;
    const size_t stride = (size_t)H * Nseq * Nseq;
    float v[64];
    float mx = -1e30f;
    #pragma unroll
    for (int b = 0; b < 64; b++) {
        float t = __half2float(g_S[(size_t)b * stride + idx]) * (1.0f / 11.0f);
        v[b] = t;
        mx = fmaxf(mx, t);
    }
    float s = 0.f;
    #pragma unroll
    for (int b = 0; b < 64; b++) { float e = __expf(v[b] - mx); v[b] = e; s += e; }
    const float inv = 1.0f / s;
    #pragma unroll
    for (int b = 0; b < 64; b++)
        g_P[(size_t)b * stride + idx] = __float2half(v[b] * inv);
}

// A = P V (1-pass) -> single concat layout. grid (4, 1, 256)
__global__ __launch_bounds__(256, 2) void av_mma()
{
    const int bh = blockIdx.z, b = bh >> 2, h = bh & 3;
    const size_t rowBase = blockIdx.x * 128;
    float acc[4][4][4];
    mma_core1(g_P + ((size_t)bh * Nseq + rowBase) * Nseq, Nseq,
              g_Vt + (size_t)bh * E * Nseq, Nseq, Nseq, dynsm, acc);
    const size_t off = ((size_t)b * Nseq + rowBase) * (H * E) + (size_t)h * E;
    store_single(acc, g_A + off, H * E);
}

// h1 = relu(A @ W1 + b1) (1-pass) -> single. grid (256)
__global__ __launch_bounds__(256, 2) void mlp1_mma(const float* __restrict__ b1)
{
    const int rowBase = blockIdx.x * 128;
    float acc[4][4][4];
    mma_core1(g_A + (size_t)rowBase * (H * E), H * E,
              g_W1T, H * E, H * E, dynsm, acc);

    const int lane = threadIdx.x & 31, wid = threadIdx.x >> 5;
    const int n0 = (wid & 3) * 32, cg = lane & 3;
    #pragma unroll
    for (int nt = 0; nt < 4; nt++) {
        float2 bv2 = *reinterpret_cast<const float2*>(b1 + n0 + nt * 8 + 2 * cg);
        #pragma unroll
        for (int mt = 0; mt < 4; mt++) {
            acc[mt][nt][0] = fmaxf(acc[mt][nt][0] + bv2.x, 0.f);
            acc[mt][nt][1] = fmaxf(acc[mt][nt][1] + bv2.y, 0.f);
            acc[mt][nt][2] = fmaxf(acc[mt][nt][2] + bv2.x, 0.f);
            acc[mt][nt][3] = fmaxf(acc[mt][nt][3] + bv2.y, 0.f);
        }
    }
    store_single(acc, g_H1 + (size_t)rowBase * E, E);
}

// out = LN(x + relu(h1 @ W2 + b2)) * gamma + beta (1-pass). grid (256)
__global__ __launch_bounds__(256, 2) void mlp2_mma(
    const float* __restrict__ x, const float* __restrict__ b2,
    const float* __restrict__ gamma, const float* __restrict__ beta,
    float* __restrict__ out)
{
    const int rowBase = blockIdx.x * 128;
    float acc[4][4][4];
    mma_core1(g_H1 + (size_t)rowBase * E, E, g_W2T, E, E, dynsm, acc);

    const int lane = threadIdx.x & 31, wid = threadIdx.x >> 5;
    const int m0 = (wid >> 2) * 64, n0 = (wid & 3) * 32;
    const int rr = lane >> 2, cg = lane & 3;
    #pragma unroll
    for (int nt = 0; nt < 4; nt++) {
        const int c = n0 + nt * 8 + 2 * cg;
        float2 bv2 = *reinterpret_cast<const float2*>(b2 + c);
        #pragma unroll
        for (int mt = 0; mt < 4; mt++)
            #pragma unroll
            for (int half_ = 0; half_ < 2; half_++) {
                int row = rowBase + m0 + mt * 16 + half_ * 8 + rr;
                float2 xv = *reinterpret_cast<const float2*>(x + (size_t)row * E + c);
                acc[mt][nt][2*half_]   = fmaxf(acc[mt][nt][2*half_]   + bv2.x, 0.f) + xv.x;
                acc[mt][nt][2*half_+1] = fmaxf(acc[mt][nt][2*half_+1] + bv2.y, 0.f) + xv.y;
            }
    }

    ln_mma(acc, (float*)dynsm);

    #pragma unroll
    for (int nt = 0; nt < 4; nt++) {
        const int c = n0 + nt * 8 + 2 * cg;
        float2 gv = *reinterpret_cast<const float2*>(gamma + c);
        float2 ev = *reinterpret_cast<const float2*>(beta + c);
        #pragma unroll
        for (int mt = 0; mt < 4; mt++)
            #pragma unroll
            for (int half_ = 0; half_ < 2; half_++) {
                int row = rowBase + m0 + mt * 16 + half_ * 8 + rr;
                float o0 = acc[mt][nt][2*half_]   * gv.x + ev.x;
                float o1 = acc[mt][nt][2*half_+1] * gv.y + ev.y;
                *reinterpret_cast<float2*>(out + (size_t)row * E + c) = make_float2(o0, o1);
            }
    }
}

// ---------------------------------------------------------------------------
extern "C" void kernel_launch(void* const* d_in, const int* in_sizes, int n_in,
                              void* d_out, int out_size)
{
    const float* x     = (const float*)d_in[0];
    const float* Wq    = (const float*)d_in[1];
    const float* bq    = (const float*)d_in[2];
    const float* Wk    = (const float*)d_in[3];
    const float* bk    = (const float*)d_in[4];
    const float* Wv    = (const float*)d_in[5];
    const float* bv    = (const float*)d_in[6];
    const float* W1    = (const float*)d_in[7];
    const float* b1    = (const float*)d_in[8];
    const float* W2    = (const float*)d_in[9];
    const float* b2    = (const float*)d_in[10];
    const float* gamma = (const float*)d_in[11];
    const float* beta  = (const float*)d_in[12];
    float* out = (float*)d_out;

    const int SMEM1 = 2 * 2 * 4096 * (int)sizeof(__half);   // 32KB (1-pass)
    cudaFuncSetAttribute(qkv_mma,    cudaFuncAttributeMaxDynamicSharedMemorySize, SMEM1);
    cudaFuncSetAttribute(scores_mma, cudaFuncAttributeMaxDynamicSharedMemorySize, SMEM1);
    cudaFuncSetAttribute(av_mma,     cudaFuncAttributeMaxDynamicSharedMemorySize, SMEM1);
    cudaFuncSetAttribute(mlp1_mma,   cudaFuncAttributeMaxDynamicSharedMemorySize, SMEM1);
    cudaFuncSetAttribute(mlp2_mma,   cudaFuncAttributeMaxDynamicSharedMemorySize, SMEM1);

    dim3 blk(256);
    prep_all      <<<dim3(4368), blk>>>(x, Wq, Wk, Wv, W1, W2);
    qkv_mma       <<<dim3(256, 4, 3), blk, SMEM1>>>(bq, bk, bv);
    vtrans_kernel <<<dim3(256, 4, 16), blk>>>();
    scores_mma    <<<dim3(4, 4, 256), blk, SMEM1>>>();
    softmax_kernel<<<dim3(4096), blk>>>();
    av_mma        <<<dim3(4, 1, 256), blk, SMEM1>>>();
    mlp1_mma      <<<dim3(256), blk, SMEM1>>>(b1);
    mlp2_mma      <<<dim3(256), blk, SMEM1>>>(x, b2, gamma, beta, out);
}

// round 16
// speedup vs baseline: 2.1573x; 1.0001x over previous
#include <cuda_runtime.h>
#include <cuda_fp16.h>
#include <cstdint>

constexpr int Bdim = 64;
constexpr int Nseq = 512;
constexpr int E    = 128;
constexpr int D    = 128;
constexpr int H    = 4;

// ---------------- scratch (allocation-free) ----------------
__device__ __half g_x  [(size_t)Bdim*Nseq*E];     // single fp16
__device__ __half g_WT [12 * 128 * 128];          // [which*4+h][d][e] transposed
__device__ __half g_W1T[128 * 512];               // [e_out][k]
__device__ __half g_W2T[128 * 128];
__device__ __half g_Q [(size_t)Bdim*H*Nseq*D];
__device__ __half g_K [(size_t)Bdim*H*Nseq*D];
__device__ __half g_V [(size_t)Bdim*H*Nseq*E];    // [bh][n][e]
__device__ __half g_Vt[(size_t)Bdim*H*E*Nseq];    // [bh][e][n]
__device__ __half g_S [(size_t)Bdim*H*Nseq*Nseq]; // fp16 scores (unscaled)
__device__ __half g_P [(size_t)Bdim*H*Nseq*Nseq]; // post-softmax
__device__ __half g_A [(size_t)Bdim*Nseq*H*E];    // [B,N,512] concat
__device__ __half g_H1[(size_t)Bdim*Nseq*E];

// ======================= mma.sync machinery (fp16) =======================
__device__ __forceinline__ void ldsm_x4(uint32_t r[4], const void* p) {
    uint32_t addr = (uint32_t)__cvta_generic_to_shared(p);
    asm volatile("ldmatrix.sync.aligned.m8n8.x4.shared.b16 {%0,%1,%2,%3}, [%4];"
                 : "=r"(r[0]), "=r"(r[1]), "=r"(r[2]), "=r"(r[3]) : "r"(addr));
}
__device__ __forceinline__ void mma16816(float c[4], const uint32_t a[4], const uint32_t b[2]) {
    asm volatile("mma.sync.aligned.m16n8k16.row.col.f32.f16.f16.f32 "
                 "{%0,%1,%2,%3}, {%4,%5,%6,%7}, {%8,%9}, {%0,%1,%2,%3};"
                 : "+f"(c[0]), "+f"(c[1]), "+f"(c[2]), "+f"(c[3])
                 : "r"(a[0]), "r"(a[1]), "r"(a[2]), "r"(a[3]), "r"(b[0]), "r"(b[1]));
}
__device__ __forceinline__ int sw_idx(int row, int seg) {
    return row * 32 + ((seg ^ ((row >> 1) & 3)) << 3);
}
__device__ __forceinline__ void cp_plane(__half* dst, const __half* src,
                                         int ld, int kc, int tid)
{
    #pragma unroll
    for (int s = 0; s < 2; s++) {
        int idx = tid + s * 256;
        int row = idx >> 2, seg = idx & 3;
        uint32_t d = (uint32_t)__cvta_generic_to_shared(dst + sw_idx(row, seg));
        const __half* g = src + (size_t)row * ld + kc + seg * 8;
        asm volatile("cp.async.cg.shared.global [%0], [%1], 16;" :: "r"(d), "l"(g));
    }
}
__device__ __forceinline__ void load_a_frag(uint32_t a[4][4], const __half* plane,
                                            int m0, int seg_base, int lane)
{
    const int r = lane & 15, half_ = lane >> 4;
    #pragma unroll
    for (int t = 0; t < 4; t++)
        ldsm_x4(a[t], plane + sw_idx(m0 + t * 16 + r, seg_base + half_));
}
__device__ __forceinline__ void load_b_frag(uint32_t b[4][2], const __half* plane,
                                            int n0, int seg_base, int lane)
{
    const int r = lane & 15, half_ = lane >> 4;
    #pragma unroll
    for (int p = 0; p < 2; p++) {
        uint32_t t[4];
        ldsm_x4(t, plane + sw_idx(n0 + p * 16 + r, seg_base + half_));
        b[2*p][0]   = t[0];
        b[2*p+1][0] = t[1];
        b[2*p][1]   = t[2];
        b[2*p+1][1] = t[3];
    }
}
__device__ __forceinline__ void mma_all(float acc[4][4][4], const uint32_t a[4][4],
                                        const uint32_t b[4][2])
{
    #pragma unroll
    for (int mt = 0; mt < 4; mt++)
        #pragma unroll
        for (int nt = 0; nt < 4; nt++)
            mma16816(acc[mt][nt], a[mt], b[nt]);
}
__device__ __forceinline__ void acc_zero(float acc[4][4][4])
{
    #pragma unroll
    for (int mt = 0; mt < 4; mt++)
        #pragma unroll
        for (int nt = 0; nt < 4; nt++)
            #pragma unroll
            for (int q = 0; q < 4; q++) acc[mt][nt][q] = 0.f;
}

#define PLANE 4096

// ---------------------------------------------------------------------------
// 1-pass streaming core: C = A * B. 2 stages x 2 planes = 32KB smem.
// ---------------------------------------------------------------------------
__device__ __forceinline__ void mma_core1(
                         const __half* __restrict__ A, int lda,
                         const __half* __restrict__ B, int ldb,
                         int K, __half* sm, float acc[4][4][4])
{
    const int tid = threadIdx.x, lane = tid & 31, wid = tid >> 5;
    const int m0 = (wid >> 2) * 64, n0 = (wid & 3) * 32;
    acc_zero(acc);

    cp_plane(sm + 0*PLANE, A, lda, 0, tid);
    cp_plane(sm + 1*PLANE, B, ldb, 0, tid);
    asm volatile("cp.async.commit_group;");

    const int NC = K >> 5;
    for (int c = 0; c < NC; c++) {
        __half* st = sm + (c & 1) * (2 * PLANE);
        if (c + 1 < NC) {
            __half* st2 = sm + ((c + 1) & 1) * (2 * PLANE);
            const int kc = (c + 1) * 32;
            cp_plane(st2 + 0*PLANE, A, lda, kc, tid);
            cp_plane(st2 + 1*PLANE, B, ldb, kc, tid);
            asm volatile("cp.async.commit_group;");
            asm volatile("cp.async.wait_group 1;");
        } else {
            asm volatile("cp.async.wait_group 0;");
        }
        __syncthreads();
        #pragma unroll
        for (int ks = 0; ks < 2; ks++) {
            const int seg = ks * 2;
            uint32_t a[4][4];
            uint32_t b[4][2];
            load_b_frag(b, st + 1*PLANE, n0, seg, lane);
            load_a_frag(a, st + 0*PLANE, m0, seg, lane);
            mma_all(acc, a, b);
        }
        __syncthreads();
    }
}

// Compute 128x128 tile from fully-resident smem tiles (4 planes each), no syncs.
__device__ __forceinline__ void mma_resident(const __half* As, const __half* Bs,
                                             float acc[4][4][4])
{
    const int lane = threadIdx.x & 31, wid = threadIdx.x >> 5;
    const int m0 = (wid >> 2) * 64, n0 = (wid & 3) * 32;
    acc_zero(acc);
    #pragma unroll
    for (int chunk = 0; chunk < 4; chunk++) {
        #pragma unroll
        for (int ks = 0; ks < 2; ks++) {
            const int seg = ks * 2;
            uint32_t a[4][4];
            uint32_t b[4][2];
            load_b_frag(b, Bs + chunk * PLANE, n0, seg, lane);
            load_a_frag(a, As + chunk * PLANE, m0, seg, lane);
            mma_all(acc, a, b);
        }
    }
}

// LayerNorm over 128 cols in mma fragment layout. lnbuf >= 1280 floats.
__device__ __forceinline__ void ln_mma(float acc[4][4][4], float* lnbuf)
{
    float* lnS = lnbuf;
    float* lnQ = lnbuf + 512;
    float* mrs = lnbuf + 1024;
    const int tid = threadIdx.x, lane = tid & 31, wid = tid >> 5;
    const int wn = wid & 3, m0 = (wid >> 2) * 64;
    const int rr = lane >> 2, cg = lane & 3;

    #pragma unroll
    for (int mt = 0; mt < 4; mt++)
        #pragma unroll
        for (int half_ = 0; half_ < 2; half_++) {
            float s = 0.f, q = 0.f;
            #pragma unroll
            for (int nt = 0; nt < 4; nt++) {
                float v0 = acc[mt][nt][2*half_], v1 = acc[mt][nt][2*half_+1];
                s += v0 + v1; q += v0 * v0 + v1 * v1;
            }
            s += __shfl_xor_sync(0xffffffffu, s, 1);
            s += __shfl_xor_sync(0xffffffffu, s, 2);
            q += __shfl_xor_sync(0xffffffffu, q, 1);
            q += __shfl_xor_sync(0xffffffffu, q, 2);
            if (cg == 0) {
                int row = m0 + mt * 16 + half_ * 8 + rr;
                lnS[row * 4 + wn] = s;
                lnQ[row * 4 + wn] = q;
            }
        }
    __syncthreads();
    if (tid < 128) {
        float s = lnS[tid*4] + lnS[tid*4+1] + lnS[tid*4+2] + lnS[tid*4+3];
        float q = lnQ[tid*4] + lnQ[tid*4+1] + lnQ[tid*4+2] + lnQ[tid*4+3];
        float mean = s * (1.0f / 128.0f);
        float var  = q * (1.0f / 128.0f) - mean * mean;
        mrs[tid]       = mean;
        mrs[128 + tid] = rsqrtf(var + 1e-5f);
    }
    __syncthreads();
    #pragma unroll
    for (int mt = 0; mt < 4; mt++)
        #pragma unroll
        for (int half_ = 0; half_ < 2; half_++) {
            int row = m0 + mt * 16 + half_ * 8 + rr;
            float mu = mrs[row], rs = mrs[128 + row];
            #pragma unroll
            for (int nt = 0; nt < 4; nt++) {
                acc[mt][nt][2*half_]   = (acc[mt][nt][2*half_]   - mu) * rs;
                acc[mt][nt][2*half_+1] = (acc[mt][nt][2*half_+1] - mu) * rs;
            }
        }
}

__device__ __forceinline__ uint32_t pack_s2(float v0, float v1)
{
    __half h0 = __float2half(v0), h1 = __float2half(v1);
    return (uint32_t)__half_as_ushort(h0) | ((uint32_t)__half_as_ushort(h1) << 16);
}

__device__ __forceinline__ void store_single(const float acc[4][4][4],
                                             __half* o, int ldc)
{
    const int lane = threadIdx.x & 31, wid = threadIdx.x >> 5;
    const int m0 = (wid >> 2) * 64, n0 = (wid & 3) * 32;
    const int rr = lane >> 2, cg = lane & 3;
    #pragma unroll
    for (int mt = 0; mt < 4; mt++)
        #pragma unroll
        for (int half_ = 0; half_ < 2; half_++) {
            int row = m0 + mt * 16 + half_ * 8 + rr;
            #pragma unroll
            for (int nt = 0; nt < 4; nt++) {
                int c = n0 + nt * 8 + 2 * cg;
                *reinterpret_cast<uint32_t*>(o + (size_t)row * ldc + c) =
                    pack_s2(acc[mt][nt][2*half_], acc[mt][nt][2*half_+1]);
            }
        }
}

// ======================= fused prep kernel =======================
__device__ __forceinline__ void transplit_tile(const float* src, __half* dh,
                                               int R, int C, int r0, int c0)
{
    __shared__ float t[32][33];
    const int tid = threadIdx.x;
    #pragma unroll
    for (int s = 0; s < 4; s++) {
        int idx = tid + s * 256;
        int r = idx >> 5, c = idx & 31;
        t[r][c] = src[(size_t)(r0 + r) * C + c0 + c];
    }
    __syncthreads();
    #pragma unroll
    for (int s = 0; s < 4; s++) {
        int idx = tid + s * 256;
        int co = idx >> 5, ro = idx & 31;
        dh[(size_t)(c0 + co) * R + r0 + ro] = __float2half(t[ro][co]);
    }
}

__global__ __launch_bounds__(256) void prep_all(
    const float* __restrict__ x,
    const float* __restrict__ Wq, const float* __restrict__ Wk, const float* __restrict__ Wv,
    const float* __restrict__ W1, const float* __restrict__ W2)
{
    const int bid = blockIdx.x;
    if (bid < 4096) {
        const size_t i4 = (size_t)bid * 256 + threadIdx.x;
        float4 v = *reinterpret_cast<const float4*>(x + i4 * 4);
        uint32_t h0 = pack_s2(v.x, v.y);
        uint32_t h1 = pack_s2(v.z, v.w);
        *reinterpret_cast<uint2*>(g_x + i4 * 4) = make_uint2(h0, h1);
    } else if (bid < 4288) {
        const int j = bid - 4096;
        const int midx = j >> 4, rem = j & 15;
        const int which = midx >> 2, h = midx & 3;
        const float* src = (which == 0 ? Wq : (which == 1 ? Wk : Wv)) + (size_t)h * 128 * 128;
        transplit_tile(src, g_WT + (size_t)midx * 16384,
                       128, 128, (rem >> 2) * 32, (rem & 3) * 32);
    } else if (bid < 4352) {
        const int j = bid - 4288;
        transplit_tile(W1, g_W1T, 512, 128, (j >> 2) * 32, (j & 3) * 32);
    } else {
        const int j = bid - 4352;
        transplit_tile(W2, g_W2T, 128, 128, (j >> 2) * 32, (j & 3) * 32);
    }
}

// ======================= main kernels =======================
extern __shared__ __half dynsm[];

// QKV strip: grid (256). x tile resident; loop over all 12 weight tiles.
// smem: x 4 planes | W 2x4 planes | LN buffer (1280 floats).
__global__ __launch_bounds__(256, 2) void qkv_strip(
    const float* __restrict__ bq, const float* __restrict__ bk, const float* __restrict__ bv)
{
    const int rowBase = blockIdx.x * 128;
    const int tid = threadIdx.x;
    __half* xs  = dynsm;                 // 4 planes
    __half* ws  = dynsm + 4 * PLANE;     // 2 x 4 planes
    float* lnbuf = (float*)(dynsm + 12 * PLANE);

    const __half* xg = g_x + (size_t)rowBase * E;
    #pragma unroll
    for (int p = 0; p < 4; p++) cp_plane(xs + p * PLANE, xg, E, p * 32, tid);
    asm volatile("cp.async.commit_group;");
    #pragma unroll
    for (int p = 0; p < 4; p++) cp_plane(ws + p * PLANE, g_WT, E, p * 32, tid);
    asm volatile("cp.async.commit_group;");

    const int b = rowBase >> 9, nBase = rowBase & 511;
    const int lane = tid & 31, wid = tid >> 5;
    const int n0 = (wid & 3) * 32, cg = lane & 3;

    for (int midx = 0; midx < 12; midx++) {
        __half* wcur = ws + (midx & 1) * (4 * PLANE);
        if (midx + 1 < 12) {
            __half* wnxt = ws + ((midx + 1) & 1) * (4 * PLANE);
            const __half* wg = g_WT + (size_t)(midx + 1) * 16384;
            #pragma unroll
            for (int p = 0; p < 4; p++) cp_plane(wnxt + p * PLANE, wg, E, p * 32, tid);
            asm volatile("cp.async.commit_group;");
            asm volatile("cp.async.wait_group 1;");
        } else {
            asm volatile("cp.async.wait_group 0;");
        }
        __syncthreads();

        float acc[4][4][4];
        mma_resident(xs, wcur, acc);

        const int which = midx >> 2, h = midx & 3;
        const float* bias = (which == 0 ? bq : (which == 1 ? bk : bv)) + (size_t)h * 128;
        #pragma unroll
        for (int nt = 0; nt < 4; nt++) {
            float2 bv2 = *reinterpret_cast<const float2*>(bias + n0 + nt * 8 + 2 * cg);
            #pragma unroll
            for (int mt = 0; mt < 4; mt++) {
                acc[mt][nt][0] += bv2.x; acc[mt][nt][1] += bv2.y;
                acc[mt][nt][2] += bv2.x; acc[mt][nt][3] += bv2.y;
            }
        }
        ln_mma(acc, lnbuf);

        const int bh = b * H + h;
        const size_t off = ((size_t)bh * Nseq + nBase) * 128;
        __half* o = (which == 0 ? g_Q : (which == 1 ? g_K : g_V)) + off;
        store_single(acc, o, 128);
        __syncthreads();   // all reads of wcur done before next prefetch overwrites it
    }
}

// V transpose: grid (256, 4, 16)
__global__ __launch_bounds__(256) void vtrans_kernel()
{
    __shared__ __half t[32][33];
    const int bh = blockIdx.x, e0 = blockIdx.y * 32, n0 = blockIdx.z * 32;
    const int tid = threadIdx.x;
    const size_t inBase = ((size_t)bh * Nseq + n0) * E + e0;
    #pragma unroll
    for (int s = 0; s < 4; s++) {
        int idx = tid + s * 256;
        int r = idx >> 5, c = idx & 31;
        t[r][c] = g_V[inBase + (size_t)r * E + c];
    }
    __syncthreads();
    const size_t outBase = ((size_t)bh * E + e0) * Nseq + n0;
    #pragma unroll
    for (int s = 0; s < 4; s++) {
        int idx = tid + s * 256;
        int r = idx >> 5, c = idx & 31;
        g_Vt[outBase + (size_t)r * Nseq + c] = t[c][r];
    }
}

// scores strip: grid (4, 256). Q tile resident; loop 4 K col tiles.
// smem: Q 4 planes | K 2x4 planes = 96KB.
__global__ __launch_bounds__(256, 2) void scores_strip()
{
    const int rowBase = blockIdx.x * 128;
    const int bh = blockIdx.y;
    const int tid = threadIdx.x;
    __half* qs = dynsm;                 // 4 planes
    __half* ks = dynsm + 4 * PLANE;     // 2 x 4 planes

    const __half* qg = g_Q + ((size_t)bh * Nseq + rowBase) * D;
    #pragma unroll
    for (int p = 0; p < 4; p++) cp_plane(qs + p * PLANE, qg, D, p * 32, tid);
    asm volatile("cp.async.commit_group;");
    {
        const __half* kg = g_K + (size_t)bh * Nseq * D;
        #pragma unroll
        for (int p = 0; p < 4; p++) cp_plane(ks + p * PLANE, kg, D, p * 32, tid);
        asm volatile("cp.async.commit_group;");
    }

    for (int col = 0; col < 4; col++) {
        __half* kcur = ks + (col & 1) * (4 * PLANE);
        if (col + 1 < 4) {
            __half* knxt = ks + ((col + 1) & 1) * (4 * PLANE);
            const __half* kg = g_K + ((size_t)bh * Nseq + (col + 1) * 128) * D;
            #pragma unroll
            for (int p = 0; p < 4; p++) cp_plane(knxt + p * PLANE, kg, D, p * 32, tid);
            asm volatile("cp.async.commit_group;");
            asm volatile("cp.async.wait_group 1;");
        } else {
            asm volatile("cp.async.wait_group 0;");
        }
        __syncthreads();

        float acc[4][4][4];
        mma_resident(qs, kcur, acc);
        store_single(acc, g_S + (size_t)bh * Nseq * Nseq + (size_t)rowBase * Nseq + col * 128,
                     Nseq);
        __syncthreads();
    }
}

// batch-axis softmax -> P single plane. grid (4096)
__global__ __launch_bounds__(256) void softmax_kernel()
{
    const size_t idx = (size_t)blockIdx.x * 256 + threadIdx.x;
    const size_t stride = (size_t)H * Nseq * Nseq;
    float v[64];
    float mx = -1e30f;
    #pragma unroll
    for (int b = 0; b < 64; b++) {
        float t = __half2float(g_S[(size_t)b * stride + idx]) * (1.0f / 11.0f);
        v[b] = t;
        mx = fmaxf(mx, t);
    }
    float s = 0.f;
    #pragma unroll
    for (int b = 0; b < 64; b++) { float e = __expf(v[b] - mx); v[b] = e; s += e; }
    const float inv = 1.0f / s;
    #pragma unroll
    for (int b = 0; b < 64; b++)
        g_P[(size_t)b * stride + idx] = __float2half(v[b] * inv);
}

// A = P V (1-pass streaming) -> single concat layout. grid (4, 1, 256)
__global__ __launch_bounds__(256, 2) void av_mma()
{
    const int bh = blockIdx.z, b = bh >> 2, h = bh & 3;
    const size_t rowBase = blockIdx.x * 128;
    float acc[4][4][4];
    mma_core1(g_P + ((size_t)bh * Nseq + rowBase) * Nseq, Nseq,
              g_Vt + (size_t)bh * E * Nseq, Nseq, Nseq, dynsm, acc);
    const size_t off = ((size_t)b * Nseq + rowBase) * (H * E) + (size_t)h * E;
    store_single(acc, g_A + off, H * E);
}

// h1 = relu(A @ W1 + b1) -> single. grid (256)
__global__ __launch_bounds__(256, 2) void mlp1_mma(const float* __restrict__ b1)
{
    const int rowBase = blockIdx.x * 128;
    float acc[4][4][4];
    mma_core1(g_A + (size_t)rowBase * (H * E), H * E,
              g_W1T, H * E, H * E, dynsm, acc);

    const int lane = threadIdx.x & 31, wid = threadIdx.x >> 5;
    const int n0 = (wid & 3) * 32, cg = lane & 3;
    #pragma unroll
    for (int nt = 0; nt < 4; nt++) {
        float2 bv2 = *reinterpret_cast<const float2*>(b1 + n0 + nt * 8 + 2 * cg);
        #pragma unroll
        for (int mt = 0; mt < 4; mt++) {
            acc[mt][nt][0] = fmaxf(acc[mt][nt][0] + bv2.x, 0.f);
            acc[mt][nt][1] = fmaxf(acc[mt][nt][1] + bv2.y, 0.f);
            acc[mt][nt][2] = fmaxf(acc[mt][nt][2] + bv2.x, 0.f);
            acc[mt][nt][3] = fmaxf(acc[mt][nt][3] + bv2.y, 0.f);
        }
    }
    store_single(acc, g_H1 + (size_t)rowBase * E, E);
}

// out = LN(x + relu(h1 @ W2 + b2)) * gamma + beta. grid (256)
__global__ __launch_bounds__(256, 2) void mlp2_mma(
    const float* __restrict__ x, const float* __restrict__ b2,
    const float* __restrict__ gamma, const float* __restrict__ beta,
    float* __restrict__ out)
{
    const int rowBase = blockIdx.x * 128;
    float acc[4][4][4];
    mma_core1(g_H1 + (size_t)rowBase * E, E, g_W2T, E, E, dynsm, acc);

    const int lane = threadIdx.x & 31, wid = threadIdx.x >> 5;
    const int m0 = (wid >> 2) * 64, n0 = (wid & 3) * 32;
    const int rr = lane >> 2, cg = lane & 3;
    #pragma unroll
    for (int nt = 0; nt < 4; nt++) {
        const int c = n0 + nt * 8 + 2 * cg;
        float2 bv2 = *reinterpret_cast<const float2*>(b2 + c);
        #pragma unroll
        for (int mt = 0; mt < 4; mt++)
            #pragma unroll
            for (int half_ = 0; half_ < 2; half_++) {
                int row = rowBase + m0 + mt * 16 + half_ * 8 + rr;
                float2 xv = *reinterpret_cast<const float2*>(x + (size_t)row * E + c);
                acc[mt][nt][2*half_]   = fmaxf(acc[mt][nt][2*half_]   + bv2.x, 0.f) + xv.x;
                acc[mt][nt][2*half_+1] = fmaxf(acc[mt][nt][2*half_+1] + bv2.y, 0.f) + xv.y;
            }
    }

    ln_mma(acc, (float*)dynsm);

    #pragma unroll
    for (int nt = 0; nt < 4; nt++) {
        const int c = n0 + nt * 8 + 2 * cg;
        float2 gv = *reinterpret_cast<const float2*>(gamma + c);
        float2 ev = *reinterpret_cast<const float2*>(beta + c);
        #pragma unroll
        for (int mt = 0; mt < 4; mt++)
            #pragma unroll
            for (int half_ = 0; half_ < 2; half_++) {
                int row = rowBase + m0 + mt * 16 + half_ * 8 + rr;
                float o0 = acc[mt][nt][2*half_]   * gv.x + ev.x;
                float o1 = acc[mt][nt][2*half_+1] * gv.y + ev.y;
                *reinterpret_cast<float2*>(out + (size_t)row * E + c) = make_float2(o0, o1);
            }
    }
}

// ---------------------------------------------------------------------------
extern "C" void kernel_launch(void* const* d_in, const int* in_sizes, int n_in,
                              void* d_out, int out_size)
{
    const float* x     = (const float*)d_in[0];
    const float* Wq    = (const float*)d_in[1];
    const float* bq    = (const float*)d_in[2];
    const float* Wk    = (const float*)d_in[3];
    const float* bk    = (const float*)d_in[4];
    const float* Wv    = (const float*)d_in[5];
    const float* bv    = (const float*)d_in[6];
    const float* W1    = (const float*)d_in[7];
    const float* b1    = (const float*)d_in[8];
    const float* W2    = (const float*)d_in[9];
    const float* b2    = (const float*)d_in[10];
    const float* gamma = (const float*)d_in[11];
    const float* beta  = (const float*)d_in[12];
    float* out = (float*)d_out;

    const int SMEM1    = 2 * 2 * 4096 * (int)sizeof(__half);          // 32KB streaming
    const int SMEM_SC  = 12 * 4096 * (int)sizeof(__half);             // 96KB scores strip
    const int SMEM_QKV = 12 * 4096 * (int)sizeof(__half) + 1280 * 4;  // 96KB + LN buf
    cudaFuncSetAttribute(qkv_strip,    cudaFuncAttributeMaxDynamicSharedMemorySize, SMEM_QKV);
    cudaFuncSetAttribute(scores_strip, cudaFuncAttributeMaxDynamicSharedMemorySize, SMEM_SC);
    cudaFuncSetAttribute(av_mma,       cudaFuncAttributeMaxDynamicSharedMemorySize, SMEM1);
    cudaFuncSetAttribute(mlp1_mma,     cudaFuncAttributeMaxDynamicSharedMemorySize, SMEM1);
    cudaFuncSetAttribute(mlp2_mma,     cudaFuncAttributeMaxDynamicSharedMemorySize, SMEM1);

    dim3 blk(256);
    prep_all      <<<dim3(4368), blk>>>(x, Wq, Wk, Wv, W1, W2);
    qkv_strip     <<<dim3(256), blk, SMEM_QKV>>>(bq, bk, bv);
    vtrans_kernel <<<dim3(256, 4, 16), blk>>>();
    scores_strip  <<<dim3(4, 256), blk, SMEM_SC>>>();
    softmax_kernel<<<dim3(4096), blk>>>();
    av_mma        <<<dim3(4, 1, 256), blk, SMEM1>>>();
    mlp1_mma      <<<dim3(256), blk, SMEM1>>>(b1);
    mlp2_mma      <<<dim3(256), blk, SMEM1>>>(x, b2, gamma, beta, out);
}

// round 17
// speedup vs baseline: 2.1950x; 1.0175x over previous
#include <cuda_runtime.h>
#include <cuda_fp16.h>
#include <cstdint>

constexpr int Bdim = 64;
constexpr int Nseq = 512;
constexpr int E    = 128;
constexpr int D    = 128;
constexpr int H    = 4;

// ---------------- scratch (allocation-free) ----------------
__device__ __half g_WT [12 * 128 * 128];          // [which*4+h][d][e] transposed
__device__ __half g_W1T[128 * 512];               // [e_out][k]
__device__ __half g_W2T[128 * 128];
__device__ __half g_Q [(size_t)Bdim*H*Nseq*D];
__device__ __half g_K [(size_t)Bdim*H*Nseq*D];
__device__ __half g_V [(size_t)Bdim*H*Nseq*E];    // [bh][n][e]
__device__ __half g_Vt[(size_t)Bdim*H*E*Nseq];    // [bh][e][n]
__device__ __half g_S [(size_t)Bdim*H*Nseq*Nseq]; // fp16 scores (unscaled)
__device__ __half g_P [(size_t)Bdim*H*Nseq*Nseq]; // post-softmax
__device__ __half g_A [(size_t)Bdim*Nseq*H*E];    // [B,N,512] concat

// ======================= mma.sync machinery (fp16) =======================
__device__ __forceinline__ void ldsm_x4(uint32_t r[4], const void* p) {
    uint32_t addr = (uint32_t)__cvta_generic_to_shared(p);
    asm volatile("ldmatrix.sync.aligned.m8n8.x4.shared.b16 {%0,%1,%2,%3}, [%4];"
                 : "=r"(r[0]), "=r"(r[1]), "=r"(r[2]), "=r"(r[3]) : "r"(addr));
}
__device__ __forceinline__ void mma16816(float c[4], const uint32_t a[4], const uint32_t b[2]) {
    asm volatile("mma.sync.aligned.m16n8k16.row.col.f32.f16.f16.f32 "
                 "{%0,%1,%2,%3}, {%4,%5,%6,%7}, {%8,%9}, {%0,%1,%2,%3};"
                 : "+f"(c[0]), "+f"(c[1]), "+f"(c[2]), "+f"(c[3])
                 : "r"(a[0]), "r"(a[1]), "r"(a[2]), "r"(a[3]), "r"(b[0]), "r"(b[1]));
}
__device__ __forceinline__ int sw_idx(int row, int seg) {
    return row * 32 + ((seg ^ ((row >> 1) & 3)) << 3);
}
__device__ __forceinline__ void cp_plane(__half* dst, const __half* src,
                                         int ld, int kc, int tid)
{
    #pragma unroll
    for (int s = 0; s < 2; s++) {
        int idx = tid + s * 256;
        int row = idx >> 2, seg = idx & 3;
        uint32_t d = (uint32_t)__cvta_generic_to_shared(dst + sw_idx(row, seg));
        const __half* g = src + (size_t)row * ld + kc + seg * 8;
        asm volatile("cp.async.cg.shared.global [%0], [%1], 16;" :: "r"(d), "l"(g));
    }
}
__device__ __forceinline__ void load_a_frag(uint32_t a[4][4], const __half* plane,
                                            int m0, int seg_base, int lane)
{
    const int r = lane & 15, half_ = lane >> 4;
    #pragma unroll
    for (int t = 0; t < 4; t++)
        ldsm_x4(a[t], plane + sw_idx(m0 + t * 16 + r, seg_base + half_));
}
__device__ __forceinline__ void load_b_frag(uint32_t b[4][2], const __half* plane,
                                            int n0, int seg_base, int lane)
{
    const int r = lane & 15, half_ = lane >> 4;
    #pragma unroll
    for (int p = 0; p < 2; p++) {
        uint32_t t[4];
        ldsm_x4(t, plane + sw_idx(n0 + p * 16 + r, seg_base + half_));
        b[2*p][0]   = t[0];
        b[2*p+1][0] = t[1];
        b[2*p][1]   = t[2];
        b[2*p+1][1] = t[3];
    }
}
__device__ __forceinline__ void mma_all(float acc[4][4][4], const uint32_t a[4][4],
                                        const uint32_t b[4][2])
{
    #pragma unroll
    for (int mt = 0; mt < 4; mt++)
        #pragma unroll
        for (int nt = 0; nt < 4; nt++)
            mma16816(acc[mt][nt], a[mt], b[nt]);
}
__device__ __forceinline__ void acc_zero(float acc[4][4][4])
{
    #pragma unroll
    for (int mt = 0; mt < 4; mt++)
        #pragma unroll
        for (int nt = 0; nt < 4; nt++)
            #pragma unroll
            for (int q = 0; q < 4; q++) acc[mt][nt][q] = 0.f;
}

#define PLANE 4096

// ---------------------------------------------------------------------------
// 1-pass streaming core: C = A * B. 2 stages x 2 planes = 32KB smem.
// ---------------------------------------------------------------------------
__device__ __forceinline__ void mma_core1(
                         const __half* __restrict__ A, int lda,
                         const __half* __restrict__ B, int ldb,
                         int K, __half* sm, float acc[4][4][4])
{
    const int tid = threadIdx.x, lane = tid & 31, wid = tid >> 5;
    const int m0 = (wid >> 2) * 64, n0 = (wid & 3) * 32;
    acc_zero(acc);

    cp_plane(sm + 0*PLANE, A, lda, 0, tid);
    cp_plane(sm + 1*PLANE, B, ldb, 0, tid);
    asm volatile("cp.async.commit_group;");

    const int NC = K >> 5;
    for (int c = 0; c < NC; c++) {
        __half* st = sm + (c & 1) * (2 * PLANE);
        if (c + 1 < NC) {
            __half* st2 = sm + ((c + 1) & 1) * (2 * PLANE);
            const int kc = (c + 1) * 32;
            cp_plane(st2 + 0*PLANE, A, lda, kc, tid);
            cp_plane(st2 + 1*PLANE, B, ldb, kc, tid);
            asm volatile("cp.async.commit_group;");
            asm volatile("cp.async.wait_group 1;");
        } else {
            asm volatile("cp.async.wait_group 0;");
        }
        __syncthreads();
        #pragma unroll
        for (int ks = 0; ks < 2; ks++) {
            const int seg = ks * 2;
            uint32_t a[4][4];
            uint32_t b[4][2];
            load_b_frag(b, st + 1*PLANE, n0, seg, lane);
            load_a_frag(a, st + 0*PLANE, m0, seg, lane);
            mma_all(acc, a, b);
        }
        __syncthreads();
    }
}

// Compute 128x128 tile from fully-resident smem tiles (4 planes each), no syncs.
__device__ __forceinline__ void mma_resident(const __half* As, const __half* Bs,
                                             float acc[4][4][4])
{
    const int lane = threadIdx.x & 31, wid = threadIdx.x >> 5;
    const int m0 = (wid >> 2) * 64, n0 = (wid & 3) * 32;
    acc_zero(acc);
    #pragma unroll
    for (int chunk = 0; chunk < 4; chunk++) {
        #pragma unroll
        for (int ks = 0; ks < 2; ks++) {
            const int seg = ks * 2;
            uint32_t a[4][4];
            uint32_t b[4][2];
            load_b_frag(b, Bs + chunk * PLANE, n0, seg, lane);
            load_a_frag(a, As + chunk * PLANE, m0, seg, lane);
            mma_all(acc, a, b);
        }
    }
}

// LayerNorm over 128 cols in mma fragment layout. lnbuf >= 1280 floats.
__device__ __forceinline__ void ln_mma(float acc[4][4][4], float* lnbuf)
{
    float* lnS = lnbuf;
    float* lnQ = lnbuf + 512;
    float* mrs = lnbuf + 1024;
    const int tid = threadIdx.x, lane = tid & 31, wid = tid >> 5;
    const int wn = wid & 3, m0 = (wid >> 2) * 64;
    const int rr = lane >> 2, cg = lane & 3;

    #pragma unroll
    for (int mt = 0; mt < 4; mt++)
        #pragma unroll
        for (int half_ = 0; half_ < 2; half_++) {
            float s = 0.f, q = 0.f;
            #pragma unroll
            for (int nt = 0; nt < 4; nt++) {
                float v0 = acc[mt][nt][2*half_], v1 = acc[mt][nt][2*half_+1];
                s += v0 + v1; q += v0 * v0 + v1 * v1;
            }
            s += __shfl_xor_sync(0xffffffffu, s, 1);
            s += __shfl_xor_sync(0xffffffffu, s, 2);
            q += __shfl_xor_sync(0xffffffffu, q, 1);
            q += __shfl_xor_sync(0xffffffffu, q, 2);
            if (cg == 0) {
                int row = m0 + mt * 16 + half_ * 8 + rr;
                lnS[row * 4 + wn] = s;
                lnQ[row * 4 + wn] = q;
            }
        }
    __syncthreads();
    if (tid < 128) {
        float s = lnS[tid*4] + lnS[tid*4+1] + lnS[tid*4+2] + lnS[tid*4+3];
        float q = lnQ[tid*4] + lnQ[tid*4+1] + lnQ[tid*4+2] + lnQ[tid*4+3];
        float mean = s * (1.0f / 128.0f);
        float var  = q * (1.0f / 128.0f) - mean * mean;
        mrs[tid]       = mean;
        mrs[128 + tid] = rsqrtf(var + 1e-5f);
    }
    __syncthreads();
    #pragma unroll
    for (int mt = 0; mt < 4; mt++)
        #pragma unroll
        for (int half_ = 0; half_ < 2; half_++) {
            int row = m0 + mt * 16 + half_ * 8 + rr;
            float mu = mrs[row], rs = mrs[128 + row];
            #pragma unroll
            for (int nt = 0; nt < 4; nt++) {
                acc[mt][nt][2*half_]   = (acc[mt][nt][2*half_]   - mu) * rs;
                acc[mt][nt][2*half_+1] = (acc[mt][nt][2*half_+1] - mu) * rs;
            }
        }
}

__device__ __forceinline__ uint32_t pack_s2(float v0, float v1)
{
    __half h0 = __float2half(v0), h1 = __float2half(v1);
    return (uint32_t)__half_as_ushort(h0) | ((uint32_t)__half_as_ushort(h1) << 16);
}

__device__ __forceinline__ void store_single(const float acc[4][4][4],
                                             __half* o, int ldc)
{
    const int lane = threadIdx.x & 31, wid = threadIdx.x >> 5;
    const int m0 = (wid >> 2) * 64, n0 = (wid & 3) * 32;
    const int rr = lane >> 2, cg = lane & 3;
    #pragma unroll
    for (int mt = 0; mt < 4; mt++)
        #pragma unroll
        for (int half_ = 0; half_ < 2; half_++) {
            int row = m0 + mt * 16 + half_ * 8 + rr;
            #pragma unroll
            for (int nt = 0; nt < 4; nt++) {
                int c = n0 + nt * 8 + 2 * cg;
                *reinterpret_cast<uint32_t*>(o + (size_t)row * ldc + c) =
                    pack_s2(acc[mt][nt][2*half_], acc[mt][nt][2*half_+1]);
            }
        }
}

// store fragment tile into swizzled smem planes (as next A operand)
__device__ __forceinline__ void store_smem_planes(const float acc[4][4][4], __half* base)
{
    const int lane = threadIdx.x & 31, wid = threadIdx.x >> 5;
    const int m0 = (wid >> 2) * 64, n0 = (wid & 3) * 32;
    const int rr = lane >> 2, cg = lane & 3;
    #pragma unroll
    for (int mt = 0; mt < 4; mt++)
        #pragma unroll
        for (int half_ = 0; half_ < 2; half_++) {
            int row = m0 + mt * 16 + half_ * 8 + rr;
            #pragma unroll
            for (int nt = 0; nt < 4; nt++) {
                int c = n0 + nt * 8 + 2 * cg;
                __half* p = base + (c >> 5) * PLANE + sw_idx(row, (c & 31) >> 3) + (c & 7);
                *reinterpret_cast<uint32_t*>(p) =
                    pack_s2(acc[mt][nt][2*half_], acc[mt][nt][2*half_+1]);
            }
        }
}

// ======================= prep: weight transposes only =======================
__device__ __forceinline__ void transplit_tile(const float* src, __half* dh,
                                               int R, int C, int r0, int c0)
{
    __shared__ float t[32][33];
    const int tid = threadIdx.x;
    #pragma unroll
    for (int s = 0; s < 4; s++) {
        int idx = tid + s * 256;
        int r = idx >> 5, c = idx & 31;
        t[r][c] = src[(size_t)(r0 + r) * C + c0 + c];
    }
    __syncthreads();
    #pragma unroll
    for (int s = 0; s < 4; s++) {
        int idx = tid + s * 256;
        int co = idx >> 5, ro = idx & 31;
        dh[(size_t)(c0 + co) * R + r0 + ro] = __float2half(t[ro][co]);
    }
}

// blocks: 0..191 qkv W; 192..255 W1; 256..271 W2
__global__ __launch_bounds__(256) void prep_all(
    const float* __restrict__ Wq, const float* __restrict__ Wk, const float* __restrict__ Wv,
    const float* __restrict__ W1, const float* __restrict__ W2)
{
    const int bid = blockIdx.x;
    if (bid < 192) {
        const int midx = bid >> 4, rem = bid & 15;
        const int which = midx >> 2, h = midx & 3;
        const float* src = (which == 0 ? Wq : (which == 1 ? Wk : Wv)) + (size_t)h * 128 * 128;
        transplit_tile(src, g_WT + (size_t)midx * 16384,
                       128, 128, (rem >> 2) * 32, (rem & 3) * 32);
    } else if (bid < 256) {
        const int j = bid - 192;
        transplit_tile(W1, g_W1T, 512, 128, (j >> 2) * 32, (j & 3) * 32);
    } else {
        const int j = bid - 256;
        transplit_tile(W2, g_W2T, 128, 128, (j >> 2) * 32, (j & 3) * 32);
    }
}

// ======================= main kernels =======================
extern __shared__ __half dynsm[];

// QKV strip: grid (256). x loaded fp32+converted into resident smem; loop 12 W.
// smem: x 4 planes | W 2x4 planes | LN buffer (1280 floats).
__global__ __launch_bounds__(256, 2) void qkv_strip(
    const float* __restrict__ x,
    const float* __restrict__ bq, const float* __restrict__ bk, const float* __restrict__ bv)
{
    const int rowBase = blockIdx.x * 128;
    const int tid = threadIdx.x;
    __half* xs  = dynsm;                 // 4 planes
    __half* ws  = dynsm + 4 * PLANE;     // 2 x 4 planes
    float* lnbuf = (float*)(dynsm + 12 * PLANE);

    // load + convert x tile (fp32 -> fp16, swizzled planes)
    const float* xg = x + (size_t)rowBase * E;
    #pragma unroll
    for (int s = 0; s < 8; s++) {
        int idx = tid + s * 256;             // 2048 granules
        int row = idx >> 4, g = idx & 15;
        int plane = g >> 2, seg = g & 3;
        const float* p = xg + (size_t)row * E + g * 8;
        float4 v0 = *reinterpret_cast<const float4*>(p);
        float4 v1 = *reinterpret_cast<const float4*>(p + 4);
        uint4 pk;
        pk.x = pack_s2(v0.x, v0.y); pk.y = pack_s2(v0.z, v0.w);
        pk.z = pack_s2(v1.x, v1.y); pk.w = pack_s2(v1.z, v1.w);
        *reinterpret_cast<uint4*>(xs + plane * PLANE + sw_idx(row, seg)) = pk;
    }
    #pragma unroll
    for (int p = 0; p < 4; p++) cp_plane(ws + p * PLANE, g_WT, E, p * 32, tid);
    asm volatile("cp.async.commit_group;");

    const int b = rowBase >> 9, nBase = rowBase & 511;
    const int lane = tid & 31, wid = tid >> 5;
    const int n0 = (wid & 3) * 32, cg = lane & 3;

    for (int midx = 0; midx < 12; midx++) {
        __half* wcur = ws + (midx & 1) * (4 * PLANE);
        if (midx + 1 < 12) {
            __half* wnxt = ws + ((midx + 1) & 1) * (4 * PLANE);
            const __half* wg = g_WT + (size_t)(midx + 1) * 16384;
            #pragma unroll
            for (int p = 0; p < 4; p++) cp_plane(wnxt + p * PLANE, wg, E, p * 32, tid);
            asm volatile("cp.async.commit_group;");
            asm volatile("cp.async.wait_group 1;");
        } else {
            asm volatile("cp.async.wait_group 0;");
        }
        __syncthreads();   // also orders the xs STS on first iteration

        float acc[4][4][4];
        mma_resident(xs, wcur, acc);

        const int which = midx >> 2, h = midx & 3;
        const float* bias = (which == 0 ? bq : (which == 1 ? bk : bv)) + (size_t)h * 128;
        #pragma unroll
        for (int nt = 0; nt < 4; nt++) {
            float2 bv2 = *reinterpret_cast<const float2*>(bias + n0 + nt * 8 + 2 * cg);
            #pragma unroll
            for (int mt = 0; mt < 4; mt++) {
                acc[mt][nt][0] += bv2.x; acc[mt][nt][1] += bv2.y;
                acc[mt][nt][2] += bv2.x; acc[mt][nt][3] += bv2.y;
            }
        }
        ln_mma(acc, lnbuf);

        const int bh = b * H + h;
        const size_t off = ((size_t)bh * Nseq + nBase) * 128;
        __half* o = (which == 0 ? g_Q : (which == 1 ? g_K : g_V)) + off;
        store_single(acc, o, 128);
        __syncthreads();
    }
}

// V transpose: grid (256, 4, 16)
__global__ __launch_bounds__(256) void vtrans_kernel()
{
    __shared__ __half t[32][33];
    const int bh = blockIdx.x, e0 = blockIdx.y * 32, n0 = blockIdx.z * 32;
    const int tid = threadIdx.x;
    const size_t inBase = ((size_t)bh * Nseq + n0) * E + e0;
    #pragma unroll
    for (int s = 0; s < 4; s++) {
        int idx = tid + s * 256;
        int r = idx >> 5, c = idx & 31;
        t[r][c] = g_V[inBase + (size_t)r * E + c];
    }
    __syncthreads();
    const size_t outBase = ((size_t)bh * E + e0) * Nseq + n0;
    #pragma unroll
    for (int s = 0; s < 4; s++) {
        int idx = tid + s * 256;
        int r = idx >> 5, c = idx & 31;
        g_Vt[outBase + (size_t)r * Nseq + c] = t[c][r];
    }
}

// scores strip: grid (4, 256). Q tile resident; loop 4 K col tiles. 96KB smem.
__global__ __launch_bounds__(256, 2) void scores_strip()
{
    const int rowBase = blockIdx.x * 128;
    const int bh = blockIdx.y;
    const int tid = threadIdx.x;
    __half* qs = dynsm;
    __half* ks = dynsm + 4 * PLANE;

    const __half* qg = g_Q + ((size_t)bh * Nseq + rowBase) * D;
    #pragma unroll
    for (int p = 0; p < 4; p++) cp_plane(qs + p * PLANE, qg, D, p * 32, tid);
    asm volatile("cp.async.commit_group;");
    {
        const __half* kg = g_K + (size_t)bh * Nseq * D;
        #pragma unroll
        for (int p = 0; p < 4; p++) cp_plane(ks + p * PLANE, kg, D, p * 32, tid);
        asm volatile("cp.async.commit_group;");
    }

    for (int col = 0; col < 4; col++) {
        __half* kcur = ks + (col & 1) * (4 * PLANE);
        if (col + 1 < 4) {
            __half* knxt = ks + ((col + 1) & 1) * (4 * PLANE);
            const __half* kg = g_K + ((size_t)bh * Nseq + (col + 1) * 128) * D;
            #pragma unroll
            for (int p = 0; p < 4; p++) cp_plane(knxt + p * PLANE, kg, D, p * 32, tid);
            asm volatile("cp.async.commit_group;");
            asm volatile("cp.async.wait_group 1;");
        } else {
            asm volatile("cp.async.wait_group 0;");
        }
        __syncthreads();

        float acc[4][4][4];
        mma_resident(qs, kcur, acc);
        store_single(acc, g_S + (size_t)bh * Nseq * Nseq + (size_t)rowBase * Nseq + col * 128,
                     Nseq);
        __syncthreads();
    }
}

// batch-axis softmax -> P single plane. grid (4096)
__global__ __launch_bounds__(256) void softmax_kernel()
{
    const size_t idx = (size_t)blockIdx.x * 256 + threadIdx.x;
    const size_t stride = (size_t)H * Nseq * Nseq;
    float v[64];
    float mx = -1e30f;
    #pragma unroll
    for (int b = 0; b < 64; b++) {
        float t = __half2float(g_S[(size_t)b * stride + idx]) * (1.0f / 11.0f);
        v[b] = t;
        mx = fmaxf(mx, t);
    }
    float s = 0.f;
    #pragma unroll
    for (int b = 0; b < 64; b++) { float e = __expf(v[b] - mx); v[b] = e; s += e; }
    const float inv = 1.0f / s;
    #pragma unroll
    for (int b = 0; b < 64; b++)
        g_P[(size_t)b * stride + idx] = __float2half(v[b] * inv);
}

// A = P V (1-pass streaming) -> single concat layout. grid (4, 1, 256)
__global__ __launch_bounds__(256, 2) void av_mma()
{
    const int bh = blockIdx.z, b = bh >> 2, h = bh & 3;
    const size_t rowBase = blockIdx.x * 128;
    float acc[4][4][4];
    mma_core1(g_P + ((size_t)bh * Nseq + rowBase) * Nseq, Nseq,
              g_Vt + (size_t)bh * E * Nseq, Nseq, Nseq, dynsm, acc);
    const size_t off = ((size_t)b * Nseq + rowBase) * (H * E) + (size_t)h * E;
    store_single(acc, g_A + off, H * E);
}

// Fused MLP: h1 = relu(A@W1+b1) staged in smem; out = LN(x + relu(h1@W2+b2))*g+b.
// smem: stream 4 planes | h1 4 planes | W2 4 planes = 96KB. grid (256)
__global__ __launch_bounds__(256, 2) void mlp_fused(
    const float* __restrict__ x, const float* __restrict__ b1,
    const float* __restrict__ b2,
    const float* __restrict__ gamma, const float* __restrict__ beta,
    float* __restrict__ out)
{
    const int rowBase = blockIdx.x * 128;
    const int tid = threadIdx.x;
    __half* h1s = dynsm + 4 * PLANE;
    __half* w2s = dynsm + 8 * PLANE;

    // W2 resident load (extra oldest cp.async group; drained by core's waits)
    #pragma unroll
    for (int p = 0; p < 4; p++) cp_plane(w2s + p * PLANE, g_W2T, E, p * 32, tid);
    asm volatile("cp.async.commit_group;");

    float acc[4][4][4];
    mma_core1(g_A + (size_t)rowBase * (H * E), H * E,
              g_W1T, H * E, H * E, dynsm, acc);

    const int lane = tid & 31, wid = tid >> 5;
    const int m0 = (wid >> 2) * 64, n0 = (wid & 3) * 32;
    const int rr = lane >> 2, cg = lane & 3;

    #pragma unroll
    for (int nt = 0; nt < 4; nt++) {
        float2 bv2 = *reinterpret_cast<const float2*>(b1 + n0 + nt * 8 + 2 * cg);
        #pragma unroll
        for (int mt = 0; mt < 4; mt++) {
            acc[mt][nt][0] = fmaxf(acc[mt][nt][0] + bv2.x, 0.f);
            acc[mt][nt][1] = fmaxf(acc[mt][nt][1] + bv2.y, 0.f);
            acc[mt][nt][2] = fmaxf(acc[mt][nt][2] + bv2.x, 0.f);
            acc[mt][nt][3] = fmaxf(acc[mt][nt][3] + bv2.y, 0.f);
        }
    }
    store_smem_planes(acc, h1s);
    __syncthreads();

    mma_resident(h1s, w2s, acc);

    #pragma unroll
    for (int nt = 0; nt < 4; nt++) {
        const int c = n0 + nt * 8 + 2 * cg;
        float2 bv2 = *reinterpret_cast<const float2*>(b2 + c);
        #pragma unroll
        for (int mt = 0; mt < 4; mt++)
            #pragma unroll
            for (int half_ = 0; half_ < 2; half_++) {
                int row = rowBase + m0 + mt * 16 + half_ * 8 + rr;
                float2 xv = *reinterpret_cast<const float2*>(x + (size_t)row * E + c);
                acc[mt][nt][2*half_]   = fmaxf(acc[mt][nt][2*half_]   + bv2.x, 0.f) + xv.x;
                acc[mt][nt][2*half_+1] = fmaxf(acc[mt][nt][2*half_+1] + bv2.y, 0.f) + xv.y;
            }
    }

    __syncthreads();                 // h1s reads done; reuse stream region for LN
    ln_mma(acc, (float*)dynsm);

    #pragma unroll
    for (int nt = 0; nt < 4; nt++) {
        const int c = n0 + nt * 8 + 2 * cg;
        float2 gv = *reinterpret_cast<const float2*>(gamma + c);
        float2 ev = *reinterpret_cast<const float2*>(beta + c);
        #pragma unroll
        for (int mt = 0; mt < 4; mt++)
            #pragma unroll
            for (int half_ = 0; half_ < 2; half_++) {
                int row = rowBase + m0 + mt * 16 + half_ * 8 + rr;
                float o0 = acc[mt][nt][2*half_]   * gv.x + ev.x;
                float o1 = acc[mt][nt][2*half_+1] * gv.y + ev.y;
                *reinterpret_cast<float2*>(out + (size_t)row * E + c) = make_float2(o0, o1);
            }
    }
}

// ---------------------------------------------------------------------------
extern "C" void kernel_launch(void* const* d_in, const int* in_sizes, int n_in,
                              void* d_out, int out_size)
{
    const float* x     = (const float*)d_in[0];
    const float* Wq    = (const float*)d_in[1];
    const float* bq    = (const float*)d_in[2];
    const float* Wk    = (const float*)d_in[3];
    const float* bk    = (const float*)d_in[4];
    const float* Wv    = (const float*)d_in[5];
    const float* bv    = (const float*)d_in[6];
    const float* W1    = (const float*)d_in[7];
    const float* b1    = (const float*)d_in[8];
    const float* W2    = (const float*)d_in[9];
    const float* b2    = (const float*)d_in[10];
    const float* gamma = (const float*)d_in[11];
    const float* beta  = (const float*)d_in[12];
    float* out = (float*)d_out;

    const int SMEM1    = 2 * 2 * 4096 * (int)sizeof(__half);          // 32KB streaming
    const int SMEM_BIG = 12 * 4096 * (int)sizeof(__half);             // 96KB
    const int SMEM_QKV = SMEM_BIG + 1280 * 4;                         // 96KB + LN buf
    cudaFuncSetAttribute(qkv_strip,    cudaFuncAttributeMaxDynamicSharedMemorySize, SMEM_QKV);
    cudaFuncSetAttribute(scores_strip, cudaFuncAttributeMaxDynamicSharedMemorySize, SMEM_BIG);
    cudaFuncSetAttribute(av_mma,       cudaFuncAttributeMaxDynamicSharedMemorySize, SMEM1);
    cudaFuncSetAttribute(mlp_fused,    cudaFuncAttributeMaxDynamicSharedMemorySize, SMEM_BIG);

    dim3 blk(256);
    prep_all      <<<dim3(272), blk>>>(Wq, Wk, Wv, W1, W2);
    qkv_strip     <<<dim3(256), blk, SMEM_QKV>>>(x, bq, bk, bv);
    vtrans_kernel <<<dim3(256, 4, 16), blk>>>();
    scores_strip  <<<dim3(4, 256), blk, SMEM_BIG>>>();
    softmax_kernel<<<dim3(4096), blk>>>();
    av_mma        <<<dim3(4, 1, 256), blk, SMEM1>>>();
    mlp_fused     <<<dim3(256), blk, SMEM_BIG>>>(x, b1, b2, gamma, beta, out);
}